// round 1
// baseline (speedup 1.0000x reference)
#include <cuda_runtime.h>
#include <cuda_bf16.h>
#include <math.h>

// Problem constants
#define BATCH 2
#define SEQ 1024
#define HIDDEN 2048
#define HQ 32
#define HKV 8
#define HD 64
#define MROWS (BATCH * SEQ)          // 2048
#define NEG_BIG (-1e9f)

// -------------------- scratch (no allocations allowed) --------------------
__device__ float g_q[MROWS * HQ * HD];      // [b,s,hq,64]  = 2048 x 2048
__device__ float g_k[MROWS * HKV * HD];     // [b,s,hkv,64] = 2048 x 512
__device__ float g_v[MROWS * HKV * HD];
__device__ float g_attn[MROWS * HQ * HD];   // attention output, 2048 x 2048

// ============================ SGEMM 128x128x8 =============================
// C[M,N] = A[M,K] @ B[K,N], all row-major, all dims multiples of 128.
#define BM 128
#define BN 128
#define BK 8
#define TM 8
#define TN 8

__global__ __launch_bounds__(256) void sgemm_kernel(
    const float* __restrict__ A, const float* __restrict__ B,
    float* __restrict__ C, int M, int N, int K)
{
    __shared__ float As[BK][BM + 4];   // transposed A tile, padded
    __shared__ float Bs[BK][BN];

    const int tid = threadIdx.x;
    const int m0 = blockIdx.y * BM;
    const int n0 = blockIdx.x * BN;

    const int ty = tid / 16;           // 0..15 -> row group
    const int tx = tid % 16;           // 0..15 -> col group

    // A tile load mapping: 128 rows x 8 cols, one float4 per thread
    const int arow = tid >> 1;         // 0..127
    const int acol = (tid & 1) * 4;    // 0 or 4
    // B tile load mapping: 8 rows x 128 cols, one float4 per thread
    const int brow = tid >> 5;         // 0..7
    const int bcol = (tid & 31) * 4;   // 0..124

    const float* Aptr = A + (size_t)(m0 + arow) * K + acol;
    const float* Bptr = B + (size_t)brow * N + n0 + bcol;

    float acc[TM][TN];
    #pragma unroll
    for (int i = 0; i < TM; i++)
        #pragma unroll
        for (int j = 0; j < TN; j++) acc[i][j] = 0.f;

    for (int k0 = 0; k0 < K; k0 += BK) {
        float4 av = *(const float4*)(Aptr + k0);
        float4 bv = *(const float4*)(Bptr + (size_t)k0 * N);
        As[acol + 0][arow] = av.x;
        As[acol + 1][arow] = av.y;
        As[acol + 2][arow] = av.z;
        As[acol + 3][arow] = av.w;
        *(float4*)&Bs[brow][bcol] = bv;
        __syncthreads();

        #pragma unroll
        for (int kk = 0; kk < BK; kk++) {
            float af[TM], bf[TN];
            #pragma unroll
            for (int i = 0; i < TM; i++) af[i] = As[kk][ty * TM + i];
            #pragma unroll
            for (int j = 0; j < TN; j++) bf[j] = Bs[kk][tx * TN + j];
            #pragma unroll
            for (int i = 0; i < TM; i++)
                #pragma unroll
                for (int j = 0; j < TN; j++)
                    acc[i][j] += af[i] * bf[j];
        }
        __syncthreads();
    }

    #pragma unroll
    for (int i = 0; i < TM; i++) {
        float* crow = C + (size_t)(m0 + ty * TM + i) * N + n0 + tx * TN;
        float4 v0 = make_float4(acc[i][0], acc[i][1], acc[i][2], acc[i][3]);
        float4 v1 = make_float4(acc[i][4], acc[i][5], acc[i][6], acc[i][7]);
        *(float4*)(crow) = v0;
        *(float4*)(crow + 4) = v1;
    }
}

// ============================== RoPE ======================================
// x: [B, S, heads, 64] in-place, split-half (Llama) style.
__global__ void rope_kernel(float* __restrict__ x, int heads)
{
    int idx = blockIdx.x * blockDim.x + threadIdx.x;
    int total = BATCH * SEQ * heads * (HD / 2);
    if (idx >= total) return;
    int dpair = idx & 31;
    int t = idx >> 5;
    int h = t % heads;  t /= heads;
    int s = t % SEQ;
    int b = t / SEQ;

    float inv = powf(10000.0f, -(float)(2 * dpair) / (float)HD);
    float ang = (float)s * inv;
    float sn, cs;
    sincosf(ang, &sn, &cs);

    size_t base = (((size_t)b * SEQ + s) * heads + h) * HD + dpair;
    float x1 = x[base];
    float x2 = x[base + HD / 2];
    x[base]           = x1 * cs - x2 * sn;
    x[base + HD / 2]  = x2 * cs + x1 * sn;
}

// ========================= Flash attention ================================
// 64x64 tiles, online softmax, causal mask, GQA (4 q heads per kv head).
#define FS 64
#define FP 65     // smem row pitch (pad)
#define FLASH_SMEM (4 * FS * FP * sizeof(float))

__global__ __launch_bounds__(256) void flash_kernel(
    const float* __restrict__ q, const float* __restrict__ k,
    const float* __restrict__ v, float* __restrict__ out)
{
    extern __shared__ float fsm[];
    float* Qs = fsm;
    float* Ks = fsm + FS * FP;
    float* Vs = fsm + 2 * FS * FP;
    float* Ps = fsm + 3 * FS * FP;

    const int tid = threadIdx.x;
    const int qt = blockIdx.x;            // 0..15 (q tile)
    const int bh = blockIdx.y;            // 0..63
    const int b = bh / HQ;
    const int h = bh % HQ;
    const int hkv = h / (HQ / HKV);

    const int ty = tid / 16;              // 0..15
    const int tx = tid % 16;              // 0..15

    // Load Q tile [64 x 64]
    {
        int c = tx * 4;
        for (int r = ty; r < FS; r += 16) {
            float4 qv = *(const float4*)&q[(((size_t)b * SEQ + qt * FS + r) * HQ + h) * HD + c];
            Qs[r * FP + c + 0] = qv.x;
            Qs[r * FP + c + 1] = qv.y;
            Qs[r * FP + c + 2] = qv.z;
            Qs[r * FP + c + 3] = qv.w;
        }
    }
    __syncthreads();

    float m_i[4], l_i[4], o_acc[4][4];
    #pragma unroll
    for (int i = 0; i < 4; i++) {
        m_i[i] = -1e30f; l_i[i] = 0.f;
        #pragma unroll
        for (int j = 0; j < 4; j++) o_acc[i][j] = 0.f;
    }

    const int qrow_base = qt * FS + ty * 4;
    const float scale = 0.125f;  // 1/sqrt(64)

    for (int kt = 0; kt <= qt; kt++) {
        // Load K and V tiles
        {
            int c = tx * 4;
            for (int r = ty; r < FS; r += 16) {
                size_t goff = (((size_t)b * SEQ + kt * FS + r) * HKV + hkv) * HD + c;
                float4 kv4 = *(const float4*)&k[goff];
                float4 vv4 = *(const float4*)&v[goff];
                Ks[r * FP + c + 0] = kv4.x;
                Ks[r * FP + c + 1] = kv4.y;
                Ks[r * FP + c + 2] = kv4.z;
                Ks[r * FP + c + 3] = kv4.w;
                Vs[r * FP + c + 0] = vv4.x;
                Vs[r * FP + c + 1] = vv4.y;
                Vs[r * FP + c + 2] = vv4.z;
                Vs[r * FP + c + 3] = vv4.w;
            }
        }
        __syncthreads();

        // Scores: s[4][4] = Q(4 rows) @ K^T(4 cols)
        float s[4][4];
        #pragma unroll
        for (int i = 0; i < 4; i++)
            #pragma unroll
            for (int j = 0; j < 4; j++) s[i][j] = 0.f;

        for (int d = 0; d < HD; d++) {
            float qf[4], kf[4];
            #pragma unroll
            for (int i = 0; i < 4; i++) qf[i] = Qs[(ty * 4 + i) * FP + d];
            #pragma unroll
            for (int j = 0; j < 4; j++) kf[j] = Ks[(tx * 4 + j) * FP + d];
            #pragma unroll
            for (int i = 0; i < 4; i++)
                #pragma unroll
                for (int j = 0; j < 4; j++)
                    s[i][j] += qf[i] * kf[j];
        }

        const bool diag = (kt == qt);
        #pragma unroll
        for (int i = 0; i < 4; i++)
            #pragma unroll
            for (int j = 0; j < 4; j++) {
                s[i][j] *= scale;
                if (diag && (kt * FS + tx * 4 + j) > (qrow_base + i))
                    s[i][j] = NEG_BIG;
            }

        // Row max across the 16 tx threads
        float rmax[4];
        #pragma unroll
        for (int i = 0; i < 4; i++) {
            float mx = fmaxf(fmaxf(s[i][0], s[i][1]), fmaxf(s[i][2], s[i][3]));
            mx = fmaxf(mx, __shfl_xor_sync(0xffffffffu, mx, 1));
            mx = fmaxf(mx, __shfl_xor_sync(0xffffffffu, mx, 2));
            mx = fmaxf(mx, __shfl_xor_sync(0xffffffffu, mx, 4));
            mx = fmaxf(mx, __shfl_xor_sync(0xffffffffu, mx, 8));
            rmax[i] = mx;
        }

        float m_new[4], corr[4], rsum[4];
        #pragma unroll
        for (int i = 0; i < 4; i++) {
            m_new[i] = fmaxf(m_i[i], rmax[i]);
            corr[i] = expf(m_i[i] - m_new[i]);
            float rs = 0.f;
            #pragma unroll
            for (int j = 0; j < 4; j++) {
                float p = expf(s[i][j] - m_new[i]);
                s[i][j] = p;
                rs += p;
            }
            rs += __shfl_xor_sync(0xffffffffu, rs, 1);
            rs += __shfl_xor_sync(0xffffffffu, rs, 2);
            rs += __shfl_xor_sync(0xffffffffu, rs, 4);
            rs += __shfl_xor_sync(0xffffffffu, rs, 8);
            rsum[i] = rs;
        }

        #pragma unroll
        for (int i = 0; i < 4; i++) {
            l_i[i] = l_i[i] * corr[i] + rsum[i];
            m_i[i] = m_new[i];
            #pragma unroll
            for (int j = 0; j < 4; j++) o_acc[i][j] *= corr[i];
        }

        // Stash probs to smem
        #pragma unroll
        for (int i = 0; i < 4; i++)
            #pragma unroll
            for (int j = 0; j < 4; j++)
                Ps[(ty * 4 + i) * FP + tx * 4 + j] = s[i][j];
        __syncthreads();

        // O += P @ V  (o cols = tx*4..tx*4+3 of head dim)
        for (int kk = 0; kk < FS; kk++) {
            float pf[4], vf[4];
            #pragma unroll
            for (int i = 0; i < 4; i++) pf[i] = Ps[(ty * 4 + i) * FP + kk];
            #pragma unroll
            for (int j = 0; j < 4; j++) vf[j] = Vs[kk * FP + tx * 4 + j];
            #pragma unroll
            for (int i = 0; i < 4; i++)
                #pragma unroll
                for (int j = 0; j < 4; j++)
                    o_acc[i][j] += pf[i] * vf[j];
        }
        __syncthreads();
    }

    // Write output [b, s, hq, 64]
    #pragma unroll
    for (int i = 0; i < 4; i++) {
        float invl = 1.0f / l_i[i];
        #pragma unroll
        for (int j = 0; j < 4; j++) {
            out[(((size_t)b * SEQ + qrow_base + i) * HQ + h) * HD + tx * 4 + j] =
                o_acc[i][j] * invl;
        }
    }
}

// ============================ launcher ====================================
extern "C" void kernel_launch(void* const* d_in, const int* in_sizes, int n_in,
                              void* d_out, int out_size)
{
    const float* hidden = (const float*)d_in[0];
    // d_in[1] = attention_mask (always causal tril -> reconstructed analytically)
    const float* Wq = (const float*)d_in[2];
    const float* Wk = (const float*)d_in[3];
    const float* Wv = (const float*)d_in[4];
    const float* Wo = (const float*)d_in[5];
    float* out = (float*)d_out;

    float *q_ptr, *k_ptr, *v_ptr, *attn_ptr;
    cudaGetSymbolAddress((void**)&q_ptr,    g_q);
    cudaGetSymbolAddress((void**)&k_ptr,    g_k);
    cudaGetSymbolAddress((void**)&v_ptr,    g_v);
    cudaGetSymbolAddress((void**)&attn_ptr, g_attn);

    cudaFuncSetAttribute(flash_kernel,
                         cudaFuncAttributeMaxDynamicSharedMemorySize,
                         (int)FLASH_SMEM);

    // QKV projections
    {
        dim3 gq(HQ * HD / BN, MROWS / BM);       // (16, 16)
        sgemm_kernel<<<gq, 256>>>(hidden, Wq, q_ptr, MROWS, HQ * HD, HIDDEN);
        dim3 gk(HKV * HD / BN, MROWS / BM);      // (4, 16)
        sgemm_kernel<<<gk, 256>>>(hidden, Wk, k_ptr, MROWS, HKV * HD, HIDDEN);
        sgemm_kernel<<<gk, 256>>>(hidden, Wv, v_ptr, MROWS, HKV * HD, HIDDEN);
    }

    // RoPE on q and k
    {
        int nq = BATCH * SEQ * HQ * (HD / 2);
        rope_kernel<<<(nq + 255) / 256, 256>>>(q_ptr, HQ);
        int nk = BATCH * SEQ * HKV * (HD / 2);
        rope_kernel<<<(nk + 255) / 256, 256>>>(k_ptr, HKV);
    }

    // Flash attention
    {
        dim3 g(SEQ / FS, BATCH * HQ);            // (16, 64)
        flash_kernel<<<g, 256, FLASH_SMEM>>>(q_ptr, k_ptr, v_ptr, attn_ptr);
    }

    // Output projection
    {
        dim3 go(HIDDEN / BN, MROWS / BM);        // (16, 16)
        sgemm_kernel<<<go, 256>>>(attn_ptr, Wo, out, MROWS, HIDDEN, HIDDEN);
    }
}

// round 3
// speedup vs baseline: 2.0375x; 2.0375x over previous
#include <cuda_runtime.h>
#include <cuda_bf16.h>
#include <math.h>
#include <stdint.h>

// ---------------- problem constants ----------------
#define BATCH 2
#define SEQ 1024
#define HIDDEN 2048
#define HQ 32
#define HKV 8
#define HD 64
#define MROWS (BATCH * SEQ)     // 2048
#define KDIM HIDDEN             // 2048
#define NEG_BIG (-1e9f)

// ---------------- scratch ----------------
__device__ float g_q[MROWS * HQ * HD];
__device__ float g_k[MROWS * HKV * HD];
__device__ float g_v[MROWS * HKV * HD];
__device__ float g_attn[MROWS * HQ * HD];

__device__ __nv_bfloat16 gA_hi[MROWS * KDIM];
__device__ __nv_bfloat16 gA_lo[MROWS * KDIM];
__device__ __nv_bfloat16 gBq_hi[2048 * KDIM];
__device__ __nv_bfloat16 gBq_lo[2048 * KDIM];
__device__ __nv_bfloat16 gBk_hi[512 * KDIM];
__device__ __nv_bfloat16 gBk_lo[512 * KDIM];
__device__ __nv_bfloat16 gBv_hi[512 * KDIM];
__device__ __nv_bfloat16 gBv_lo[512 * KDIM];
__device__ __nv_bfloat16 gBo_hi[2048 * KDIM];
__device__ __nv_bfloat16 gBo_lo[2048 * KDIM];

// ---------------- helpers ----------------
__device__ __forceinline__ uint32_t smem_to_u32(const void* p) {
    uint32_t a;
    asm("{ .reg .u64 t; cvta.to.shared.u64 t, %1; cvt.u32.u64 %0, t; }" : "=r"(a) : "l"(p));
    return a;
}
__device__ __forceinline__ uint32_t lds32(uint32_t a) {
    uint32_t v;
    asm volatile("ld.shared.b32 %0, [%1];" : "=r"(v) : "r"(a));
    return v;
}
#define MMA16816(d, a, b) \
    asm volatile("mma.sync.aligned.m16n8k16.row.col.f32.bf16.bf16.f32 " \
        "{%0,%1,%2,%3}, {%4,%5,%6,%7}, {%8,%9}, {%0,%1,%2,%3};" \
        : "+f"((d)[0]), "+f"((d)[1]), "+f"((d)[2]), "+f"((d)[3]) \
        : "r"((a)[0]), "r"((a)[1]), "r"((a)[2]), "r"((a)[3]), "r"((b)[0]), "r"((b)[1]))

// ---------------- bf16x3 GEMM via mma.sync ----------------
// C[M,N] = A[M,K] @ B^T;  A_hi/lo: [M,K] bf16 row-major; B_hi/lo: [N,K] bf16 row-major.
#define BK 32
#define PITCH 40                                   // bf16 elems per smem row (80B)
#define TILE_ELEMS (128 * PITCH)                   // 5120
#define STAGE_ELEMS (4 * TILE_ELEMS)               // Ahi, Alo, Bhi, Blo
#define GEMM_SMEM (2 * STAGE_ELEMS * 2)            // bytes = 81920
#define NCHUNK (KDIM / BK)                         // 64

__device__ __forceinline__ void issue_stage(
    uint32_t sb, int stage,
    const __nv_bfloat16* __restrict__ Ahi, const __nv_bfloat16* __restrict__ Alo,
    const __nv_bfloat16* __restrict__ Bhi, const __nv_bfloat16* __restrict__ Blo,
    int m0, int n0, int k0, int tid)
{
    const __nv_bfloat16* bases[4] = {
        Ahi + (size_t)m0 * KDIM, Alo + (size_t)m0 * KDIM,
        Bhi + (size_t)n0 * KDIM, Blo + (size_t)n0 * KDIM };
    #pragma unroll
    for (int t = 0; t < 8; t++) {
        int idx = tid + t * 256;           // 0..2047
        int tile = idx >> 9;               // 0..3
        int row  = (idx >> 2) & 127;       // 0..127
        int ch   = idx & 3;                // 0..3 (16B chunks)
        const __nv_bfloat16* src = bases[tile] + (size_t)row * KDIM + k0 + ch * 8;
        uint32_t dst = sb + 2u * (uint32_t)(stage * STAGE_ELEMS + tile * TILE_ELEMS + row * PITCH + ch * 8);
        asm volatile("cp.async.cg.shared.global [%0], [%1], 16;" :: "r"(dst), "l"(src));
    }
    asm volatile("cp.async.commit_group;");
}

__global__ __launch_bounds__(256, 1) void gemm_bf16x3_kernel(
    const __nv_bfloat16* __restrict__ Ahi, const __nv_bfloat16* __restrict__ Alo,
    const __nv_bfloat16* __restrict__ Bhi, const __nv_bfloat16* __restrict__ Blo,
    float* __restrict__ C, int N)
{
    extern __shared__ char smem[];
    const uint32_t sb = smem_to_u32(smem);
    const int tid = threadIdx.x;
    const int wid = tid >> 5;
    const int lid = tid & 31;
    const int wm = wid >> 2;               // 0..1
    const int wn = wid & 3;                // 0..3
    const int g = lid >> 2;                // 0..7
    const int t4 = lid & 3;                // 0..3
    const int n0 = blockIdx.x * 128;
    const int m0 = blockIdx.y * 128;

    float acc[4][4][4];
    #pragma unroll
    for (int i = 0; i < 4; i++)
        #pragma unroll
        for (int j = 0; j < 4; j++)
            #pragma unroll
            for (int r = 0; r < 4; r++) acc[i][j][r] = 0.f;

    issue_stage(sb, 0, Ahi, Alo, Bhi, Blo, m0, n0, 0, tid);

    for (int i = 0; i < NCHUNK; i++) {
        const int p = i & 1;
        if (i + 1 < NCHUNK) {
            issue_stage(sb, 1 - p, Ahi, Alo, Bhi, Blo, m0, n0, (i + 1) * BK, tid);
            asm volatile("cp.async.wait_group 1;" ::: "memory");
        } else {
            asm volatile("cp.async.wait_group 0;" ::: "memory");
        }
        __syncthreads();

        const uint32_t base = sb + 2u * (uint32_t)(p * STAGE_ELEMS);
        #pragma unroll
        for (int ks = 0; ks < 2; ks++) {
            const int kb = ks * 16 + 2 * t4;      // bf16 col of first pair
            uint32_t ah[4][4], al[4][4], bh[4][2], bl[4][2];
            #pragma unroll
            for (int mt = 0; mt < 4; mt++) {
                int r0 = wm * 64 + mt * 16 + g;
                uint32_t aoff = base + 2u * (uint32_t)(r0 * PITCH + kb);
                ah[mt][0] = lds32(aoff);
                ah[mt][1] = lds32(aoff + 8 * PITCH * 2);
                ah[mt][2] = lds32(aoff + 16);
                ah[mt][3] = lds32(aoff + 8 * PITCH * 2 + 16);
                uint32_t aoff2 = aoff + 2u * TILE_ELEMS;
                al[mt][0] = lds32(aoff2);
                al[mt][1] = lds32(aoff2 + 8 * PITCH * 2);
                al[mt][2] = lds32(aoff2 + 16);
                al[mt][3] = lds32(aoff2 + 8 * PITCH * 2 + 16);
            }
            #pragma unroll
            for (int nt = 0; nt < 4; nt++) {
                int r0 = wn * 32 + nt * 8 + g;
                uint32_t boff = base + 2u * (uint32_t)(2 * TILE_ELEMS + r0 * PITCH + kb);
                bh[nt][0] = lds32(boff);
                bh[nt][1] = lds32(boff + 16);
                uint32_t boff2 = boff + 2u * TILE_ELEMS;
                bl[nt][0] = lds32(boff2);
                bl[nt][1] = lds32(boff2 + 16);
            }
            #pragma unroll
            for (int mt = 0; mt < 4; mt++)
                #pragma unroll
                for (int nt = 0; nt < 4; nt++) {
                    MMA16816(acc[mt][nt], ah[mt], bh[nt]);
                    MMA16816(acc[mt][nt], ah[mt], bl[nt]);
                    MMA16816(acc[mt][nt], al[mt], bh[nt]);
                }
        }
        __syncthreads();
    }

    // epilogue
    #pragma unroll
    for (int mt = 0; mt < 4; mt++) {
        int row = m0 + wm * 64 + mt * 16 + g;
        #pragma unroll
        for (int nt = 0; nt < 4; nt++) {
            int col = n0 + wn * 32 + nt * 8 + 2 * t4;
            *(float2*)&C[(size_t)row * N + col] = make_float2(acc[mt][nt][0], acc[mt][nt][1]);
            *(float2*)&C[(size_t)(row + 8) * N + col] = make_float2(acc[mt][nt][2], acc[mt][nt][3]);
        }
    }
}

// ---------------- fp32 -> bf16 hi/lo split ----------------
__global__ void split_kernel(const float* __restrict__ x,
                             __nv_bfloat16* __restrict__ hi,
                             __nv_bfloat16* __restrict__ lo, int n)
{
    int i = blockIdx.x * blockDim.x + threadIdx.x;
    if (i >= n) return;
    float v = x[i];
    __nv_bfloat16 h = __float2bfloat16(v);
    float r = v - __bfloat162float(h);
    hi[i] = h;
    lo[i] = __float2bfloat16(r);
}

// ---------------- W[K,N] -> (hi,lo)[N,K] transpose+split ----------------
__global__ void tsplit_kernel(const float* __restrict__ W,
                              __nv_bfloat16* __restrict__ hi,
                              __nv_bfloat16* __restrict__ lo, int K, int N)
{
    __shared__ float t[32][33];
    const int n0 = blockIdx.x * 32;
    const int k0 = blockIdx.y * 32;
    const int tx = threadIdx.x, ty = threadIdx.y;  // 32 x 8
    #pragma unroll
    for (int i = 0; i < 32; i += 8)
        t[ty + i][tx] = W[(size_t)(k0 + ty + i) * N + n0 + tx];
    __syncthreads();
    #pragma unroll
    for (int i = 0; i < 32; i += 8) {
        float v = t[tx][ty + i];
        __nv_bfloat16 h = __float2bfloat16(v);
        float r = v - __bfloat162float(h);
        size_t o = (size_t)(n0 + ty + i) * K + k0 + tx;
        hi[o] = h;
        lo[o] = __float2bfloat16(r);
    }
}

// ---------------- RoPE ----------------
__global__ void rope_kernel(float* __restrict__ x, int heads)
{
    int idx = blockIdx.x * blockDim.x + threadIdx.x;
    int total = BATCH * SEQ * heads * (HD / 2);
    if (idx >= total) return;
    int dpair = idx & 31;
    int t = idx >> 5;
    int h = t % heads;  t /= heads;
    int s = t % SEQ;
    int b = t / SEQ;

    float inv = powf(10000.0f, -(float)(2 * dpair) / (float)HD);
    float ang = (float)s * inv;
    float sn, cs;
    sincosf(ang, &sn, &cs);

    size_t base = (((size_t)b * SEQ + s) * heads + h) * HD + dpair;
    float x1 = x[base];
    float x2 = x[base + HD / 2];
    x[base]          = x1 * cs - x2 * sn;
    x[base + HD / 2] = x2 * cs + x1 * sn;
}

// ---------------- flash attention (fp32) ----------------
#define FS 64
#define FP 65
#define FLASH_SMEM (4 * FS * FP * sizeof(float))

__global__ __launch_bounds__(256) void flash_kernel(
    const float* __restrict__ q, const float* __restrict__ k,
    const float* __restrict__ v, float* __restrict__ out)
{
    extern __shared__ float fsm[];
    float* Qs = fsm;
    float* Ks = fsm + FS * FP;
    float* Vs = fsm + 2 * FS * FP;
    float* Ps = fsm + 3 * FS * FP;

    const int tid = threadIdx.x;
    const int qt = blockIdx.x;
    const int bh = blockIdx.y;
    const int b = bh / HQ;
    const int h = bh % HQ;
    const int hkv = h / (HQ / HKV);

    const int ty = tid / 16;
    const int tx = tid % 16;

    {
        int c = tx * 4;
        for (int r = ty; r < FS; r += 16) {
            float4 qv = *(const float4*)&q[(((size_t)b * SEQ + qt * FS + r) * HQ + h) * HD + c];
            Qs[r * FP + c + 0] = qv.x;
            Qs[r * FP + c + 1] = qv.y;
            Qs[r * FP + c + 2] = qv.z;
            Qs[r * FP + c + 3] = qv.w;
        }
    }
    __syncthreads();

    float m_i[4], l_i[4], o_acc[4][4];
    #pragma unroll
    for (int i = 0; i < 4; i++) {
        m_i[i] = -1e30f; l_i[i] = 0.f;
        #pragma unroll
        for (int j = 0; j < 4; j++) o_acc[i][j] = 0.f;
    }

    const int qrow_base = qt * FS + ty * 4;
    const float scale = 0.125f;

    for (int kt = 0; kt <= qt; kt++) {
        {
            int c = tx * 4;
            for (int r = ty; r < FS; r += 16) {
                size_t goff = (((size_t)b * SEQ + kt * FS + r) * HKV + hkv) * HD + c;
                float4 kv4 = *(const float4*)&k[goff];
                float4 vv4 = *(const float4*)&v[goff];
                Ks[r * FP + c + 0] = kv4.x;
                Ks[r * FP + c + 1] = kv4.y;
                Ks[r * FP + c + 2] = kv4.z;
                Ks[r * FP + c + 3] = kv4.w;
                Vs[r * FP + c + 0] = vv4.x;
                Vs[r * FP + c + 1] = vv4.y;
                Vs[r * FP + c + 2] = vv4.z;
                Vs[r * FP + c + 3] = vv4.w;
            }
        }
        __syncthreads();

        float s[4][4];
        #pragma unroll
        for (int i = 0; i < 4; i++)
            #pragma unroll
            for (int j = 0; j < 4; j++) s[i][j] = 0.f;

        for (int d = 0; d < HD; d++) {
            float qf[4], kf[4];
            #pragma unroll
            for (int i = 0; i < 4; i++) qf[i] = Qs[(ty * 4 + i) * FP + d];
            #pragma unroll
            for (int j = 0; j < 4; j++) kf[j] = Ks[(tx * 4 + j) * FP + d];
            #pragma unroll
            for (int i = 0; i < 4; i++)
                #pragma unroll
                for (int j = 0; j < 4; j++)
                    s[i][j] += qf[i] * kf[j];
        }

        const bool diag = (kt == qt);
        #pragma unroll
        for (int i = 0; i < 4; i++)
            #pragma unroll
            for (int j = 0; j < 4; j++) {
                s[i][j] *= scale;
                if (diag && (kt * FS + tx * 4 + j) > (qrow_base + i))
                    s[i][j] = NEG_BIG;
            }

        float rmax[4];
        #pragma unroll
        for (int i = 0; i < 4; i++) {
            float mx = fmaxf(fmaxf(s[i][0], s[i][1]), fmaxf(s[i][2], s[i][3]));
            mx = fmaxf(mx, __shfl_xor_sync(0xffffffffu, mx, 1));
            mx = fmaxf(mx, __shfl_xor_sync(0xffffffffu, mx, 2));
            mx = fmaxf(mx, __shfl_xor_sync(0xffffffffu, mx, 4));
            mx = fmaxf(mx, __shfl_xor_sync(0xffffffffu, mx, 8));
            rmax[i] = mx;
        }

        float m_new[4], corr[4], rsum[4];
        #pragma unroll
        for (int i = 0; i < 4; i++) {
            m_new[i] = fmaxf(m_i[i], rmax[i]);
            corr[i] = expf(m_i[i] - m_new[i]);
            float rs = 0.f;
            #pragma unroll
            for (int j = 0; j < 4; j++) {
                float p = expf(s[i][j] - m_new[i]);
                s[i][j] = p;
                rs += p;
            }
            rs += __shfl_xor_sync(0xffffffffu, rs, 1);
            rs += __shfl_xor_sync(0xffffffffu, rs, 2);
            rs += __shfl_xor_sync(0xffffffffu, rs, 4);
            rs += __shfl_xor_sync(0xffffffffu, rs, 8);
            rsum[i] = rs;
        }

        #pragma unroll
        for (int i = 0; i < 4; i++) {
            l_i[i] = l_i[i] * corr[i] + rsum[i];
            m_i[i] = m_new[i];
            #pragma unroll
            for (int j = 0; j < 4; j++) o_acc[i][j] *= corr[i];
        }

        #pragma unroll
        for (int i = 0; i < 4; i++)
            #pragma unroll
            for (int j = 0; j < 4; j++)
                Ps[(ty * 4 + i) * FP + tx * 4 + j] = s[i][j];
        __syncthreads();

        for (int kk = 0; kk < FS; kk++) {
            float pf[4], vf[4];
            #pragma unroll
            for (int i = 0; i < 4; i++) pf[i] = Ps[(ty * 4 + i) * FP + kk];
            #pragma unroll
            for (int j = 0; j < 4; j++) vf[j] = Vs[kk * FP + tx * 4 + j];
            #pragma unroll
            for (int i = 0; i < 4; i++)
                #pragma unroll
                for (int j = 0; j < 4; j++)
                    o_acc[i][j] += pf[i] * vf[j];
        }
        __syncthreads();
    }

    #pragma unroll
    for (int i = 0; i < 4; i++) {
        float invl = 1.0f / l_i[i];
        #pragma unroll
        for (int j = 0; j < 4; j++) {
            out[(((size_t)b * SEQ + qrow_base + i) * HQ + h) * HD + tx * 4 + j] =
                o_acc[i][j] * invl;
        }
    }
}

// ---------------- launcher ----------------
extern "C" void kernel_launch(void* const* d_in, const int* in_sizes, int n_in,
                              void* d_out, int out_size)
{
    const float* hidden = (const float*)d_in[0];
    const float* Wq = (const float*)d_in[2];
    const float* Wk = (const float*)d_in[3];
    const float* Wv = (const float*)d_in[4];
    const float* Wo = (const float*)d_in[5];
    float* out = (float*)d_out;

    float *q_ptr, *k_ptr, *v_ptr, *attn_ptr;
    cudaGetSymbolAddress((void**)&q_ptr, g_q);
    cudaGetSymbolAddress((void**)&k_ptr, g_k);
    cudaGetSymbolAddress((void**)&v_ptr, g_v);
    cudaGetSymbolAddress((void**)&attn_ptr, g_attn);

    __nv_bfloat16 *aHi, *aLo, *bqH, *bqL, *bkH, *bkL, *bvH, *bvL, *boH, *boL;
    cudaGetSymbolAddress((void**)&aHi, gA_hi);
    cudaGetSymbolAddress((void**)&aLo, gA_lo);
    cudaGetSymbolAddress((void**)&bqH, gBq_hi);
    cudaGetSymbolAddress((void**)&bqL, gBq_lo);
    cudaGetSymbolAddress((void**)&bkH, gBk_hi);
    cudaGetSymbolAddress((void**)&bkL, gBk_lo);
    cudaGetSymbolAddress((void**)&bvH, gBv_hi);
    cudaGetSymbolAddress((void**)&bvL, gBv_lo);
    cudaGetSymbolAddress((void**)&boH, gBo_hi);
    cudaGetSymbolAddress((void**)&boL, gBo_lo);

    cudaFuncSetAttribute(flash_kernel, cudaFuncAttributeMaxDynamicSharedMemorySize, (int)FLASH_SMEM);
    cudaFuncSetAttribute(gemm_bf16x3_kernel, cudaFuncAttributeMaxDynamicSharedMemorySize, GEMM_SMEM);

    // 1) splits
    {
        int n = MROWS * KDIM;
        split_kernel<<<(n + 255) / 256, 256>>>(hidden, aHi, aLo, n);
        dim3 tb(32, 8);
        tsplit_kernel<<<dim3(2048 / 32, KDIM / 32), tb>>>(Wq, bqH, bqL, KDIM, 2048);
        tsplit_kernel<<<dim3(512 / 32,  KDIM / 32), tb>>>(Wk, bkH, bkL, KDIM, 512);
        tsplit_kernel<<<dim3(512 / 32,  KDIM / 32), tb>>>(Wv, bvH, bvL, KDIM, 512);
        tsplit_kernel<<<dim3(2048 / 32, KDIM / 32), tb>>>(Wo, boH, boL, KDIM, 2048);
    }

    // 2) QKV projections (tensor cores via mma.sync)
    gemm_bf16x3_kernel<<<dim3(2048 / 128, MROWS / 128), 256, GEMM_SMEM>>>(aHi, aLo, bqH, bqL, q_ptr, 2048);
    gemm_bf16x3_kernel<<<dim3(512 / 128,  MROWS / 128), 256, GEMM_SMEM>>>(aHi, aLo, bkH, bkL, k_ptr, 512);
    gemm_bf16x3_kernel<<<dim3(512 / 128,  MROWS / 128), 256, GEMM_SMEM>>>(aHi, aLo, bvH, bvL, v_ptr, 512);

    // 3) RoPE
    {
        int nq = BATCH * SEQ * HQ * (HD / 2);
        rope_kernel<<<(nq + 255) / 256, 256>>>(q_ptr, HQ);
        int nk = BATCH * SEQ * HKV * (HD / 2);
        rope_kernel<<<(nk + 255) / 256, 256>>>(k_ptr, HKV);
    }

    // 4) attention
    {
        dim3 g(SEQ / FS, BATCH * HQ);
        flash_kernel<<<g, 256, FLASH_SMEM>>>(q_ptr, k_ptr, v_ptr, attn_ptr);
    }

    // 5) output projection
    {
        int n = MROWS * HIDDEN;
        split_kernel<<<(n + 255) / 256, 256>>>(attn_ptr, aHi, aLo, n);
        gemm_bf16x3_kernel<<<dim3(2048 / 128, MROWS / 128), 256, GEMM_SMEM>>>(aHi, aLo, boH, boL, out, 2048);
    }
}

// round 4
// speedup vs baseline: 2.8693x; 1.4082x over previous
#include <cuda_runtime.h>
#include <cuda_bf16.h>
#include <math.h>
#include <stdint.h>

// ---------------- problem constants ----------------
#define BATCH 2
#define SEQ 1024
#define HIDDEN 2048
#define HQ 32
#define HKV 8
#define HD 64
#define MROWS (BATCH * SEQ)     // 2048
#define KDIM HIDDEN             // 2048
#define NEG_BIG (-1e9f)

// ---------------- scratch ----------------
__device__ float g_q[MROWS * HQ * HD];
__device__ float g_k[MROWS * HKV * HD];
__device__ float g_v[MROWS * HKV * HD];

__device__ __nv_bfloat16 gA_hi[MROWS * KDIM];
__device__ __nv_bfloat16 gA_lo[MROWS * KDIM];
__device__ __nv_bfloat16 gBq_hi[2048 * KDIM];
__device__ __nv_bfloat16 gBq_lo[2048 * KDIM];
__device__ __nv_bfloat16 gBk_hi[512 * KDIM];
__device__ __nv_bfloat16 gBk_lo[512 * KDIM];
__device__ __nv_bfloat16 gBv_hi[512 * KDIM];
__device__ __nv_bfloat16 gBv_lo[512 * KDIM];
__device__ __nv_bfloat16 gBo_hi[2048 * KDIM];
__device__ __nv_bfloat16 gBo_lo[2048 * KDIM];

// flash operands (bf16 split)
__device__ __nv_bfloat16 gQhi[MROWS * HQ * HD];
__device__ __nv_bfloat16 gQlo[MROWS * HQ * HD];
__device__ __nv_bfloat16 gKhi[MROWS * HKV * HD];
__device__ __nv_bfloat16 gKlo[MROWS * HKV * HD];
__device__ __nv_bfloat16 gVThi[BATCH * HKV * HD * SEQ];
__device__ __nv_bfloat16 gVTlo[BATCH * HKV * HD * SEQ];

// ---------------- helpers ----------------
__device__ __forceinline__ uint32_t smem_to_u32(const void* p) {
    uint32_t a;
    asm("{ .reg .u64 t; cvta.to.shared.u64 t, %1; cvt.u32.u64 %0, t; }" : "=r"(a) : "l"(p));
    return a;
}
#define LDM4(r0, r1, r2, r3, addr) \
    asm volatile("ldmatrix.sync.aligned.m8n8.x4.shared.b16 {%0,%1,%2,%3}, [%4];" \
        : "=r"(r0), "=r"(r1), "=r"(r2), "=r"(r3) : "r"(addr))

__device__ __forceinline__ void mma16816(float* d, const uint32_t* a, uint32_t b0, uint32_t b1) {
    asm volatile("mma.sync.aligned.m16n8k16.row.col.f32.bf16.bf16.f32 "
        "{%0,%1,%2,%3}, {%4,%5,%6,%7}, {%8,%9}, {%0,%1,%2,%3};"
        : "+f"(d[0]), "+f"(d[1]), "+f"(d[2]), "+f"(d[3])
        : "r"(a[0]), "r"(a[1]), "r"(a[2]), "r"(a[3]), "r"(b0), "r"(b1));
}
__device__ __forceinline__ uint32_t pack_bf16x2(float lo, float hi) {
    uint32_t d;
    asm("cvt.rn.bf16x2.f32 %0, %1, %2;" : "=r"(d) : "f"(hi), "f"(lo));
    return d;
}

// ---------------- bf16x3 GEMM via mma.sync + ldmatrix ----------------
#define BK 32
#define PITCH 40                                   // bf16 elems per smem row (80B)
#define TILE_ELEMS (128 * PITCH)                   // 5120
#define STAGE_ELEMS (4 * TILE_ELEMS)
#define GEMM_SMEM (2 * STAGE_ELEMS * 2)            // 81920 bytes
#define NCHUNK (KDIM / BK)                         // 64

__device__ __forceinline__ void issue_stage(
    uint32_t sb, int stage,
    const __nv_bfloat16* __restrict__ Ahi, const __nv_bfloat16* __restrict__ Alo,
    const __nv_bfloat16* __restrict__ Bhi, const __nv_bfloat16* __restrict__ Blo,
    int m0, int n0, int k0, int tid)
{
    const __nv_bfloat16* bases[4] = {
        Ahi + (size_t)m0 * KDIM, Alo + (size_t)m0 * KDIM,
        Bhi + (size_t)n0 * KDIM, Blo + (size_t)n0 * KDIM };
    #pragma unroll
    for (int t = 0; t < 8; t++) {
        int idx = tid + t * 256;
        int tile = idx >> 9;
        int row  = (idx >> 2) & 127;
        int ch   = idx & 3;
        const __nv_bfloat16* src = bases[tile] + (size_t)row * KDIM + k0 + ch * 8;
        uint32_t dst = sb + 2u * (uint32_t)(stage * STAGE_ELEMS + tile * TILE_ELEMS + row * PITCH + ch * 8);
        asm volatile("cp.async.cg.shared.global [%0], [%1], 16;" :: "r"(dst), "l"(src));
    }
    asm volatile("cp.async.commit_group;");
}

__global__ __launch_bounds__(256, 1) void gemm_bf16x3_kernel(
    const __nv_bfloat16* __restrict__ Ahi, const __nv_bfloat16* __restrict__ Alo,
    const __nv_bfloat16* __restrict__ Bhi, const __nv_bfloat16* __restrict__ Blo,
    float* __restrict__ C, int N)
{
    extern __shared__ char smem[];
    const uint32_t sb = smem_to_u32(smem);
    const int tid = threadIdx.x;
    const int wid = tid >> 5;
    const int lid = tid & 31;
    const int wm = wid >> 2;
    const int wn = wid & 3;
    const int g = lid >> 2;
    const int t4 = lid & 3;
    const int n0 = blockIdx.x * 128;
    const int m0 = blockIdx.y * 128;

    // ldmatrix lane offsets
    const int arow_l = (lid & 7) + ((lid >> 3) & 1) * 8;
    const int acol_l = (lid >> 4) * 8;
    const int brow_l = (lid & 7) + (lid >> 4) * 8;
    const int bcol_l = ((lid >> 3) & 1) * 8;

    float acc[4][4][4];
    #pragma unroll
    for (int i = 0; i < 4; i++)
        #pragma unroll
        for (int j = 0; j < 4; j++)
            #pragma unroll
            for (int r = 0; r < 4; r++) acc[i][j][r] = 0.f;

    issue_stage(sb, 0, Ahi, Alo, Bhi, Blo, m0, n0, 0, tid);

    for (int i = 0; i < NCHUNK; i++) {
        const int p = i & 1;
        if (i + 1 < NCHUNK) {
            issue_stage(sb, 1 - p, Ahi, Alo, Bhi, Blo, m0, n0, (i + 1) * BK, tid);
            asm volatile("cp.async.wait_group 1;" ::: "memory");
        } else {
            asm volatile("cp.async.wait_group 0;" ::: "memory");
        }
        __syncthreads();

        const uint32_t base = sb + 2u * (uint32_t)(p * STAGE_ELEMS);
        #pragma unroll
        for (int ks = 0; ks < 2; ks++) {
            const int kb = ks * 16;
            uint32_t ah[4][4], al[4][4], bh[4][2], bl[4][2];
            #pragma unroll
            for (int mt = 0; mt < 4; mt++) {
                uint32_t ad = base + 2u * (uint32_t)((wm * 64 + mt * 16 + arow_l) * PITCH + kb + acol_l);
                LDM4(ah[mt][0], ah[mt][1], ah[mt][2], ah[mt][3], ad);
                LDM4(al[mt][0], al[mt][1], al[mt][2], al[mt][3], ad + 2u * TILE_ELEMS);
            }
            #pragma unroll
            for (int ntp = 0; ntp < 2; ntp++) {
                uint32_t bd = base + 2u * (uint32_t)(2 * TILE_ELEMS + (wn * 32 + ntp * 16 + brow_l) * PITCH + kb + bcol_l);
                uint32_t r0, r1, r2, r3;
                LDM4(r0, r1, r2, r3, bd);
                bh[2 * ntp][0] = r0; bh[2 * ntp][1] = r1;
                bh[2 * ntp + 1][0] = r2; bh[2 * ntp + 1][1] = r3;
                LDM4(r0, r1, r2, r3, bd + 2u * TILE_ELEMS);
                bl[2 * ntp][0] = r0; bl[2 * ntp][1] = r1;
                bl[2 * ntp + 1][0] = r2; bl[2 * ntp + 1][1] = r3;
            }
            #pragma unroll
            for (int mt = 0; mt < 4; mt++)
                #pragma unroll
                for (int nt = 0; nt < 4; nt++) {
                    mma16816(acc[mt][nt], ah[mt], bh[nt][0], bh[nt][1]);
                    mma16816(acc[mt][nt], ah[mt], bl[nt][0], bl[nt][1]);
                    mma16816(acc[mt][nt], al[mt], bh[nt][0], bh[nt][1]);
                }
        }
        __syncthreads();
    }

    #pragma unroll
    for (int mt = 0; mt < 4; mt++) {
        int row = m0 + wm * 64 + mt * 16 + g;
        #pragma unroll
        for (int nt = 0; nt < 4; nt++) {
            int col = n0 + wn * 32 + nt * 8 + 2 * t4;
            *(float2*)&C[(size_t)row * N + col] = make_float2(acc[mt][nt][0], acc[mt][nt][1]);
            *(float2*)&C[(size_t)(row + 8) * N + col] = make_float2(acc[mt][nt][2], acc[mt][nt][3]);
        }
    }
}

// ---------------- fp32 -> bf16 hi/lo split ----------------
__global__ void split_kernel(const float* __restrict__ x,
                             __nv_bfloat16* __restrict__ hi,
                             __nv_bfloat16* __restrict__ lo, int n)
{
    int i = blockIdx.x * blockDim.x + threadIdx.x;
    if (i >= n) return;
    float v = x[i];
    __nv_bfloat16 h = __float2bfloat16(v);
    float r = v - __bfloat162float(h);
    hi[i] = h;
    lo[i] = __float2bfloat16(r);
}

// ---------------- W[K,N] -> (hi,lo)[N,K] transpose+split ----------------
__global__ void tsplit_kernel(const float* __restrict__ W,
                              __nv_bfloat16* __restrict__ hi,
                              __nv_bfloat16* __restrict__ lo, int K, int N)
{
    __shared__ float t[32][33];
    const int n0 = blockIdx.x * 32;
    const int k0 = blockIdx.y * 32;
    const int tx = threadIdx.x, ty = threadIdx.y;
    #pragma unroll
    for (int i = 0; i < 32; i += 8)
        t[ty + i][tx] = W[(size_t)(k0 + ty + i) * N + n0 + tx];
    __syncthreads();
    #pragma unroll
    for (int i = 0; i < 32; i += 8) {
        float v = t[tx][ty + i];
        __nv_bfloat16 h = __float2bfloat16(v);
        float r = v - __bfloat162float(h);
        size_t o = (size_t)(n0 + ty + i) * K + k0 + tx;
        hi[o] = h;
        lo[o] = __float2bfloat16(r);
    }
}

// ---------------- V [b,s,8,64] fp32 -> V^T [b,8,64,1024] bf16 hi/lo ----------------
__global__ void vtsplit_kernel(const float* __restrict__ v,
                               __nv_bfloat16* __restrict__ hi,
                               __nv_bfloat16* __restrict__ lo)
{
    __shared__ float t[32][33];
    const int s0 = blockIdx.x * 32;
    const int d0 = blockIdx.y * 32;
    const int b = blockIdx.z >> 3;
    const int h = blockIdx.z & 7;
    const int tx = threadIdx.x, ty = threadIdx.y;
    #pragma unroll
    for (int i = 0; i < 32; i += 8)
        t[ty + i][tx] = v[(((size_t)b * SEQ + s0 + ty + i) * HKV + h) * HD + d0 + tx];
    __syncthreads();
    #pragma unroll
    for (int i = 0; i < 32; i += 8) {
        float x = t[tx][ty + i];          // v[s0+tx][d0+ty+i]
        __nv_bfloat16 hh = __float2bfloat16(x);
        float r = x - __bfloat162float(hh);
        size_t o = (((size_t)b * HKV + h) * HD + d0 + ty + i) * SEQ + s0 + tx;
        hi[o] = hh;
        lo[o] = __float2bfloat16(r);
    }
}

// ---------------- RoPE + bf16 split ----------------
__global__ void rope_split_kernel(const float* __restrict__ x,
                                  __nv_bfloat16* __restrict__ hi,
                                  __nv_bfloat16* __restrict__ lo, int heads)
{
    int idx = blockIdx.x * blockDim.x + threadIdx.x;
    int total = BATCH * SEQ * heads * (HD / 2);
    if (idx >= total) return;
    int dpair = idx & 31;
    int t = idx >> 5;
    int h = t % heads;  t /= heads;
    int s = t % SEQ;
    int b = t / SEQ;

    float inv = powf(10000.0f, -(float)(2 * dpair) / (float)HD);
    float ang = (float)s * inv;
    float sn, cs;
    sincosf(ang, &sn, &cs);

    size_t base = (((size_t)b * SEQ + s) * heads + h) * HD + dpair;
    float x1 = x[base];
    float x2 = x[base + HD / 2];
    float y1 = x1 * cs - x2 * sn;
    float y2 = x2 * cs + x1 * sn;

    __nv_bfloat16 h1 = __float2bfloat16(y1);
    __nv_bfloat16 h2 = __float2bfloat16(y2);
    hi[base] = h1;
    hi[base + HD / 2] = h2;
    lo[base] = __float2bfloat16(y1 - __bfloat162float(h1));
    lo[base + HD / 2] = __float2bfloat16(y2 - __bfloat162float(h2));
}

// ---------------- flash attention (tensor cores, split precision) ----------------
#define FPITCH 72
#define QH_OFF 0
#define QL_OFF (128 * FPITCH)
#define KH_OFF (256 * FPITCH)
#define KL_OFF (320 * FPITCH)
#define VH_OFF (384 * FPITCH)
#define VL_OFF (448 * FPITCH)
#define FLASH_SMEM (512 * FPITCH * 2)   // 73728 bytes

__global__ __launch_bounds__(256, 1) void flash_mma_kernel(
    const __nv_bfloat16* __restrict__ qhi, const __nv_bfloat16* __restrict__ qlo,
    const __nv_bfloat16* __restrict__ khi, const __nv_bfloat16* __restrict__ klo,
    const __nv_bfloat16* __restrict__ vthi, const __nv_bfloat16* __restrict__ vtlo,
    __nv_bfloat16* __restrict__ outHi, __nv_bfloat16* __restrict__ outLo)
{
    extern __shared__ char smem[];
    const uint32_t sb = smem_to_u32(smem);
    __nv_bfloat16* sm = (__nv_bfloat16*)smem;

    const int tid = threadIdx.x;
    const int wid = tid >> 5;       // 0..7
    const int lid = tid & 31;
    const int g = lid >> 2;
    const int t4 = lid & 3;
    const int qt = blockIdx.x;      // 0..7
    const int bh = blockIdx.y;      // 0..63
    const int b = bh >> 5;
    const int h = bh & 31;
    const int hkv = h >> 2;

    const int arow_l = (lid & 7) + ((lid >> 3) & 1) * 8;
    const int acol_l = (lid >> 4) * 8;
    const int brow_l = (lid & 7) + (lid >> 4) * 8;
    const int bcol_l = ((lid >> 3) & 1) * 8;

    // ---- load Q tile (128 x 64) hi/lo ----
    #pragma unroll
    for (int it = 0; it < 4; it++) {
        int idx = tid + it * 256;          // 0..1023
        int row = idx >> 3;
        int ch = idx & 7;
        size_t goff = (((size_t)b * SEQ + qt * 128 + row) * HQ + h) * HD + ch * 8;
        *(uint4*)&sm[QH_OFF + row * FPITCH + ch * 8] = *(const uint4*)&qhi[goff];
        *(uint4*)&sm[QL_OFF + row * FPITCH + ch * 8] = *(const uint4*)&qlo[goff];
    }
    __syncthreads();

    // ---- Q fragments (held in regs for the whole kernel) ----
    uint32_t qh[4][4], ql[4][4];
    #pragma unroll
    for (int ks = 0; ks < 4; ks++) {
        uint32_t ad = sb + 2u * (uint32_t)(QH_OFF + (wid * 16 + arow_l) * FPITCH + ks * 16 + acol_l);
        LDM4(qh[ks][0], qh[ks][1], qh[ks][2], qh[ks][3], ad);
        ad = sb + 2u * (uint32_t)(QL_OFF + (wid * 16 + arow_l) * FPITCH + ks * 16 + acol_l);
        LDM4(ql[ks][0], ql[ks][1], ql[ks][2], ql[ks][3], ad);
    }

    float m0 = -1e30f, m1 = -1e30f, l0 = 0.f, l1 = 0.f;
    float oacc[8][4];
    #pragma unroll
    for (int nt = 0; nt < 8; nt++)
        #pragma unroll
        for (int r = 0; r < 4; r++) oacc[nt][r] = 0.f;

    const int row0 = qt * 128 + wid * 16;
    const int r_g = row0 + g;
    const int r_g8 = r_g + 8;
    const float scale = 0.125f;
    const int nkt = 2 * qt + 2;

    for (int kt = 0; kt < nkt; kt++) {
        // ---- load K, V^T tiles (4 x 64x64 bf16) ----
        #pragma unroll
        for (int it = 0; it < 8; it++) {
            int idx = tid + it * 256;       // 0..2047
            int tile = idx >> 9;
            int r = (idx >> 3) & 63;
            int ch = idx & 7;
            const __nv_bfloat16* src;
            int dstoff;
            if (tile == 0) { src = &khi[(((size_t)b * SEQ + kt * 64 + r) * HKV + hkv) * HD + ch * 8]; dstoff = KH_OFF; }
            else if (tile == 1) { src = &klo[(((size_t)b * SEQ + kt * 64 + r) * HKV + hkv) * HD + ch * 8]; dstoff = KL_OFF; }
            else if (tile == 2) { src = &vthi[(((size_t)b * HKV + hkv) * HD + r) * SEQ + kt * 64 + ch * 8]; dstoff = VH_OFF; }
            else { src = &vtlo[(((size_t)b * HKV + hkv) * HD + r) * SEQ + kt * 64 + ch * 8]; dstoff = VL_OFF; }
            *(uint4*)&sm[dstoff + r * FPITCH + ch * 8] = *(const uint4*)src;
        }
        __syncthreads();

        // ---- S = Q K^T (bf16x3) ----
        float sacc[8][4];
        #pragma unroll
        for (int nt = 0; nt < 8; nt++)
            #pragma unroll
            for (int r = 0; r < 4; r++) sacc[nt][r] = 0.f;

        #pragma unroll
        for (int ks = 0; ks < 4; ks++) {
            #pragma unroll
            for (int ntp = 0; ntp < 4; ntp++) {
                uint32_t bd = sb + 2u * (uint32_t)(KH_OFF + (ntp * 16 + brow_l) * FPITCH + ks * 16 + bcol_l);
                uint32_t h0, h1, h2, h3, u0, u1, u2, u3;
                LDM4(h0, h1, h2, h3, bd);
                bd = sb + 2u * (uint32_t)(KL_OFF + (ntp * 16 + brow_l) * FPITCH + ks * 16 + bcol_l);
                LDM4(u0, u1, u2, u3, bd);
                mma16816(sacc[2 * ntp], qh[ks], h0, h1);
                mma16816(sacc[2 * ntp], qh[ks], u0, u1);
                mma16816(sacc[2 * ntp], ql[ks], h0, h1);
                mma16816(sacc[2 * ntp + 1], qh[ks], h2, h3);
                mma16816(sacc[2 * ntp + 1], qh[ks], u2, u3);
                mma16816(sacc[2 * ntp + 1], ql[ks], h2, h3);
            }
        }

        // ---- scale + causal mask + row max ----
        const bool maybe_mask = (kt * 64 + 63 > row0);
        float mx0 = -1e30f, mx1 = -1e30f;
        #pragma unroll
        for (int nt = 0; nt < 8; nt++) {
            #pragma unroll
            for (int r = 0; r < 4; r++) sacc[nt][r] *= scale;
            if (maybe_mask) {
                int colb = kt * 64 + nt * 8 + 2 * t4;
                if (colb > r_g)      sacc[nt][0] = NEG_BIG;
                if (colb + 1 > r_g)  sacc[nt][1] = NEG_BIG;
                if (colb > r_g8)     sacc[nt][2] = NEG_BIG;
                if (colb + 1 > r_g8) sacc[nt][3] = NEG_BIG;
            }
            mx0 = fmaxf(mx0, fmaxf(sacc[nt][0], sacc[nt][1]));
            mx1 = fmaxf(mx1, fmaxf(sacc[nt][2], sacc[nt][3]));
        }
        mx0 = fmaxf(mx0, __shfl_xor_sync(0xffffffffu, mx0, 1));
        mx0 = fmaxf(mx0, __shfl_xor_sync(0xffffffffu, mx0, 2));
        mx1 = fmaxf(mx1, __shfl_xor_sync(0xffffffffu, mx1, 1));
        mx1 = fmaxf(mx1, __shfl_xor_sync(0xffffffffu, mx1, 2));

        float mn0 = fmaxf(m0, mx0), mn1 = fmaxf(m1, mx1);
        float corr0 = __expf(m0 - mn0), corr1 = __expf(m1 - mn1);

        // ---- exp + row sum + pack P (hi/lo) ----
        uint32_t ph[8][2], pl[8][2];
        float rs0 = 0.f, rs1 = 0.f;
        #pragma unroll
        for (int nt = 0; nt < 8; nt++) {
            float p00 = __expf(sacc[nt][0] - mn0);
            float p01 = __expf(sacc[nt][1] - mn0);
            float p10 = __expf(sacc[nt][2] - mn1);
            float p11 = __expf(sacc[nt][3] - mn1);
            rs0 += p00 + p01;
            rs1 += p10 + p11;
            float h00 = __bfloat162float(__float2bfloat16(p00));
            float h01 = __bfloat162float(__float2bfloat16(p01));
            float h10 = __bfloat162float(__float2bfloat16(p10));
            float h11 = __bfloat162float(__float2bfloat16(p11));
            ph[nt][0] = pack_bf16x2(h00, h01);
            ph[nt][1] = pack_bf16x2(h10, h11);
            pl[nt][0] = pack_bf16x2(p00 - h00, p01 - h01);
            pl[nt][1] = pack_bf16x2(p10 - h10, p11 - h11);
        }
        rs0 += __shfl_xor_sync(0xffffffffu, rs0, 1);
        rs0 += __shfl_xor_sync(0xffffffffu, rs0, 2);
        rs1 += __shfl_xor_sync(0xffffffffu, rs1, 1);
        rs1 += __shfl_xor_sync(0xffffffffu, rs1, 2);

        l0 = l0 * corr0 + rs0;
        l1 = l1 * corr1 + rs1;
        m0 = mn0; m1 = mn1;
        #pragma unroll
        for (int nt = 0; nt < 8; nt++) {
            oacc[nt][0] *= corr0; oacc[nt][1] *= corr0;
            oacc[nt][2] *= corr1; oacc[nt][3] *= corr1;
        }

        // ---- O += P V ----
        #pragma unroll
        for (int ks = 0; ks < 4; ks++) {
            uint32_t pah[4] = { ph[2 * ks][0], ph[2 * ks][1], ph[2 * ks + 1][0], ph[2 * ks + 1][1] };
            uint32_t pal[4] = { pl[2 * ks][0], pl[2 * ks][1], pl[2 * ks + 1][0], pl[2 * ks + 1][1] };
            #pragma unroll
            for (int ntp = 0; ntp < 4; ntp++) {
                uint32_t bd = sb + 2u * (uint32_t)(VH_OFF + (ntp * 16 + brow_l) * FPITCH + ks * 16 + bcol_l);
                uint32_t v0, v1, v2, v3, w0, w1, w2, w3;
                LDM4(v0, v1, v2, v3, bd);
                bd = sb + 2u * (uint32_t)(VL_OFF + (ntp * 16 + brow_l) * FPITCH + ks * 16 + bcol_l);
                LDM4(w0, w1, w2, w3, bd);
                mma16816(oacc[2 * ntp], pah, v0, v1);
                mma16816(oacc[2 * ntp], pah, w0, w1);
                mma16816(oacc[2 * ntp], pal, v0, v1);
                mma16816(oacc[2 * ntp + 1], pah, v2, v3);
                mma16816(oacc[2 * ntp + 1], pah, w2, w3);
                mma16816(oacc[2 * ntp + 1], pal, v2, v3);
            }
        }
        __syncthreads();
    }

    // ---- epilogue: normalize, split, store ----
    float inv0 = 1.0f / l0, inv1 = 1.0f / l1;
    uint32_t* oHi = (uint32_t*)outHi;
    uint32_t* oLo = (uint32_t*)outLo;
    #pragma unroll
    for (int nt = 0; nt < 8; nt++) {
        float o00 = oacc[nt][0] * inv0, o01 = oacc[nt][1] * inv0;
        float o10 = oacc[nt][2] * inv1, o11 = oacc[nt][3] * inv1;
        float h00 = __bfloat162float(__float2bfloat16(o00));
        float h01 = __bfloat162float(__float2bfloat16(o01));
        float h10 = __bfloat162float(__float2bfloat16(o10));
        float h11 = __bfloat162float(__float2bfloat16(o11));
        size_t row = (size_t)b * SEQ + qt * 128 + wid * 16 + g;
        int col = h * 64 + nt * 8 + 2 * t4;
        oHi[(row * 2048 + col) >> 1] = pack_bf16x2(h00, h01);
        oLo[(row * 2048 + col) >> 1] = pack_bf16x2(o00 - h00, o01 - h01);
        oHi[((row + 8) * 2048 + col) >> 1] = pack_bf16x2(h10, h11);
        oLo[((row + 8) * 2048 + col) >> 1] = pack_bf16x2(o10 - h10, o11 - h11);
    }
}

// ---------------- launcher ----------------
extern "C" void kernel_launch(void* const* d_in, const int* in_sizes, int n_in,
                              void* d_out, int out_size)
{
    const float* hidden = (const float*)d_in[0];
    const float* Wq = (const float*)d_in[2];
    const float* Wk = (const float*)d_in[3];
    const float* Wv = (const float*)d_in[4];
    const float* Wo = (const float*)d_in[5];
    float* out = (float*)d_out;

    float *q_ptr, *k_ptr, *v_ptr;
    cudaGetSymbolAddress((void**)&q_ptr, g_q);
    cudaGetSymbolAddress((void**)&k_ptr, g_k);
    cudaGetSymbolAddress((void**)&v_ptr, g_v);

    __nv_bfloat16 *aHi, *aLo, *bqH, *bqL, *bkH, *bkL, *bvH, *bvL, *boH, *boL;
    __nv_bfloat16 *qH, *qL, *kH, *kL, *vtH, *vtL;
    cudaGetSymbolAddress((void**)&aHi, gA_hi);
    cudaGetSymbolAddress((void**)&aLo, gA_lo);
    cudaGetSymbolAddress((void**)&bqH, gBq_hi);
    cudaGetSymbolAddress((void**)&bqL, gBq_lo);
    cudaGetSymbolAddress((void**)&bkH, gBk_hi);
    cudaGetSymbolAddress((void**)&bkL, gBk_lo);
    cudaGetSymbolAddress((void**)&bvH, gBv_hi);
    cudaGetSymbolAddress((void**)&bvL, gBv_lo);
    cudaGetSymbolAddress((void**)&boH, gBo_hi);
    cudaGetSymbolAddress((void**)&boL, gBo_lo);
    cudaGetSymbolAddress((void**)&qH, gQhi);
    cudaGetSymbolAddress((void**)&qL, gQlo);
    cudaGetSymbolAddress((void**)&kH, gKhi);
    cudaGetSymbolAddress((void**)&kL, gKlo);
    cudaGetSymbolAddress((void**)&vtH, gVThi);
    cudaGetSymbolAddress((void**)&vtL, gVTlo);

    cudaFuncSetAttribute(gemm_bf16x3_kernel, cudaFuncAttributeMaxDynamicSharedMemorySize, GEMM_SMEM);
    cudaFuncSetAttribute(flash_mma_kernel, cudaFuncAttributeMaxDynamicSharedMemorySize, FLASH_SMEM);

    // 1) splits
    {
        int n = MROWS * KDIM;
        split_kernel<<<(n + 255) / 256, 256>>>(hidden, aHi, aLo, n);
        dim3 tb(32, 8);
        tsplit_kernel<<<dim3(2048 / 32, KDIM / 32), tb>>>(Wq, bqH, bqL, KDIM, 2048);
        tsplit_kernel<<<dim3(512 / 32,  KDIM / 32), tb>>>(Wk, bkH, bkL, KDIM, 512);
        tsplit_kernel<<<dim3(512 / 32,  KDIM / 32), tb>>>(Wv, bvH, bvL, KDIM, 512);
        tsplit_kernel<<<dim3(2048 / 32, KDIM / 32), tb>>>(Wo, boH, boL, KDIM, 2048);
    }

    // 2) QKV projections
    gemm_bf16x3_kernel<<<dim3(2048 / 128, MROWS / 128), 256, GEMM_SMEM>>>(aHi, aLo, bqH, bqL, q_ptr, 2048);
    gemm_bf16x3_kernel<<<dim3(512 / 128,  MROWS / 128), 256, GEMM_SMEM>>>(aHi, aLo, bkH, bkL, k_ptr, 512);
    gemm_bf16x3_kernel<<<dim3(512 / 128,  MROWS / 128), 256, GEMM_SMEM>>>(aHi, aLo, bvH, bvL, v_ptr, 512);

    // 3) RoPE + split; V transpose + split
    {
        int nq = BATCH * SEQ * HQ * (HD / 2);
        rope_split_kernel<<<(nq + 255) / 256, 256>>>(q_ptr, qH, qL, HQ);
        int nk = BATCH * SEQ * HKV * (HD / 2);
        rope_split_kernel<<<(nk + 255) / 256, 256>>>(k_ptr, kH, kL, HKV);
        dim3 tb(32, 8);
        vtsplit_kernel<<<dim3(SEQ / 32, HD / 32, BATCH * HKV), tb>>>(v_ptr, vtH, vtL);
    }

    // 4) attention (writes split output directly into aHi/aLo)
    {
        dim3 g(SEQ / 128, BATCH * HQ);
        flash_mma_kernel<<<g, 256, FLASH_SMEM>>>(qH, qL, kH, kL, vtH, vtL, aHi, aLo);
    }

    // 5) output projection
    gemm_bf16x3_kernel<<<dim3(2048 / 128, MROWS / 128), 256, GEMM_SMEM>>>(aHi, aLo, boH, boL, out, 2048);
}

// round 5
// speedup vs baseline: 3.2578x; 1.1354x over previous
#include <cuda_runtime.h>
#include <cuda_bf16.h>
#include <math.h>
#include <stdint.h>

// ---------------- problem constants ----------------
#define BATCH 2
#define SEQ 1024
#define HIDDEN 2048
#define HQ 32
#define HKV 8
#define HD 64
#define MROWS (BATCH * SEQ)     // 2048
#define KDIM HIDDEN             // 2048
#define NQKV 3072               // fused q(2048) | k(512) | v(512)
#define NEG_BIG (-1e9f)

// ---------------- scratch ----------------
__device__ float g_qkv[MROWS * NQKV];            // fused projection output (fp32)

__device__ __nv_bfloat16 gA_hi[MROWS * KDIM];
__device__ __nv_bfloat16 gA_lo[MROWS * KDIM];
__device__ __nv_bfloat16 gBqkv_hi[NQKV * KDIM];  // [3072, 2048] = Wq^T | Wk^T | Wv^T
__device__ __nv_bfloat16 gBqkv_lo[NQKV * KDIM];
__device__ __nv_bfloat16 gBo_hi[2048 * KDIM];
__device__ __nv_bfloat16 gBo_lo[2048 * KDIM];

// flash operands (bf16 split)
__device__ __nv_bfloat16 gQhi[MROWS * HQ * HD];
__device__ __nv_bfloat16 gQlo[MROWS * HQ * HD];
__device__ __nv_bfloat16 gKhi[MROWS * HKV * HD];
__device__ __nv_bfloat16 gKlo[MROWS * HKV * HD];
__device__ __nv_bfloat16 gVThi[BATCH * HKV * HD * SEQ];
__device__ __nv_bfloat16 gVTlo[BATCH * HKV * HD * SEQ];

// ---------------- helpers ----------------
__device__ __forceinline__ uint32_t smem_to_u32(const void* p) {
    uint32_t a;
    asm("{ .reg .u64 t; cvta.to.shared.u64 t, %1; cvt.u32.u64 %0, t; }" : "=r"(a) : "l"(p));
    return a;
}
#define LDM4(r0, r1, r2, r3, addr) \
    asm volatile("ldmatrix.sync.aligned.m8n8.x4.shared.b16 {%0,%1,%2,%3}, [%4];" \
        : "=r"(r0), "=r"(r1), "=r"(r2), "=r"(r3) : "r"(addr))

__device__ __forceinline__ void mma16816(float* d, const uint32_t* a, uint32_t b0, uint32_t b1) {
    asm volatile("mma.sync.aligned.m16n8k16.row.col.f32.bf16.bf16.f32 "
        "{%0,%1,%2,%3}, {%4,%5,%6,%7}, {%8,%9}, {%0,%1,%2,%3};"
        : "+f"(d[0]), "+f"(d[1]), "+f"(d[2]), "+f"(d[3])
        : "r"(a[0]), "r"(a[1]), "r"(a[2]), "r"(a[3]), "r"(b0), "r"(b1));
}
__device__ __forceinline__ uint32_t pack_bf16x2(float lo, float hi) {
    uint32_t d;
    asm("cvt.rn.bf16x2.f32 %0, %1, %2;" : "=r"(d) : "f"(hi), "f"(lo));
    return d;
}

// ---------------- bf16x3 GEMM: 3-stage cp.async pipeline ----------------
#define BK 32
#define PITCH 40                                   // bf16 elems per smem row (80B)
#define TILE_ELEMS (128 * PITCH)                   // 5120
#define STAGE_ELEMS (4 * TILE_ELEMS)               // 20480 elems = 40960 B
#define NSTAGE 3
#define GEMM_SMEM (NSTAGE * STAGE_ELEMS * 2)       // 122880 bytes
#define NCHUNK (KDIM / BK)                         // 64

__device__ __forceinline__ void issue_stage(
    uint32_t sb, int stage,
    const __nv_bfloat16* __restrict__ Ahi, const __nv_bfloat16* __restrict__ Alo,
    const __nv_bfloat16* __restrict__ Bhi, const __nv_bfloat16* __restrict__ Blo,
    int m0, int n0, int k0, int tid)
{
    const __nv_bfloat16* bases[4] = {
        Ahi + (size_t)m0 * KDIM, Alo + (size_t)m0 * KDIM,
        Bhi + (size_t)n0 * KDIM, Blo + (size_t)n0 * KDIM };
    #pragma unroll
    for (int t = 0; t < 8; t++) {
        int idx = tid + t * 256;
        int tile = idx >> 9;
        int row  = (idx >> 2) & 127;
        int ch   = idx & 3;
        const __nv_bfloat16* src = bases[tile] + (size_t)row * KDIM + k0 + ch * 8;
        uint32_t dst = sb + 2u * (uint32_t)(stage * STAGE_ELEMS + tile * TILE_ELEMS + row * PITCH + ch * 8);
        asm volatile("cp.async.cg.shared.global [%0], [%1], 16;" :: "r"(dst), "l"(src));
    }
    asm volatile("cp.async.commit_group;");
}

__global__ __launch_bounds__(256, 1) void gemm_bf16x3_kernel(
    const __nv_bfloat16* __restrict__ Ahi, const __nv_bfloat16* __restrict__ Alo,
    const __nv_bfloat16* __restrict__ Bhi, const __nv_bfloat16* __restrict__ Blo,
    float* __restrict__ C, int N)
{
    extern __shared__ char smem[];
    const uint32_t sb = smem_to_u32(smem);
    const int tid = threadIdx.x;
    const int wid = tid >> 5;
    const int lid = tid & 31;
    const int wm = wid >> 2;
    const int wn = wid & 3;
    const int g = lid >> 2;
    const int t4 = lid & 3;
    const int n0 = blockIdx.x * 128;
    const int m0 = blockIdx.y * 128;

    const int arow_l = (lid & 7) + ((lid >> 3) & 1) * 8;
    const int acol_l = (lid >> 4) * 8;
    const int brow_l = (lid & 7) + (lid >> 4) * 8;
    const int bcol_l = ((lid >> 3) & 1) * 8;

    float acc[4][4][4];
    #pragma unroll
    for (int i = 0; i < 4; i++)
        #pragma unroll
        for (int j = 0; j < 4; j++)
            #pragma unroll
            for (int r = 0; r < 4; r++) acc[i][j][r] = 0.f;

    issue_stage(sb, 0, Ahi, Alo, Bhi, Blo, m0, n0, 0, tid);
    issue_stage(sb, 1, Ahi, Alo, Bhi, Blo, m0, n0, BK, tid);

    int p = 0;
    for (int i = 0; i < NCHUNK; i++) {
        if (i + 2 < NCHUNK) {
            int st = p + 2; if (st >= NSTAGE) st -= NSTAGE;
            issue_stage(sb, st, Ahi, Alo, Bhi, Blo, m0, n0, (i + 2) * BK, tid);
            asm volatile("cp.async.wait_group 2;" ::: "memory");
        } else if (i + 1 < NCHUNK) {
            asm volatile("cp.async.wait_group 1;" ::: "memory");
        } else {
            asm volatile("cp.async.wait_group 0;" ::: "memory");
        }
        __syncthreads();

        const uint32_t base = sb + 2u * (uint32_t)(p * STAGE_ELEMS);
        #pragma unroll
        for (int ks = 0; ks < 2; ks++) {
            const int kb = ks * 16;
            uint32_t ah[4][4], al[4][4], bh[4][2], bl[4][2];
            #pragma unroll
            for (int mt = 0; mt < 4; mt++) {
                uint32_t ad = base + 2u * (uint32_t)((wm * 64 + mt * 16 + arow_l) * PITCH + kb + acol_l);
                LDM4(ah[mt][0], ah[mt][1], ah[mt][2], ah[mt][3], ad);
                LDM4(al[mt][0], al[mt][1], al[mt][2], al[mt][3], ad + 2u * TILE_ELEMS);
            }
            #pragma unroll
            for (int ntp = 0; ntp < 2; ntp++) {
                uint32_t bd = base + 2u * (uint32_t)(2 * TILE_ELEMS + (wn * 32 + ntp * 16 + brow_l) * PITCH + kb + bcol_l);
                uint32_t r0, r1, r2, r3;
                LDM4(r0, r1, r2, r3, bd);
                bh[2 * ntp][0] = r0; bh[2 * ntp][1] = r1;
                bh[2 * ntp + 1][0] = r2; bh[2 * ntp + 1][1] = r3;
                LDM4(r0, r1, r2, r3, bd + 2u * TILE_ELEMS);
                bl[2 * ntp][0] = r0; bl[2 * ntp][1] = r1;
                bl[2 * ntp + 1][0] = r2; bl[2 * ntp + 1][1] = r3;
            }
            #pragma unroll
            for (int mt = 0; mt < 4; mt++)
                #pragma unroll
                for (int nt = 0; nt < 4; nt++) {
                    mma16816(acc[mt][nt], ah[mt], bh[nt][0], bh[nt][1]);
                    mma16816(acc[mt][nt], ah[mt], bl[nt][0], bl[nt][1]);
                    mma16816(acc[mt][nt], al[mt], bh[nt][0], bh[nt][1]);
                }
        }
        __syncthreads();
        if (++p == NSTAGE) p = 0;
    }

    #pragma unroll
    for (int mt = 0; mt < 4; mt++) {
        int row = m0 + wm * 64 + mt * 16 + g;
        #pragma unroll
        for (int nt = 0; nt < 4; nt++) {
            int col = n0 + wn * 32 + nt * 8 + 2 * t4;
            *(float2*)&C[(size_t)row * N + col] = make_float2(acc[mt][nt][0], acc[mt][nt][1]);
            *(float2*)&C[(size_t)(row + 8) * N + col] = make_float2(acc[mt][nt][2], acc[mt][nt][3]);
        }
    }
}

// ---------------- fp32 -> bf16 hi/lo split ----------------
__global__ void split_kernel(const float* __restrict__ x,
                             __nv_bfloat16* __restrict__ hi,
                             __nv_bfloat16* __restrict__ lo, int n)
{
    int i = blockIdx.x * blockDim.x + threadIdx.x;
    if (i >= n) return;
    float v = x[i];
    __nv_bfloat16 h = __float2bfloat16(v);
    float r = v - __bfloat162float(h);
    hi[i] = h;
    lo[i] = __float2bfloat16(r);
}

// ---------------- W[K,N] -> (hi,lo)[N,K] transpose+split ----------------
__global__ void tsplit_kernel(const float* __restrict__ W,
                              __nv_bfloat16* __restrict__ hi,
                              __nv_bfloat16* __restrict__ lo, int K, int N)
{
    __shared__ float t[32][33];
    const int n0 = blockIdx.x * 32;
    const int k0 = blockIdx.y * 32;
    const int tx = threadIdx.x, ty = threadIdx.y;
    #pragma unroll
    for (int i = 0; i < 32; i += 8)
        t[ty + i][tx] = W[(size_t)(k0 + ty + i) * N + n0 + tx];
    __syncthreads();
    #pragma unroll
    for (int i = 0; i < 32; i += 8) {
        float v = t[tx][ty + i];
        __nv_bfloat16 h = __float2bfloat16(v);
        float r = v - __bfloat162float(h);
        size_t o = (size_t)(n0 + ty + i) * K + k0 + tx;
        hi[o] = h;
        lo[o] = __float2bfloat16(r);
    }
}

// ---------------- V cols of qkv -> V^T [b,8,64,1024] bf16 hi/lo ----------------
__global__ void vtsplit_kernel(const float* __restrict__ qkv,
                               __nv_bfloat16* __restrict__ hi,
                               __nv_bfloat16* __restrict__ lo)
{
    __shared__ float t[32][33];
    const int s0 = blockIdx.x * 32;
    const int d0 = blockIdx.y * 32;
    const int b = blockIdx.z >> 3;
    const int h = blockIdx.z & 7;
    const int tx = threadIdx.x, ty = threadIdx.y;
    #pragma unroll
    for (int i = 0; i < 32; i += 8)
        t[ty + i][tx] = qkv[((size_t)b * SEQ + s0 + ty + i) * NQKV + 2560 + h * HD + d0 + tx];
    __syncthreads();
    #pragma unroll
    for (int i = 0; i < 32; i += 8) {
        float x = t[tx][ty + i];
        __nv_bfloat16 hh = __float2bfloat16(x);
        float r = x - __bfloat162float(hh);
        size_t o = (((size_t)b * HKV + h) * HD + d0 + ty + i) * SEQ + s0 + tx;
        hi[o] = hh;
        lo[o] = __float2bfloat16(r);
    }
}

// ---------------- RoPE + bf16 split (reads fused qkv) ----------------
__global__ void rope_split_kernel(const float* __restrict__ qkv, int colOff,
                                  __nv_bfloat16* __restrict__ hi,
                                  __nv_bfloat16* __restrict__ lo, int heads)
{
    int idx = blockIdx.x * blockDim.x + threadIdx.x;
    int total = BATCH * SEQ * heads * (HD / 2);
    if (idx >= total) return;
    int dpair = idx & 31;
    int t = idx >> 5;
    int h = t % heads;  t /= heads;
    int s = t % SEQ;
    int b = t / SEQ;

    float inv = powf(10000.0f, -(float)(2 * dpair) / (float)HD);
    float ang = (float)s * inv;
    float sn, cs;
    sincosf(ang, &sn, &cs);

    size_t src = ((size_t)b * SEQ + s) * NQKV + colOff + h * HD + dpair;
    float x1 = qkv[src];
    float x2 = qkv[src + HD / 2];
    float y1 = x1 * cs - x2 * sn;
    float y2 = x2 * cs + x1 * sn;

    size_t base = (((size_t)b * SEQ + s) * heads + h) * HD + dpair;
    __nv_bfloat16 h1 = __float2bfloat16(y1);
    __nv_bfloat16 h2 = __float2bfloat16(y2);
    hi[base] = h1;
    hi[base + HD / 2] = h2;
    lo[base] = __float2bfloat16(y1 - __bfloat162float(h1));
    lo[base + HD / 2] = __float2bfloat16(y2 - __bfloat162float(h2));
}

// ---------------- flash attention (tensor cores, split precision) ----------------
#define FPITCH 72
#define QH_OFF 0
#define QL_OFF (128 * FPITCH)
#define KH_OFF (256 * FPITCH)
#define KL_OFF (320 * FPITCH)
#define VH_OFF (384 * FPITCH)
#define VL_OFF (448 * FPITCH)
#define FLASH_SMEM (512 * FPITCH * 2)   // 73728 bytes

__global__ __launch_bounds__(256, 1) void flash_mma_kernel(
    const __nv_bfloat16* __restrict__ qhi, const __nv_bfloat16* __restrict__ qlo,
    const __nv_bfloat16* __restrict__ khi, const __nv_bfloat16* __restrict__ klo,
    const __nv_bfloat16* __restrict__ vthi, const __nv_bfloat16* __restrict__ vtlo,
    __nv_bfloat16* __restrict__ outHi, __nv_bfloat16* __restrict__ outLo)
{
    extern __shared__ char smem[];
    const uint32_t sb = smem_to_u32(smem);
    __nv_bfloat16* sm = (__nv_bfloat16*)smem;

    const int tid = threadIdx.x;
    const int wid = tid >> 5;
    const int lid = tid & 31;
    const int g = lid >> 2;
    const int t4 = lid & 3;
    const int qt = blockIdx.x;
    const int bh = blockIdx.y;
    const int b = bh >> 5;
    const int h = bh & 31;
    const int hkv = h >> 2;

    const int arow_l = (lid & 7) + ((lid >> 3) & 1) * 8;
    const int acol_l = (lid >> 4) * 8;
    const int brow_l = (lid & 7) + (lid >> 4) * 8;
    const int bcol_l = ((lid >> 3) & 1) * 8;

    #pragma unroll
    for (int it = 0; it < 4; it++) {
        int idx = tid + it * 256;
        int row = idx >> 3;
        int ch = idx & 7;
        size_t goff = (((size_t)b * SEQ + qt * 128 + row) * HQ + h) * HD + ch * 8;
        *(uint4*)&sm[QH_OFF + row * FPITCH + ch * 8] = *(const uint4*)&qhi[goff];
        *(uint4*)&sm[QL_OFF + row * FPITCH + ch * 8] = *(const uint4*)&qlo[goff];
    }
    __syncthreads();

    uint32_t qh[4][4], ql[4][4];
    #pragma unroll
    for (int ks = 0; ks < 4; ks++) {
        uint32_t ad = sb + 2u * (uint32_t)(QH_OFF + (wid * 16 + arow_l) * FPITCH + ks * 16 + acol_l);
        LDM4(qh[ks][0], qh[ks][1], qh[ks][2], qh[ks][3], ad);
        ad = sb + 2u * (uint32_t)(QL_OFF + (wid * 16 + arow_l) * FPITCH + ks * 16 + acol_l);
        LDM4(ql[ks][0], ql[ks][1], ql[ks][2], ql[ks][3], ad);
    }

    float m0 = -1e30f, m1 = -1e30f, l0 = 0.f, l1 = 0.f;
    float oacc[8][4];
    #pragma unroll
    for (int nt = 0; nt < 8; nt++)
        #pragma unroll
        for (int r = 0; r < 4; r++) oacc[nt][r] = 0.f;

    const int row0 = qt * 128 + wid * 16;
    const int r_g = row0 + g;
    const int r_g8 = r_g + 8;
    const float scale = 0.125f;
    const int nkt = 2 * qt + 2;

    for (int kt = 0; kt < nkt; kt++) {
        #pragma unroll
        for (int it = 0; it < 8; it++) {
            int idx = tid + it * 256;
            int tile = idx >> 9;
            int r = (idx >> 3) & 63;
            int ch = idx & 7;
            const __nv_bfloat16* src;
            int dstoff;
            if (tile == 0) { src = &khi[(((size_t)b * SEQ + kt * 64 + r) * HKV + hkv) * HD + ch * 8]; dstoff = KH_OFF; }
            else if (tile == 1) { src = &klo[(((size_t)b * SEQ + kt * 64 + r) * HKV + hkv) * HD + ch * 8]; dstoff = KL_OFF; }
            else if (tile == 2) { src = &vthi[(((size_t)b * HKV + hkv) * HD + r) * SEQ + kt * 64 + ch * 8]; dstoff = VH_OFF; }
            else { src = &vtlo[(((size_t)b * HKV + hkv) * HD + r) * SEQ + kt * 64 + ch * 8]; dstoff = VL_OFF; }
            *(uint4*)&sm[dstoff + r * FPITCH + ch * 8] = *(const uint4*)src;
        }
        __syncthreads();

        float sacc[8][4];
        #pragma unroll
        for (int nt = 0; nt < 8; nt++)
            #pragma unroll
            for (int r = 0; r < 4; r++) sacc[nt][r] = 0.f;

        #pragma unroll
        for (int ks = 0; ks < 4; ks++) {
            #pragma unroll
            for (int ntp = 0; ntp < 4; ntp++) {
                uint32_t bd = sb + 2u * (uint32_t)(KH_OFF + (ntp * 16 + brow_l) * FPITCH + ks * 16 + bcol_l);
                uint32_t h0, h1, h2, h3, u0, u1, u2, u3;
                LDM4(h0, h1, h2, h3, bd);
                bd = sb + 2u * (uint32_t)(KL_OFF + (ntp * 16 + brow_l) * FPITCH + ks * 16 + bcol_l);
                LDM4(u0, u1, u2, u3, bd);
                mma16816(sacc[2 * ntp], qh[ks], h0, h1);
                mma16816(sacc[2 * ntp], qh[ks], u0, u1);
                mma16816(sacc[2 * ntp], ql[ks], h0, h1);
                mma16816(sacc[2 * ntp + 1], qh[ks], h2, h3);
                mma16816(sacc[2 * ntp + 1], qh[ks], u2, u3);
                mma16816(sacc[2 * ntp + 1], ql[ks], h2, h3);
            }
        }

        const bool maybe_mask = (kt * 64 + 63 > row0);
        float mx0 = -1e30f, mx1 = -1e30f;
        #pragma unroll
        for (int nt = 0; nt < 8; nt++) {
            #pragma unroll
            for (int r = 0; r < 4; r++) sacc[nt][r] *= scale;
            if (maybe_mask) {
                int colb = kt * 64 + nt * 8 + 2 * t4;
                if (colb > r_g)      sacc[nt][0] = NEG_BIG;
                if (colb + 1 > r_g)  sacc[nt][1] = NEG_BIG;
                if (colb > r_g8)     sacc[nt][2] = NEG_BIG;
                if (colb + 1 > r_g8) sacc[nt][3] = NEG_BIG;
            }
            mx0 = fmaxf(mx0, fmaxf(sacc[nt][0], sacc[nt][1]));
            mx1 = fmaxf(mx1, fmaxf(sacc[nt][2], sacc[nt][3]));
        }
        mx0 = fmaxf(mx0, __shfl_xor_sync(0xffffffffu, mx0, 1));
        mx0 = fmaxf(mx0, __shfl_xor_sync(0xffffffffu, mx0, 2));
        mx1 = fmaxf(mx1, __shfl_xor_sync(0xffffffffu, mx1, 1));
        mx1 = fmaxf(mx1, __shfl_xor_sync(0xffffffffu, mx1, 2));

        float mn0 = fmaxf(m0, mx0), mn1 = fmaxf(m1, mx1);
        float corr0 = __expf(m0 - mn0), corr1 = __expf(m1 - mn1);

        uint32_t ph[8][2], pl[8][2];
        float rs0 = 0.f, rs1 = 0.f;
        #pragma unroll
        for (int nt = 0; nt < 8; nt++) {
            float p00 = __expf(sacc[nt][0] - mn0);
            float p01 = __expf(sacc[nt][1] - mn0);
            float p10 = __expf(sacc[nt][2] - mn1);
            float p11 = __expf(sacc[nt][3] - mn1);
            rs0 += p00 + p01;
            rs1 += p10 + p11;
            float h00 = __bfloat162float(__float2bfloat16(p00));
            float h01 = __bfloat162float(__float2bfloat16(p01));
            float h10 = __bfloat162float(__float2bfloat16(p10));
            float h11 = __bfloat162float(__float2bfloat16(p11));
            ph[nt][0] = pack_bf16x2(h00, h01);
            ph[nt][1] = pack_bf16x2(h10, h11);
            pl[nt][0] = pack_bf16x2(p00 - h00, p01 - h01);
            pl[nt][1] = pack_bf16x2(p10 - h10, p11 - h11);
        }
        rs0 += __shfl_xor_sync(0xffffffffu, rs0, 1);
        rs0 += __shfl_xor_sync(0xffffffffu, rs0, 2);
        rs1 += __shfl_xor_sync(0xffffffffu, rs1, 1);
        rs1 += __shfl_xor_sync(0xffffffffu, rs1, 2);

        l0 = l0 * corr0 + rs0;
        l1 = l1 * corr1 + rs1;
        m0 = mn0; m1 = mn1;
        #pragma unroll
        for (int nt = 0; nt < 8; nt++) {
            oacc[nt][0] *= corr0; oacc[nt][1] *= corr0;
            oacc[nt][2] *= corr1; oacc[nt][3] *= corr1;
        }

        #pragma unroll
        for (int ks = 0; ks < 4; ks++) {
            uint32_t pah[4] = { ph[2 * ks][0], ph[2 * ks][1], ph[2 * ks + 1][0], ph[2 * ks + 1][1] };
            uint32_t pal[4] = { pl[2 * ks][0], pl[2 * ks][1], pl[2 * ks + 1][0], pl[2 * ks + 1][1] };
            #pragma unroll
            for (int ntp = 0; ntp < 4; ntp++) {
                uint32_t bd = sb + 2u * (uint32_t)(VH_OFF + (ntp * 16 + brow_l) * FPITCH + ks * 16 + bcol_l);
                uint32_t v0, v1, v2, v3, w0, w1, w2, w3;
                LDM4(v0, v1, v2, v3, bd);
                bd = sb + 2u * (uint32_t)(VL_OFF + (ntp * 16 + brow_l) * FPITCH + ks * 16 + bcol_l);
                LDM4(w0, w1, w2, w3, bd);
                mma16816(oacc[2 * ntp], pah, v0, v1);
                mma16816(oacc[2 * ntp], pah, w0, w1);
                mma16816(oacc[2 * ntp], pal, v0, v1);
                mma16816(oacc[2 * ntp + 1], pah, v2, v3);
                mma16816(oacc[2 * ntp + 1], pah, w2, w3);
                mma16816(oacc[2 * ntp + 1], pal, v2, v3);
            }
        }
        __syncthreads();
    }

    float inv0 = 1.0f / l0, inv1 = 1.0f / l1;
    uint32_t* oHi = (uint32_t*)outHi;
    uint32_t* oLo = (uint32_t*)outLo;
    #pragma unroll
    for (int nt = 0; nt < 8; nt++) {
        float o00 = oacc[nt][0] * inv0, o01 = oacc[nt][1] * inv0;
        float o10 = oacc[nt][2] * inv1, o11 = oacc[nt][3] * inv1;
        float h00 = __bfloat162float(__float2bfloat16(o00));
        float h01 = __bfloat162float(__float2bfloat16(o01));
        float h10 = __bfloat162float(__float2bfloat16(o10));
        float h11 = __bfloat162float(__float2bfloat16(o11));
        size_t row = (size_t)b * SEQ + qt * 128 + wid * 16 + g;
        int col = h * 64 + nt * 8 + 2 * t4;
        oHi[(row * 2048 + col) >> 1] = pack_bf16x2(h00, h01);
        oLo[(row * 2048 + col) >> 1] = pack_bf16x2(o00 - h00, o01 - h01);
        oHi[((row + 8) * 2048 + col) >> 1] = pack_bf16x2(h10, h11);
        oLo[((row + 8) * 2048 + col) >> 1] = pack_bf16x2(o10 - h10, o11 - h11);
    }
}

// ---------------- launcher ----------------
extern "C" void kernel_launch(void* const* d_in, const int* in_sizes, int n_in,
                              void* d_out, int out_size)
{
    const float* hidden = (const float*)d_in[0];
    const float* Wq = (const float*)d_in[2];
    const float* Wk = (const float*)d_in[3];
    const float* Wv = (const float*)d_in[4];
    const float* Wo = (const float*)d_in[5];
    float* out = (float*)d_out;

    float* qkv_ptr;
    cudaGetSymbolAddress((void**)&qkv_ptr, g_qkv);

    __nv_bfloat16 *aHi, *aLo, *bH, *bL, *boH, *boL;
    __nv_bfloat16 *qH, *qL, *kH, *kL, *vtH, *vtL;
    cudaGetSymbolAddress((void**)&aHi, gA_hi);
    cudaGetSymbolAddress((void**)&aLo, gA_lo);
    cudaGetSymbolAddress((void**)&bH, gBqkv_hi);
    cudaGetSymbolAddress((void**)&bL, gBqkv_lo);
    cudaGetSymbolAddress((void**)&boH, gBo_hi);
    cudaGetSymbolAddress((void**)&boL, gBo_lo);
    cudaGetSymbolAddress((void**)&qH, gQhi);
    cudaGetSymbolAddress((void**)&qL, gQlo);
    cudaGetSymbolAddress((void**)&kH, gKhi);
    cudaGetSymbolAddress((void**)&kL, gKlo);
    cudaGetSymbolAddress((void**)&vtH, gVThi);
    cudaGetSymbolAddress((void**)&vtL, gVTlo);

    cudaFuncSetAttribute(gemm_bf16x3_kernel, cudaFuncAttributeMaxDynamicSharedMemorySize, GEMM_SMEM);
    cudaFuncSetAttribute(flash_mma_kernel, cudaFuncAttributeMaxDynamicSharedMemorySize, FLASH_SMEM);

    // 1) splits (weights concatenated into one [3072, 2048] B buffer)
    {
        int n = MROWS * KDIM;
        split_kernel<<<(n + 255) / 256, 256>>>(hidden, aHi, aLo, n);
        dim3 tb(32, 8);
        tsplit_kernel<<<dim3(2048 / 32, KDIM / 32), tb>>>(Wq, bH,                       bL,                       KDIM, 2048);
        tsplit_kernel<<<dim3(512 / 32,  KDIM / 32), tb>>>(Wk, bH + (size_t)2048 * KDIM, bL + (size_t)2048 * KDIM, KDIM, 512);
        tsplit_kernel<<<dim3(512 / 32,  KDIM / 32), tb>>>(Wv, bH + (size_t)2560 * KDIM, bL + (size_t)2560 * KDIM, KDIM, 512);
        tsplit_kernel<<<dim3(2048 / 32, KDIM / 32), tb>>>(Wo, boH, boL, KDIM, 2048);
    }

    // 2) fused QKV projection
    gemm_bf16x3_kernel<<<dim3(NQKV / 128, MROWS / 128), 256, GEMM_SMEM>>>(aHi, aLo, bH, bL, qkv_ptr, NQKV);

    // 3) RoPE + split; V transpose + split
    {
        int nq = BATCH * SEQ * HQ * (HD / 2);
        rope_split_kernel<<<(nq + 255) / 256, 256>>>(qkv_ptr, 0, qH, qL, HQ);
        int nk = BATCH * SEQ * HKV * (HD / 2);
        rope_split_kernel<<<(nk + 255) / 256, 256>>>(qkv_ptr, 2048, kH, kL, HKV);
        dim3 tb(32, 8);
        vtsplit_kernel<<<dim3(SEQ / 32, HD / 32, BATCH * HKV), tb>>>(qkv_ptr, vtH, vtL);
    }

    // 4) attention (writes split output directly into aHi/aLo)
    {
        dim3 g(SEQ / 128, BATCH * HQ);
        flash_mma_kernel<<<g, 256, FLASH_SMEM>>>(qH, qL, kH, kL, vtH, vtL, aHi, aLo);
    }

    // 5) output projection
    gemm_bf16x3_kernel<<<dim3(2048 / 128, MROWS / 128), 256, GEMM_SMEM>>>(aHi, aLo, boH, boL, out, 2048);
}

// round 6
// speedup vs baseline: 4.3008x; 1.3201x over previous
#include <cuda_runtime.h>
#include <cuda_fp16.h>
#include <math.h>
#include <stdint.h>

// ---------------- problem constants ----------------
#define BATCH 2
#define SEQ 1024
#define HIDDEN 2048
#define HQ 32
#define HKV 8
#define HD 64
#define MROWS (BATCH * SEQ)     // 2048
#define KDIM HIDDEN             // 2048
#define NQKV 3072               // fused q(2048) | k(512) | v(512)
#define NEG_BIG (-1e9f)

// ---------------- scratch ----------------
__device__ float g_qkv[MROWS * NQKV];        // fused projection output (fp32)

__device__ __half gA_hi[MROWS * KDIM];       // A operand hi (activations / attn-out)
__device__ __half gA_lo[MROWS * KDIM];       // A operand lo
__device__ __half gBqkv[NQKV * KDIM];        // [3072, 2048] = Wq^T | Wk^T | Wv^T (fp16)
__device__ __half gBo[2048 * KDIM];          // Wo^T (fp16)

// flash operands
__device__ __half gQhi[MROWS * HQ * HD];
__device__ __half gQlo[MROWS * HQ * HD];
__device__ __half gKhi[MROWS * HKV * HD];    // K single fp16
__device__ __half gVThi[BATCH * HKV * HD * SEQ];
__device__ __half gVTlo[BATCH * HKV * HD * SEQ];

// ---------------- helpers ----------------
__device__ __forceinline__ uint32_t smem_to_u32(const void* p) {
    uint32_t a;
    asm("{ .reg .u64 t; cvta.to.shared.u64 t, %1; cvt.u32.u64 %0, t; }" : "=r"(a) : "l"(p));
    return a;
}
#define LDM4(r0, r1, r2, r3, addr) \
    asm volatile("ldmatrix.sync.aligned.m8n8.x4.shared.b16 {%0,%1,%2,%3}, [%4];" \
        : "=r"(r0), "=r"(r1), "=r"(r2), "=r"(r3) : "r"(addr))

__device__ __forceinline__ void mma16816(float* d, const uint32_t* a, uint32_t b0, uint32_t b1) {
    asm volatile("mma.sync.aligned.m16n8k16.row.col.f32.f16.f16.f32 "
        "{%0,%1,%2,%3}, {%4,%5,%6,%7}, {%8,%9}, {%0,%1,%2,%3};"
        : "+f"(d[0]), "+f"(d[1]), "+f"(d[2]), "+f"(d[3])
        : "r"(a[0]), "r"(a[1]), "r"(a[2]), "r"(a[3]), "r"(b0), "r"(b1));
}
__device__ __forceinline__ uint32_t pack_f16x2(float lo, float hi) {
    uint32_t d;
    asm("cvt.rn.f16x2.f32 %0, %1, %2;" : "=r"(d) : "f"(hi), "f"(lo));
    return d;
}

// ---------------- fp16x2 GEMM: 4-stage cp.async pipeline ----------------
// C[M,N] = A[M,K] @ B^T; A = hi+lo fp16, B = single fp16 [N,K].
#define BK 32
#define PITCH 40                                   // fp16 elems per smem row (80B)
#define TILE_ELEMS (128 * PITCH)                   // 5120
#define STAGE_TILES 3                              // Ahi, Alo, B
#define STAGE_ELEMS (STAGE_TILES * TILE_ELEMS)     // 15360 elems = 30720 B
#define NSTAGE 4
#define GEMM_SMEM (NSTAGE * STAGE_ELEMS * 2)       // 122880 bytes
#define NCHUNK (KDIM / BK)                         // 64

__device__ __forceinline__ void issue_stage(
    uint32_t sb, int stage,
    const __half* __restrict__ Ahi, const __half* __restrict__ Alo,
    const __half* __restrict__ B,
    int m0, int n0, int k0, int tid)
{
    const __half* bases[3] = {
        Ahi + (size_t)m0 * KDIM, Alo + (size_t)m0 * KDIM, B + (size_t)n0 * KDIM };
    #pragma unroll
    for (int t = 0; t < 6; t++) {
        int idx = tid + t * 256;           // 0..1535
        int tile = idx >> 9;               // 0..2
        int row  = (idx >> 2) & 127;
        int ch   = idx & 3;
        const __half* src = bases[tile] + (size_t)row * KDIM + k0 + ch * 8;
        uint32_t dst = sb + 2u * (uint32_t)(stage * STAGE_ELEMS + tile * TILE_ELEMS + row * PITCH + ch * 8);
        asm volatile("cp.async.cg.shared.global [%0], [%1], 16;" :: "r"(dst), "l"(src));
    }
    asm volatile("cp.async.commit_group;");
}

__global__ __launch_bounds__(256, 1) void gemm_fp16x2_kernel(
    const __half* __restrict__ Ahi, const __half* __restrict__ Alo,
    const __half* __restrict__ B,
    float* __restrict__ C, int N)
{
    extern __shared__ char smem[];
    const uint32_t sb = smem_to_u32(smem);
    const int tid = threadIdx.x;
    const int wid = tid >> 5;
    const int lid = tid & 31;
    const int wm = wid >> 2;
    const int wn = wid & 3;
    const int g = lid >> 2;
    const int t4 = lid & 3;
    const int n0 = blockIdx.x * 128;
    const int m0 = blockIdx.y * 128;

    const int arow_l = (lid & 7) + ((lid >> 3) & 1) * 8;
    const int acol_l = (lid >> 4) * 8;
    const int brow_l = (lid & 7) + (lid >> 4) * 8;
    const int bcol_l = ((lid >> 3) & 1) * 8;

    float acc[4][4][4];
    #pragma unroll
    for (int i = 0; i < 4; i++)
        #pragma unroll
        for (int j = 0; j < 4; j++)
            #pragma unroll
            for (int r = 0; r < 4; r++) acc[i][j][r] = 0.f;

    issue_stage(sb, 0, Ahi, Alo, B, m0, n0, 0, tid);
    issue_stage(sb, 1, Ahi, Alo, B, m0, n0, BK, tid);
    issue_stage(sb, 2, Ahi, Alo, B, m0, n0, 2 * BK, tid);

    int p = 0;
    for (int i = 0; i < NCHUNK; i++) {
        if (i + 3 < NCHUNK) {
            int st = p + 3; if (st >= NSTAGE) st -= NSTAGE;
            issue_stage(sb, st, Ahi, Alo, B, m0, n0, (i + 3) * BK, tid);
            asm volatile("cp.async.wait_group 3;" ::: "memory");
        } else if (i + 2 < NCHUNK) {
            asm volatile("cp.async.wait_group 2;" ::: "memory");
        } else if (i + 1 < NCHUNK) {
            asm volatile("cp.async.wait_group 1;" ::: "memory");
        } else {
            asm volatile("cp.async.wait_group 0;" ::: "memory");
        }
        __syncthreads();

        const uint32_t base = sb + 2u * (uint32_t)(p * STAGE_ELEMS);
        #pragma unroll
        for (int ks = 0; ks < 2; ks++) {
            const int kb = ks * 16;
            uint32_t ah[4][4], al[4][4], bb[4][2];
            #pragma unroll
            for (int mt = 0; mt < 4; mt++) {
                uint32_t ad = base + 2u * (uint32_t)((wm * 64 + mt * 16 + arow_l) * PITCH + kb + acol_l);
                LDM4(ah[mt][0], ah[mt][1], ah[mt][2], ah[mt][3], ad);
                LDM4(al[mt][0], al[mt][1], al[mt][2], al[mt][3], ad + 2u * TILE_ELEMS);
            }
            #pragma unroll
            for (int ntp = 0; ntp < 2; ntp++) {
                uint32_t bd = base + 2u * (uint32_t)(2 * TILE_ELEMS + (wn * 32 + ntp * 16 + brow_l) * PITCH + kb + bcol_l);
                uint32_t r0, r1, r2, r3;
                LDM4(r0, r1, r2, r3, bd);
                bb[2 * ntp][0] = r0; bb[2 * ntp][1] = r1;
                bb[2 * ntp + 1][0] = r2; bb[2 * ntp + 1][1] = r3;
            }
            #pragma unroll
            for (int mt = 0; mt < 4; mt++)
                #pragma unroll
                for (int nt = 0; nt < 4; nt++) {
                    mma16816(acc[mt][nt], ah[mt], bb[nt][0], bb[nt][1]);
                    mma16816(acc[mt][nt], al[mt], bb[nt][0], bb[nt][1]);
                }
        }
        __syncthreads();
        if (++p == NSTAGE) p = 0;
    }

    #pragma unroll
    for (int mt = 0; mt < 4; mt++) {
        int row = m0 + wm * 64 + mt * 16 + g;
        #pragma unroll
        for (int nt = 0; nt < 4; nt++) {
            int col = n0 + wn * 32 + nt * 8 + 2 * t4;
            *(float2*)&C[(size_t)row * N + col] = make_float2(acc[mt][nt][0], acc[mt][nt][1]);
            *(float2*)&C[(size_t)(row + 8) * N + col] = make_float2(acc[mt][nt][2], acc[mt][nt][3]);
        }
    }
}

// ---------------- fp32 -> fp16 hi/lo split ----------------
__global__ void split_kernel(const float* __restrict__ x,
                             __half* __restrict__ hi,
                             __half* __restrict__ lo, int n)
{
    int i = blockIdx.x * blockDim.x + threadIdx.x;
    if (i >= n) return;
    float v = x[i];
    __half h = __float2half_rn(v);
    float r = v - __half2float(h);
    hi[i] = h;
    lo[i] = __float2half_rn(r);
}

// ---------------- W[K,N] -> fp16 [N,K] transpose (single precision B) ----------------
__global__ void tsplit_kernel(const float* __restrict__ W,
                              __half* __restrict__ hi, int K, int N)
{
    __shared__ float t[32][33];
    const int n0 = blockIdx.x * 32;
    const int k0 = blockIdx.y * 32;
    const int tx = threadIdx.x, ty = threadIdx.y;
    #pragma unroll
    for (int i = 0; i < 32; i += 8)
        t[ty + i][tx] = W[(size_t)(k0 + ty + i) * N + n0 + tx];
    __syncthreads();
    #pragma unroll
    for (int i = 0; i < 32; i += 8) {
        float v = t[tx][ty + i];
        hi[(size_t)(n0 + ty + i) * K + k0 + tx] = __float2half_rn(v);
    }
}

// ---------------- V cols of qkv -> V^T [b,8,64,1024] fp16 hi/lo ----------------
__global__ void vtsplit_kernel(const float* __restrict__ qkv,
                               __half* __restrict__ hi,
                               __half* __restrict__ lo)
{
    __shared__ float t[32][33];
    const int s0 = blockIdx.x * 32;
    const int d0 = blockIdx.y * 32;
    const int b = blockIdx.z >> 3;
    const int h = blockIdx.z & 7;
    const int tx = threadIdx.x, ty = threadIdx.y;
    #pragma unroll
    for (int i = 0; i < 32; i += 8)
        t[ty + i][tx] = qkv[((size_t)b * SEQ + s0 + ty + i) * NQKV + 2560 + h * HD + d0 + tx];
    __syncthreads();
    #pragma unroll
    for (int i = 0; i < 32; i += 8) {
        float x = t[tx][ty + i];
        __half hh = __float2half_rn(x);
        float r = x - __half2float(hh);
        size_t o = (((size_t)b * HKV + h) * HD + d0 + ty + i) * SEQ + s0 + tx;
        hi[o] = hh;
        lo[o] = __float2half_rn(r);
    }
}

// ---------------- RoPE + fp16 split (reads fused qkv) ----------------
__global__ void rope_split_kernel(const float* __restrict__ qkv, int colOff,
                                  __half* __restrict__ hi,
                                  __half* __restrict__ lo, int heads)
{
    int idx = blockIdx.x * blockDim.x + threadIdx.x;
    int total = BATCH * SEQ * heads * (HD / 2);
    if (idx >= total) return;
    int dpair = idx & 31;
    int t = idx >> 5;
    int h = t % heads;  t /= heads;
    int s = t % SEQ;
    int b = t / SEQ;

    float inv = powf(10000.0f, -(float)(2 * dpair) / (float)HD);
    float ang = (float)s * inv;
    float sn, cs;
    sincosf(ang, &sn, &cs);

    size_t src = ((size_t)b * SEQ + s) * NQKV + colOff + h * HD + dpair;
    float x1 = qkv[src];
    float x2 = qkv[src + HD / 2];
    float y1 = x1 * cs - x2 * sn;
    float y2 = x2 * cs + x1 * sn;

    size_t base = (((size_t)b * SEQ + s) * heads + h) * HD + dpair;
    __half h1 = __float2half_rn(y1);
    __half h2 = __float2half_rn(y2);
    hi[base] = h1;
    hi[base + HD / 2] = h2;
    if (lo) {
        lo[base] = __float2half_rn(y1 - __half2float(h1));
        lo[base + HD / 2] = __float2half_rn(y2 - __half2float(h2));
    }
}

// ---------------- flash attention (fp16 tensor cores) ----------------
#define FPITCH 72
#define QH_OFF 0
#define QL_OFF (128 * FPITCH)
#define KH_OFF (256 * FPITCH)
#define VH_OFF (320 * FPITCH)
#define VL_OFF (384 * FPITCH)
#define FLASH_SMEM (448 * FPITCH * 2)   // 64512 bytes

__global__ __launch_bounds__(256, 1) void flash_mma_kernel(
    const __half* __restrict__ qhi, const __half* __restrict__ qlo,
    const __half* __restrict__ khi,
    const __half* __restrict__ vthi, const __half* __restrict__ vtlo,
    __half* __restrict__ outHi, __half* __restrict__ outLo)
{
    extern __shared__ char smem[];
    const uint32_t sb = smem_to_u32(smem);
    __half* sm = (__half*)smem;

    const int tid = threadIdx.x;
    const int wid = tid >> 5;
    const int lid = tid & 31;
    const int g = lid >> 2;
    const int t4 = lid & 3;
    const int qt = blockIdx.x;
    const int bh = blockIdx.y;
    const int b = bh >> 5;
    const int h = bh & 31;
    const int hkv = h >> 2;

    const int arow_l = (lid & 7) + ((lid >> 3) & 1) * 8;
    const int acol_l = (lid >> 4) * 8;
    const int brow_l = (lid & 7) + (lid >> 4) * 8;
    const int bcol_l = ((lid >> 3) & 1) * 8;

    #pragma unroll
    for (int it = 0; it < 4; it++) {
        int idx = tid + it * 256;
        int row = idx >> 3;
        int ch = idx & 7;
        size_t goff = (((size_t)b * SEQ + qt * 128 + row) * HQ + h) * HD + ch * 8;
        *(uint4*)&sm[QH_OFF + row * FPITCH + ch * 8] = *(const uint4*)&qhi[goff];
        *(uint4*)&sm[QL_OFF + row * FPITCH + ch * 8] = *(const uint4*)&qlo[goff];
    }
    __syncthreads();

    uint32_t qh[4][4], ql[4][4];
    #pragma unroll
    for (int ks = 0; ks < 4; ks++) {
        uint32_t ad = sb + 2u * (uint32_t)(QH_OFF + (wid * 16 + arow_l) * FPITCH + ks * 16 + acol_l);
        LDM4(qh[ks][0], qh[ks][1], qh[ks][2], qh[ks][3], ad);
        ad = sb + 2u * (uint32_t)(QL_OFF + (wid * 16 + arow_l) * FPITCH + ks * 16 + acol_l);
        LDM4(ql[ks][0], ql[ks][1], ql[ks][2], ql[ks][3], ad);
    }

    float m0 = -1e30f, m1 = -1e30f, l0 = 0.f, l1 = 0.f;
    float oacc[8][4];
    #pragma unroll
    for (int nt = 0; nt < 8; nt++)
        #pragma unroll
        for (int r = 0; r < 4; r++) oacc[nt][r] = 0.f;

    const int row0 = qt * 128 + wid * 16;
    const int r_g = row0 + g;
    const int r_g8 = r_g + 8;
    const float scale = 0.125f;
    const int nkt = 2 * qt + 2;

    for (int kt = 0; kt < nkt; kt++) {
        // ---- load K, Vh, Vl tiles (3 x 64x64 fp16) ----
        #pragma unroll
        for (int it = 0; it < 6; it++) {
            int idx = tid + it * 256;       // 0..1535
            int tile = idx >> 9;            // 0..2
            int r = (idx >> 3) & 63;
            int ch = idx & 7;
            const __half* src;
            int dstoff;
            if (tile == 0) { src = &khi[(((size_t)b * SEQ + kt * 64 + r) * HKV + hkv) * HD + ch * 8]; dstoff = KH_OFF; }
            else if (tile == 1) { src = &vthi[(((size_t)b * HKV + hkv) * HD + r) * SEQ + kt * 64 + ch * 8]; dstoff = VH_OFF; }
            else { src = &vtlo[(((size_t)b * HKV + hkv) * HD + r) * SEQ + kt * 64 + ch * 8]; dstoff = VL_OFF; }
            *(uint4*)&sm[dstoff + r * FPITCH + ch * 8] = *(const uint4*)src;
        }
        __syncthreads();

        // ---- S = Q K^T (Q hi/lo x K single) ----
        float sacc[8][4];
        #pragma unroll
        for (int nt = 0; nt < 8; nt++)
            #pragma unroll
            for (int r = 0; r < 4; r++) sacc[nt][r] = 0.f;

        #pragma unroll
        for (int ks = 0; ks < 4; ks++) {
            #pragma unroll
            for (int ntp = 0; ntp < 4; ntp++) {
                uint32_t bd = sb + 2u * (uint32_t)(KH_OFF + (ntp * 16 + brow_l) * FPITCH + ks * 16 + bcol_l);
                uint32_t k0, k1, k2, k3;
                LDM4(k0, k1, k2, k3, bd);
                mma16816(sacc[2 * ntp], qh[ks], k0, k1);
                mma16816(sacc[2 * ntp], ql[ks], k0, k1);
                mma16816(sacc[2 * ntp + 1], qh[ks], k2, k3);
                mma16816(sacc[2 * ntp + 1], ql[ks], k2, k3);
            }
        }

        const bool maybe_mask = (kt * 64 + 63 > row0);
        float mx0 = -1e30f, mx1 = -1e30f;
        #pragma unroll
        for (int nt = 0; nt < 8; nt++) {
            #pragma unroll
            for (int r = 0; r < 4; r++) sacc[nt][r] *= scale;
            if (maybe_mask) {
                int colb = kt * 64 + nt * 8 + 2 * t4;
                if (colb > r_g)      sacc[nt][0] = NEG_BIG;
                if (colb + 1 > r_g)  sacc[nt][1] = NEG_BIG;
                if (colb > r_g8)     sacc[nt][2] = NEG_BIG;
                if (colb + 1 > r_g8) sacc[nt][3] = NEG_BIG;
            }
            mx0 = fmaxf(mx0, fmaxf(sacc[nt][0], sacc[nt][1]));
            mx1 = fmaxf(mx1, fmaxf(sacc[nt][2], sacc[nt][3]));
        }
        mx0 = fmaxf(mx0, __shfl_xor_sync(0xffffffffu, mx0, 1));
        mx0 = fmaxf(mx0, __shfl_xor_sync(0xffffffffu, mx0, 2));
        mx1 = fmaxf(mx1, __shfl_xor_sync(0xffffffffu, mx1, 1));
        mx1 = fmaxf(mx1, __shfl_xor_sync(0xffffffffu, mx1, 2));

        float mn0 = fmaxf(m0, mx0), mn1 = fmaxf(m1, mx1);
        float corr0 = __expf(m0 - mn0), corr1 = __expf(m1 - mn1);

        uint32_t ph[8][2];
        float rs0 = 0.f, rs1 = 0.f;
        #pragma unroll
        for (int nt = 0; nt < 8; nt++) {
            float p00 = __expf(sacc[nt][0] - mn0);
            float p01 = __expf(sacc[nt][1] - mn0);
            float p10 = __expf(sacc[nt][2] - mn1);
            float p11 = __expf(sacc[nt][3] - mn1);
            rs0 += p00 + p01;
            rs1 += p10 + p11;
            ph[nt][0] = pack_f16x2(p00, p01);
            ph[nt][1] = pack_f16x2(p10, p11);
        }
        rs0 += __shfl_xor_sync(0xffffffffu, rs0, 1);
        rs0 += __shfl_xor_sync(0xffffffffu, rs0, 2);
        rs1 += __shfl_xor_sync(0xffffffffu, rs1, 1);
        rs1 += __shfl_xor_sync(0xffffffffu, rs1, 2);

        l0 = l0 * corr0 + rs0;
        l1 = l1 * corr1 + rs1;
        m0 = mn0; m1 = mn1;
        #pragma unroll
        for (int nt = 0; nt < 8; nt++) {
            oacc[nt][0] *= corr0; oacc[nt][1] *= corr0;
            oacc[nt][2] *= corr1; oacc[nt][3] *= corr1;
        }

        // ---- O += P (Vh + Vl) ----
        #pragma unroll
        for (int ks = 0; ks < 4; ks++) {
            uint32_t pah[4] = { ph[2 * ks][0], ph[2 * ks][1], ph[2 * ks + 1][0], ph[2 * ks + 1][1] };
            #pragma unroll
            for (int ntp = 0; ntp < 4; ntp++) {
                uint32_t bd = sb + 2u * (uint32_t)(VH_OFF + (ntp * 16 + brow_l) * FPITCH + ks * 16 + bcol_l);
                uint32_t v0, v1, v2, v3, w0, w1, w2, w3;
                LDM4(v0, v1, v2, v3, bd);
                bd = sb + 2u * (uint32_t)(VL_OFF + (ntp * 16 + brow_l) * FPITCH + ks * 16 + bcol_l);
                LDM4(w0, w1, w2, w3, bd);
                mma16816(oacc[2 * ntp], pah, v0, v1);
                mma16816(oacc[2 * ntp], pah, w0, w1);
                mma16816(oacc[2 * ntp + 1], pah, v2, v3);
                mma16816(oacc[2 * ntp + 1], pah, w2, w3);
            }
        }
        __syncthreads();
    }

    float inv0 = 1.0f / l0, inv1 = 1.0f / l1;
    uint32_t* oHi = (uint32_t*)outHi;
    uint32_t* oLo = (uint32_t*)outLo;
    #pragma unroll
    for (int nt = 0; nt < 8; nt++) {
        float o00 = oacc[nt][0] * inv0, o01 = oacc[nt][1] * inv0;
        float o10 = oacc[nt][2] * inv1, o11 = oacc[nt][3] * inv1;
        float h00 = __half2float(__float2half_rn(o00));
        float h01 = __half2float(__float2half_rn(o01));
        float h10 = __half2float(__float2half_rn(o10));
        float h11 = __half2float(__float2half_rn(o11));
        size_t row = (size_t)b * SEQ + qt * 128 + wid * 16 + g;
        int col = h * 64 + nt * 8 + 2 * t4;
        oHi[(row * 2048 + col) >> 1] = pack_f16x2(h00, h01);
        oLo[(row * 2048 + col) >> 1] = pack_f16x2(o00 - h00, o01 - h01);
        oHi[((row + 8) * 2048 + col) >> 1] = pack_f16x2(h10, h11);
        oLo[((row + 8) * 2048 + col) >> 1] = pack_f16x2(o10 - h10, o11 - h11);
    }
}

// ---------------- launcher ----------------
extern "C" void kernel_launch(void* const* d_in, const int* in_sizes, int n_in,
                              void* d_out, int out_size)
{
    const float* hidden = (const float*)d_in[0];
    const float* Wq = (const float*)d_in[2];
    const float* Wk = (const float*)d_in[3];
    const float* Wv = (const float*)d_in[4];
    const float* Wo = (const float*)d_in[5];
    float* out = (float*)d_out;

    float* qkv_ptr;
    cudaGetSymbolAddress((void**)&qkv_ptr, g_qkv);

    __half *aHi, *aLo, *bQKV, *bO;
    __half *qH, *qL, *kH, *vtH, *vtL;
    cudaGetSymbolAddress((void**)&aHi, gA_hi);
    cudaGetSymbolAddress((void**)&aLo, gA_lo);
    cudaGetSymbolAddress((void**)&bQKV, gBqkv);
    cudaGetSymbolAddress((void**)&bO, gBo);
    cudaGetSymbolAddress((void**)&qH, gQhi);
    cudaGetSymbolAddress((void**)&qL, gQlo);
    cudaGetSymbolAddress((void**)&kH, gKhi);
    cudaGetSymbolAddress((void**)&vtH, gVThi);
    cudaGetSymbolAddress((void**)&vtL, gVTlo);

    cudaFuncSetAttribute(gemm_fp16x2_kernel, cudaFuncAttributeMaxDynamicSharedMemorySize, GEMM_SMEM);
    cudaFuncSetAttribute(flash_mma_kernel, cudaFuncAttributeMaxDynamicSharedMemorySize, FLASH_SMEM);

    // 1) splits (weights -> fp16 [N,K], activations -> fp16 hi/lo)
    {
        int n = MROWS * KDIM;
        split_kernel<<<(n + 255) / 256, 256>>>(hidden, aHi, aLo, n);
        dim3 tb(32, 8);
        tsplit_kernel<<<dim3(2048 / 32, KDIM / 32), tb>>>(Wq, bQKV,                       KDIM, 2048);
        tsplit_kernel<<<dim3(512 / 32,  KDIM / 32), tb>>>(Wk, bQKV + (size_t)2048 * KDIM, KDIM, 512);
        tsplit_kernel<<<dim3(512 / 32,  KDIM / 32), tb>>>(Wv, bQKV + (size_t)2560 * KDIM, KDIM, 512);
        tsplit_kernel<<<dim3(2048 / 32, KDIM / 32), tb>>>(Wo, bO, KDIM, 2048);
    }

    // 2) fused QKV projection
    gemm_fp16x2_kernel<<<dim3(NQKV / 128, MROWS / 128), 256, GEMM_SMEM>>>(aHi, aLo, bQKV, qkv_ptr, NQKV);

    // 3) RoPE + split; V transpose + split
    {
        int nq = BATCH * SEQ * HQ * (HD / 2);
        rope_split_kernel<<<(nq + 255) / 256, 256>>>(qkv_ptr, 0, qH, qL, HQ);
        int nk = BATCH * SEQ * HKV * (HD / 2);
        rope_split_kernel<<<(nk + 255) / 256, 256>>>(qkv_ptr, 2048, kH, (__half*)nullptr, HKV);
        dim3 tb(32, 8);
        vtsplit_kernel<<<dim3(SEQ / 32, HD / 32, BATCH * HKV), tb>>>(qkv_ptr, vtH, vtL);
    }

    // 4) attention (writes split output directly into aHi/aLo)
    {
        dim3 g(SEQ / 128, BATCH * HQ);
        flash_mma_kernel<<<g, 256, FLASH_SMEM>>>(qH, qL, kH, vtH, vtL, aHi, aLo);
    }

    // 5) output projection
    gemm_fp16x2_kernel<<<dim3(2048 / 128, MROWS / 128), 256, GEMM_SMEM>>>(aHi, aLo, bO, out, 2048);
}

// round 7
// speedup vs baseline: 4.3108x; 1.0023x over previous
#include <cuda_runtime.h>
#include <cuda_fp16.h>
#include <math.h>
#include <stdint.h>

// ---------------- problem constants ----------------
#define BATCH 2
#define SEQ 1024
#define HIDDEN 2048
#define HQ 32
#define HKV 8
#define HD 64
#define MROWS (BATCH * SEQ)     // 2048
#define KDIM HIDDEN             // 2048
#define NQKV 3072               // fused q(2048) | k(512) | v(512)
#define NEG_BIG (-1e9f)

// ---------------- scratch ----------------
__device__ float g_qkv[MROWS * NQKV];        // fused projection output (fp32)

__device__ __half gA_hi[MROWS * KDIM];
__device__ __half gA_lo[MROWS * KDIM];
__device__ __half gBqkv[NQKV * KDIM];        // [3072, 2048] = Wq^T | Wk^T | Wv^T (fp16)
__device__ __half gBo[2048 * KDIM];          // Wo^T (fp16)

// flash operands
__device__ __half gQhi[MROWS * HQ * HD];
__device__ __half gQlo[MROWS * HQ * HD];
__device__ __half gKhi[MROWS * HKV * HD];    // K single fp16
__device__ __half gVThi[BATCH * HKV * HD * SEQ];
__device__ __half gVTlo[BATCH * HKV * HD * SEQ];

// ---------------- helpers ----------------
__device__ __forceinline__ uint32_t smem_to_u32(const void* p) {
    uint32_t a;
    asm("{ .reg .u64 t; cvta.to.shared.u64 t, %1; cvt.u32.u64 %0, t; }" : "=r"(a) : "l"(p));
    return a;
}
#define LDM4(r0, r1, r2, r3, addr) \
    asm volatile("ldmatrix.sync.aligned.m8n8.x4.shared.b16 {%0,%1,%2,%3}, [%4];" \
        : "=r"(r0), "=r"(r1), "=r"(r2), "=r"(r3) : "r"(addr))

__device__ __forceinline__ void mma16816(float* d, const uint32_t* a, uint32_t b0, uint32_t b1) {
    asm volatile("mma.sync.aligned.m16n8k16.row.col.f32.f16.f16.f32 "
        "{%0,%1,%2,%3}, {%4,%5,%6,%7}, {%8,%9}, {%0,%1,%2,%3};"
        : "+f"(d[0]), "+f"(d[1]), "+f"(d[2]), "+f"(d[3])
        : "r"(a[0]), "r"(a[1]), "r"(a[2]), "r"(a[3]), "r"(b0), "r"(b1));
}
__device__ __forceinline__ uint32_t pack_f16x2(float lo, float hi) {
    uint32_t d;
    asm("cvt.rn.f16x2.f32 %0, %1, %2;" : "=r"(d) : "f"(hi), "f"(lo));
    return d;
}

// ---------------- fp16x2 GEMM: 4-stage cp.async pipeline ----------------
#define BK 32
#define PITCH 40
#define TILE_ELEMS (128 * PITCH)
#define STAGE_TILES 3                              // Ahi, Alo, B
#define STAGE_ELEMS (STAGE_TILES * TILE_ELEMS)
#define NSTAGE 4
#define GEMM_SMEM (NSTAGE * STAGE_ELEMS * 2)       // 122880 bytes
#define NCHUNK (KDIM / BK)                         // 64

__device__ __forceinline__ void issue_stage(
    uint32_t sb, int stage,
    const __half* __restrict__ Ahi, const __half* __restrict__ Alo,
    const __half* __restrict__ B,
    int m0, int n0, int k0, int tid)
{
    const __half* bases[3] = {
        Ahi + (size_t)m0 * KDIM, Alo + (size_t)m0 * KDIM, B + (size_t)n0 * KDIM };
    #pragma unroll
    for (int t = 0; t < 6; t++) {
        int idx = tid + t * 256;
        int tile = idx >> 9;
        int row  = (idx >> 2) & 127;
        int ch   = idx & 3;
        const __half* src = bases[tile] + (size_t)row * KDIM + k0 + ch * 8;
        uint32_t dst = sb + 2u * (uint32_t)(stage * STAGE_ELEMS + tile * TILE_ELEMS + row * PITCH + ch * 8);
        asm volatile("cp.async.cg.shared.global [%0], [%1], 16;" :: "r"(dst), "l"(src));
    }
    asm volatile("cp.async.commit_group;");
}

__global__ __launch_bounds__(256, 1) void gemm_fp16x2_kernel(
    const __half* __restrict__ Ahi, const __half* __restrict__ Alo,
    const __half* __restrict__ B,
    float* __restrict__ C, int N)
{
    extern __shared__ char smem[];
    const uint32_t sb = smem_to_u32(smem);
    const int tid = threadIdx.x;
    const int wid = tid >> 5;
    const int lid = tid & 31;
    const int wm = wid >> 2;
    const int wn = wid & 3;
    const int g = lid >> 2;
    const int t4 = lid & 3;
    const int n0 = blockIdx.x * 128;
    const int m0 = blockIdx.y * 128;

    const int arow_l = (lid & 7) + ((lid >> 3) & 1) * 8;
    const int acol_l = (lid >> 4) * 8;
    const int brow_l = (lid & 7) + (lid >> 4) * 8;
    const int bcol_l = ((lid >> 3) & 1) * 8;

    float acc[4][4][4];
    #pragma unroll
    for (int i = 0; i < 4; i++)
        #pragma unroll
        for (int j = 0; j < 4; j++)
            #pragma unroll
            for (int r = 0; r < 4; r++) acc[i][j][r] = 0.f;

    issue_stage(sb, 0, Ahi, Alo, B, m0, n0, 0, tid);
    issue_stage(sb, 1, Ahi, Alo, B, m0, n0, BK, tid);
    issue_stage(sb, 2, Ahi, Alo, B, m0, n0, 2 * BK, tid);

    int p = 0;
    for (int i = 0; i < NCHUNK; i++) {
        if (i + 3 < NCHUNK) {
            int st = p + 3; if (st >= NSTAGE) st -= NSTAGE;
            issue_stage(sb, st, Ahi, Alo, B, m0, n0, (i + 3) * BK, tid);
            asm volatile("cp.async.wait_group 3;" ::: "memory");
        } else if (i + 2 < NCHUNK) {
            asm volatile("cp.async.wait_group 2;" ::: "memory");
        } else if (i + 1 < NCHUNK) {
            asm volatile("cp.async.wait_group 1;" ::: "memory");
        } else {
            asm volatile("cp.async.wait_group 0;" ::: "memory");
        }
        __syncthreads();

        const uint32_t base = sb + 2u * (uint32_t)(p * STAGE_ELEMS);
        #pragma unroll
        for (int ks = 0; ks < 2; ks++) {
            const int kb = ks * 16;
            uint32_t ah[4][4], al[4][4], bb[4][2];
            #pragma unroll
            for (int mt = 0; mt < 4; mt++) {
                uint32_t ad = base + 2u * (uint32_t)((wm * 64 + mt * 16 + arow_l) * PITCH + kb + acol_l);
                LDM4(ah[mt][0], ah[mt][1], ah[mt][2], ah[mt][3], ad);
                LDM4(al[mt][0], al[mt][1], al[mt][2], al[mt][3], ad + 2u * TILE_ELEMS);
            }
            #pragma unroll
            for (int ntp = 0; ntp < 2; ntp++) {
                uint32_t bd = base + 2u * (uint32_t)(2 * TILE_ELEMS + (wn * 32 + ntp * 16 + brow_l) * PITCH + kb + bcol_l);
                uint32_t r0, r1, r2, r3;
                LDM4(r0, r1, r2, r3, bd);
                bb[2 * ntp][0] = r0; bb[2 * ntp][1] = r1;
                bb[2 * ntp + 1][0] = r2; bb[2 * ntp + 1][1] = r3;
            }
            // hi pass: 16 independent MMAs
            #pragma unroll
            for (int mt = 0; mt < 4; mt++)
                #pragma unroll
                for (int nt = 0; nt < 4; nt++)
                    mma16816(acc[mt][nt], ah[mt], bb[nt][0], bb[nt][1]);
            // lo pass: 16 independent MMAs (dep distance to hi pass = 16)
            #pragma unroll
            for (int mt = 0; mt < 4; mt++)
                #pragma unroll
                for (int nt = 0; nt < 4; nt++)
                    mma16816(acc[mt][nt], al[mt], bb[nt][0], bb[nt][1]);
        }
        __syncthreads();
        if (++p == NSTAGE) p = 0;
    }

    #pragma unroll
    for (int mt = 0; mt < 4; mt++) {
        int row = m0 + wm * 64 + mt * 16 + g;
        #pragma unroll
        for (int nt = 0; nt < 4; nt++) {
            int col = n0 + wn * 32 + nt * 8 + 2 * t4;
            *(float2*)&C[(size_t)row * N + col] = make_float2(acc[mt][nt][0], acc[mt][nt][1]);
            *(float2*)&C[(size_t)(row + 8) * N + col] = make_float2(acc[mt][nt][2], acc[mt][nt][3]);
        }
    }
}

// ---------------- fp32 -> fp16 hi/lo split ----------------
__global__ void split_kernel(const float* __restrict__ x,
                             __half* __restrict__ hi,
                             __half* __restrict__ lo, int n)
{
    int i = blockIdx.x * blockDim.x + threadIdx.x;
    if (i >= n) return;
    float v = x[i];
    __half h = __float2half_rn(v);
    float r = v - __half2float(h);
    hi[i] = h;
    lo[i] = __float2half_rn(r);
}

// ---------------- W[K,N] -> fp16 [N,K] transpose ----------------
__global__ void tsplit_kernel(const float* __restrict__ W,
                              __half* __restrict__ hi, int K, int N)
{
    __shared__ float t[32][33];
    const int n0 = blockIdx.x * 32;
    const int k0 = blockIdx.y * 32;
    const int tx = threadIdx.x, ty = threadIdx.y;
    #pragma unroll
    for (int i = 0; i < 32; i += 8)
        t[ty + i][tx] = W[(size_t)(k0 + ty + i) * N + n0 + tx];
    __syncthreads();
    #pragma unroll
    for (int i = 0; i < 32; i += 8) {
        float v = t[tx][ty + i];
        hi[(size_t)(n0 + ty + i) * K + k0 + tx] = __float2half_rn(v);
    }
}

// ---------------- V cols of qkv -> V^T [b,8,64,1024] fp16 hi/lo ----------------
__global__ void vtsplit_kernel(const float* __restrict__ qkv,
                               __half* __restrict__ hi,
                               __half* __restrict__ lo)
{
    __shared__ float t[32][33];
    const int s0 = blockIdx.x * 32;
    const int d0 = blockIdx.y * 32;
    const int b = blockIdx.z >> 3;
    const int h = blockIdx.z & 7;
    const int tx = threadIdx.x, ty = threadIdx.y;
    #pragma unroll
    for (int i = 0; i < 32; i += 8)
        t[ty + i][tx] = qkv[((size_t)b * SEQ + s0 + ty + i) * NQKV + 2560 + h * HD + d0 + tx];
    __syncthreads();
    #pragma unroll
    for (int i = 0; i < 32; i += 8) {
        float x = t[tx][ty + i];
        __half hh = __float2half_rn(x);
        float r = x - __half2float(hh);
        size_t o = (((size_t)b * HKV + h) * HD + d0 + ty + i) * SEQ + s0 + tx;
        hi[o] = hh;
        lo[o] = __float2half_rn(r);
    }
}

// ---------------- RoPE + fp16 split (reads fused qkv) ----------------
__global__ void rope_split_kernel(const float* __restrict__ qkv, int colOff,
                                  __half* __restrict__ hi,
                                  __half* __restrict__ lo, int heads)
{
    int idx = blockIdx.x * blockDim.x + threadIdx.x;
    int total = BATCH * SEQ * heads * (HD / 2);
    if (idx >= total) return;
    int dpair = idx & 31;
    int t = idx >> 5;
    int h = t % heads;  t /= heads;
    int s = t % SEQ;
    int b = t / SEQ;

    float inv = powf(10000.0f, -(float)(2 * dpair) / (float)HD);
    float ang = (float)s * inv;
    float sn, cs;
    sincosf(ang, &sn, &cs);

    size_t src = ((size_t)b * SEQ + s) * NQKV + colOff + h * HD + dpair;
    float x1 = qkv[src];
    float x2 = qkv[src + HD / 2];
    float y1 = x1 * cs - x2 * sn;
    float y2 = x2 * cs + x1 * sn;

    size_t base = (((size_t)b * SEQ + s) * heads + h) * HD + dpair;
    __half h1 = __float2half_rn(y1);
    __half h2 = __float2half_rn(y2);
    hi[base] = h1;
    hi[base + HD / 2] = h2;
    if (lo) {
        lo[base] = __float2half_rn(y1 - __half2float(h1));
        lo[base + HD / 2] = __float2half_rn(y2 - __half2float(h2));
    }
}

// ---------------- flash attention (fp16 tensor cores) ----------------
#define FPITCH 72
#define QH_OFF 0
#define QL_OFF (128 * FPITCH)
#define KH_OFF (256 * FPITCH)
#define VH_OFF (320 * FPITCH)
#define VL_OFF (384 * FPITCH)
#define FLASH_SMEM (448 * FPITCH * 2)   // 64512 bytes

__global__ __launch_bounds__(256, 1) void flash_mma_kernel(
    const __half* __restrict__ qhi, const __half* __restrict__ qlo,
    const __half* __restrict__ khi,
    const __half* __restrict__ vthi, const __half* __restrict__ vtlo,
    __half* __restrict__ outHi, __half* __restrict__ outLo)
{
    extern __shared__ char smem[];
    const uint32_t sb = smem_to_u32(smem);
    __half* sm = (__half*)smem;

    const int tid = threadIdx.x;
    const int wid = tid >> 5;
    const int lid = tid & 31;
    const int g = lid >> 2;
    const int t4 = lid & 3;
    const int qt = blockIdx.x;
    const int bh = blockIdx.y;
    const int b = bh >> 5;
    const int h = bh & 31;
    const int hkv = h >> 2;

    const int arow_l = (lid & 7) + ((lid >> 3) & 1) * 8;
    const int acol_l = (lid >> 4) * 8;
    const int brow_l = (lid & 7) + (lid >> 4) * 8;
    const int bcol_l = ((lid >> 3) & 1) * 8;

    #pragma unroll
    for (int it = 0; it < 4; it++) {
        int idx = tid + it * 256;
        int row = idx >> 3;
        int ch = idx & 7;
        size_t goff = (((size_t)b * SEQ + qt * 128 + row) * HQ + h) * HD + ch * 8;
        *(uint4*)&sm[QH_OFF + row * FPITCH + ch * 8] = *(const uint4*)&qhi[goff];
        *(uint4*)&sm[QL_OFF + row * FPITCH + ch * 8] = *(const uint4*)&qlo[goff];
    }
    __syncthreads();

    uint32_t qh[4][4], ql[4][4];
    #pragma unroll
    for (int ks = 0; ks < 4; ks++) {
        uint32_t ad = sb + 2u * (uint32_t)(QH_OFF + (wid * 16 + arow_l) * FPITCH + ks * 16 + acol_l);
        LDM4(qh[ks][0], qh[ks][1], qh[ks][2], qh[ks][3], ad);
        ad = sb + 2u * (uint32_t)(QL_OFF + (wid * 16 + arow_l) * FPITCH + ks * 16 + acol_l);
        LDM4(ql[ks][0], ql[ks][1], ql[ks][2], ql[ks][3], ad);
    }

    float m0 = -1e30f, m1 = -1e30f, l0 = 0.f, l1 = 0.f;
    float oacc[8][4];
    #pragma unroll
    for (int nt = 0; nt < 8; nt++)
        #pragma unroll
        for (int r = 0; r < 4; r++) oacc[nt][r] = 0.f;

    const int row0 = qt * 128 + wid * 16;
    const int r_g = row0 + g;
    const int r_g8 = r_g + 8;
    const float scale = 0.125f;
    const int nkt = 2 * qt + 2;

    for (int kt = 0; kt < nkt; kt++) {
        #pragma unroll
        for (int it = 0; it < 6; it++) {
            int idx = tid + it * 256;
            int tile = idx >> 9;
            int r = (idx >> 3) & 63;
            int ch = idx & 7;
            const __half* src;
            int dstoff;
            if (tile == 0) { src = &khi[(((size_t)b * SEQ + kt * 64 + r) * HKV + hkv) * HD + ch * 8]; dstoff = KH_OFF; }
            else if (tile == 1) { src = &vthi[(((size_t)b * HKV + hkv) * HD + r) * SEQ + kt * 64 + ch * 8]; dstoff = VH_OFF; }
            else { src = &vtlo[(((size_t)b * HKV + hkv) * HD + r) * SEQ + kt * 64 + ch * 8]; dstoff = VL_OFF; }
            *(uint4*)&sm[dstoff + r * FPITCH + ch * 8] = *(const uint4*)src;
        }
        __syncthreads();

        // ---- S = Q K^T ----
        float sacc[8][4];
        #pragma unroll
        for (int nt = 0; nt < 8; nt++)
            #pragma unroll
            for (int r = 0; r < 4; r++) sacc[nt][r] = 0.f;

        #pragma unroll
        for (int ks = 0; ks < 4; ks++) {
            uint32_t kf[4][4];
            #pragma unroll
            for (int ntp = 0; ntp < 4; ntp++) {
                uint32_t bd = sb + 2u * (uint32_t)(KH_OFF + (ntp * 16 + brow_l) * FPITCH + ks * 16 + bcol_l);
                LDM4(kf[ntp][0], kf[ntp][1], kf[ntp][2], kf[ntp][3], bd);
            }
            // hi pass (8 independent MMAs), then lo pass
            #pragma unroll
            for (int ntp = 0; ntp < 4; ntp++) {
                mma16816(sacc[2 * ntp],     qh[ks], kf[ntp][0], kf[ntp][1]);
                mma16816(sacc[2 * ntp + 1], qh[ks], kf[ntp][2], kf[ntp][3]);
            }
            #pragma unroll
            for (int ntp = 0; ntp < 4; ntp++) {
                mma16816(sacc[2 * ntp],     ql[ks], kf[ntp][0], kf[ntp][1]);
                mma16816(sacc[2 * ntp + 1], ql[ks], kf[ntp][2], kf[ntp][3]);
            }
        }

        const bool maybe_mask = (kt * 64 + 63 > row0);
        float mx0 = -1e30f, mx1 = -1e30f;
        #pragma unroll
        for (int nt = 0; nt < 8; nt++) {
            #pragma unroll
            for (int r = 0; r < 4; r++) sacc[nt][r] *= scale;
            if (maybe_mask) {
                int colb = kt * 64 + nt * 8 + 2 * t4;
                if (colb > r_g)      sacc[nt][0] = NEG_BIG;
                if (colb + 1 > r_g)  sacc[nt][1] = NEG_BIG;
                if (colb > r_g8)     sacc[nt][2] = NEG_BIG;
                if (colb + 1 > r_g8) sacc[nt][3] = NEG_BIG;
            }
            mx0 = fmaxf(mx0, fmaxf(sacc[nt][0], sacc[nt][1]));
            mx1 = fmaxf(mx1, fmaxf(sacc[nt][2], sacc[nt][3]));
        }
        mx0 = fmaxf(mx0, __shfl_xor_sync(0xffffffffu, mx0, 1));
        mx0 = fmaxf(mx0, __shfl_xor_sync(0xffffffffu, mx0, 2));
        mx1 = fmaxf(mx1, __shfl_xor_sync(0xffffffffu, mx1, 1));
        mx1 = fmaxf(mx1, __shfl_xor_sync(0xffffffffu, mx1, 2));

        float mn0 = fmaxf(m0, mx0), mn1 = fmaxf(m1, mx1);
        float corr0 = __expf(m0 - mn0), corr1 = __expf(m1 - mn1);

        uint32_t ph[8][2];
        float rs0 = 0.f, rs1 = 0.f;
        #pragma unroll
        for (int nt = 0; nt < 8; nt++) {
            float p00 = __expf(sacc[nt][0] - mn0);
            float p01 = __expf(sacc[nt][1] - mn0);
            float p10 = __expf(sacc[nt][2] - mn1);
            float p11 = __expf(sacc[nt][3] - mn1);
            rs0 += p00 + p01;
            rs1 += p10 + p11;
            ph[nt][0] = pack_f16x2(p00, p01);
            ph[nt][1] = pack_f16x2(p10, p11);
        }
        rs0 += __shfl_xor_sync(0xffffffffu, rs0, 1);
        rs0 += __shfl_xor_sync(0xffffffffu, rs0, 2);
        rs1 += __shfl_xor_sync(0xffffffffu, rs1, 1);
        rs1 += __shfl_xor_sync(0xffffffffu, rs1, 2);

        l0 = l0 * corr0 + rs0;
        l1 = l1 * corr1 + rs1;
        m0 = mn0; m1 = mn1;
        #pragma unroll
        for (int nt = 0; nt < 8; nt++) {
            oacc[nt][0] *= corr0; oacc[nt][1] *= corr0;
            oacc[nt][2] *= corr1; oacc[nt][3] *= corr1;
        }

        // ---- O += P (Vh + Vl): hi pass then lo pass ----
        #pragma unroll
        for (int ks = 0; ks < 4; ks++) {
            uint32_t pah[4] = { ph[2 * ks][0], ph[2 * ks][1], ph[2 * ks + 1][0], ph[2 * ks + 1][1] };
            uint32_t vfh[4][4], vfl[4][4];
            #pragma unroll
            for (int ntp = 0; ntp < 4; ntp++) {
                uint32_t bd = sb + 2u * (uint32_t)(VH_OFF + (ntp * 16 + brow_l) * FPITCH + ks * 16 + bcol_l);
                LDM4(vfh[ntp][0], vfh[ntp][1], vfh[ntp][2], vfh[ntp][3], bd);
                bd = sb + 2u * (uint32_t)(VL_OFF + (ntp * 16 + brow_l) * FPITCH + ks * 16 + bcol_l);
                LDM4(vfl[ntp][0], vfl[ntp][1], vfl[ntp][2], vfl[ntp][3], bd);
            }
            #pragma unroll
            for (int ntp = 0; ntp < 4; ntp++) {
                mma16816(oacc[2 * ntp],     pah, vfh[ntp][0], vfh[ntp][1]);
                mma16816(oacc[2 * ntp + 1], pah, vfh[ntp][2], vfh[ntp][3]);
            }
            #pragma unroll
            for (int ntp = 0; ntp < 4; ntp++) {
                mma16816(oacc[2 * ntp],     pah, vfl[ntp][0], vfl[ntp][1]);
                mma16816(oacc[2 * ntp + 1], pah, vfl[ntp][2], vfl[ntp][3]);
            }
        }
        __syncthreads();
    }

    float inv0 = 1.0f / l0, inv1 = 1.0f / l1;
    uint32_t* oHi = (uint32_t*)outHi;
    uint32_t* oLo = (uint32_t*)outLo;
    #pragma unroll
    for (int nt = 0; nt < 8; nt++) {
        float o00 = oacc[nt][0] * inv0, o01 = oacc[nt][1] * inv0;
        float o10 = oacc[nt][2] * inv1, o11 = oacc[nt][3] * inv1;
        float h00 = __half2float(__float2half_rn(o00));
        float h01 = __half2float(__float2half_rn(o01));
        float h10 = __half2float(__float2half_rn(o10));
        float h11 = __half2float(__float2half_rn(o11));
        size_t row = (size_t)b * SEQ + qt * 128 + wid * 16 + g;
        int col = h * 64 + nt * 8 + 2 * t4;
        oHi[(row * 2048 + col) >> 1] = pack_f16x2(h00, h01);
        oLo[(row * 2048 + col) >> 1] = pack_f16x2(o00 - h00, o01 - h01);
        oHi[((row + 8) * 2048 + col) >> 1] = pack_f16x2(h10, h11);
        oLo[((row + 8) * 2048 + col) >> 1] = pack_f16x2(o10 - h10, o11 - h11);
    }
}

// ---------------- launcher ----------------
extern "C" void kernel_launch(void* const* d_in, const int* in_sizes, int n_in,
                              void* d_out, int out_size)
{
    const float* hidden = (const float*)d_in[0];
    const float* Wq = (const float*)d_in[2];
    const float* Wk = (const float*)d_in[3];
    const float* Wv = (const float*)d_in[4];
    const float* Wo = (const float*)d_in[5];
    float* out = (float*)d_out;

    float* qkv_ptr;
    cudaGetSymbolAddress((void**)&qkv_ptr, g_qkv);

    __half *aHi, *aLo, *bQKV, *bO;
    __half *qH, *qL, *kH, *vtH, *vtL;
    cudaGetSymbolAddress((void**)&aHi, gA_hi);
    cudaGetSymbolAddress((void**)&aLo, gA_lo);
    cudaGetSymbolAddress((void**)&bQKV, gBqkv);
    cudaGetSymbolAddress((void**)&bO, gBo);
    cudaGetSymbolAddress((void**)&qH, gQhi);
    cudaGetSymbolAddress((void**)&qL, gQlo);
    cudaGetSymbolAddress((void**)&kH, gKhi);
    cudaGetSymbolAddress((void**)&vtH, gVThi);
    cudaGetSymbolAddress((void**)&vtL, gVTlo);

    cudaFuncSetAttribute(gemm_fp16x2_kernel, cudaFuncAttributeMaxDynamicSharedMemorySize, GEMM_SMEM);
    cudaFuncSetAttribute(flash_mma_kernel, cudaFuncAttributeMaxDynamicSharedMemorySize, FLASH_SMEM);

    // 1) splits
    {
        int n = MROWS * KDIM;
        split_kernel<<<(n + 255) / 256, 256>>>(hidden, aHi, aLo, n);
        dim3 tb(32, 8);
        tsplit_kernel<<<dim3(2048 / 32, KDIM / 32), tb>>>(Wq, bQKV,                       KDIM, 2048);
        tsplit_kernel<<<dim3(512 / 32,  KDIM / 32), tb>>>(Wk, bQKV + (size_t)2048 * KDIM, KDIM, 512);
        tsplit_kernel<<<dim3(512 / 32,  KDIM / 32), tb>>>(Wv, bQKV + (size_t)2560 * KDIM, KDIM, 512);
        tsplit_kernel<<<dim3(2048 / 32, KDIM / 32), tb>>>(Wo, bO, KDIM, 2048);
    }

    // 2) fused QKV projection
    gemm_fp16x2_kernel<<<dim3(NQKV / 128, MROWS / 128), 256, GEMM_SMEM>>>(aHi, aLo, bQKV, qkv_ptr, NQKV);

    // 3) RoPE + split; V transpose + split
    {
        int nq = BATCH * SEQ * HQ * (HD / 2);
        rope_split_kernel<<<(nq + 255) / 256, 256>>>(qkv_ptr, 0, qH, qL, HQ);
        int nk = BATCH * SEQ * HKV * (HD / 2);
        rope_split_kernel<<<(nk + 255) / 256, 256>>>(qkv_ptr, 2048, kH, (__half*)nullptr, HKV);
        dim3 tb(32, 8);
        vtsplit_kernel<<<dim3(SEQ / 32, HD / 32, BATCH * HKV), tb>>>(qkv_ptr, vtH, vtL);
    }

    // 4) attention
    {
        dim3 g(SEQ / 128, BATCH * HQ);
        flash_mma_kernel<<<g, 256, FLASH_SMEM>>>(qH, qL, kH, vtH, vtL, aHi, aLo);
    }

    // 5) output projection
    gemm_fp16x2_kernel<<<dim3(2048 / 128, MROWS / 128), 256, GEMM_SMEM>>>(aHi, aLo, bO, out, 2048);
}

// round 8
// speedup vs baseline: 4.8809x; 1.1323x over previous
#include <cuda_runtime.h>
#include <cuda_fp16.h>
#include <math.h>
#include <stdint.h>

// ---------------- problem constants ----------------
#define BATCH 2
#define SEQ 1024
#define HIDDEN 2048
#define HQ 32
#define HKV 8
#define HD 64
#define MROWS (BATCH * SEQ)     // 2048
#define KDIM HIDDEN             // 2048
#define NQKV 3072               // fused q(2048) | k(512) | v(512)
#define NEG_BIG (-1e9f)

// ---------------- scratch ----------------
__device__ float g_qkv[MROWS * NQKV];

__device__ __half gA_hi[MROWS * KDIM];
__device__ __half gA_lo[MROWS * KDIM];
__device__ __half gBqkv[NQKV * KDIM];
__device__ __half gBo[2048 * KDIM];

__device__ __half gQhi[MROWS * HQ * HD];
__device__ __half gQlo[MROWS * HQ * HD];
__device__ __half gKhi[MROWS * HKV * HD];
__device__ __half gVThi[BATCH * HKV * HD * SEQ];
__device__ __half gVTlo[BATCH * HKV * HD * SEQ];

// ---------------- helpers ----------------
__device__ __forceinline__ uint32_t smem_to_u32(const void* p) {
    uint32_t a;
    asm("{ .reg .u64 t; cvta.to.shared.u64 t, %1; cvt.u32.u64 %0, t; }" : "=r"(a) : "l"(p));
    return a;
}
#define LDM4(r0, r1, r2, r3, addr) \
    asm volatile("ldmatrix.sync.aligned.m8n8.x4.shared.b16 {%0,%1,%2,%3}, [%4];" \
        : "=r"(r0), "=r"(r1), "=r"(r2), "=r"(r3) : "r"(addr))

__device__ __forceinline__ void mma16816(float* d, const uint32_t* a, uint32_t b0, uint32_t b1) {
    asm volatile("mma.sync.aligned.m16n8k16.row.col.f32.f16.f16.f32 "
        "{%0,%1,%2,%3}, {%4,%5,%6,%7}, {%8,%9}, {%0,%1,%2,%3};"
        : "+f"(d[0]), "+f"(d[1]), "+f"(d[2]), "+f"(d[3])
        : "r"(a[0]), "r"(a[1]), "r"(a[2]), "r"(a[3]), "r"(b0), "r"(b1));
}
__device__ __forceinline__ uint32_t pack_f16x2(float lo, float hi) {
    uint32_t d;
    asm("cvt.rn.f16x2.f32 %0, %1, %2;" : "=r"(d) : "f"(hi), "f"(lo));
    return d;
}

// ---------------- fp16x2 GEMM: 64x128 tile, 128 threads, occ 3 ----------------
// C[M,N] = A[M,K] @ B^T; A = hi+lo fp16, B = single fp16 [N,K].
#define BK 32
#define PITCH 40                                    // fp16 elems per smem row (80B)
#define A_ELEMS (64 * PITCH)                        // 2560
#define B_ELEMS (128 * PITCH)                       // 5120
#define STAGE_ELEMS (2 * A_ELEMS + B_ELEMS)         // 10240 elems = 20480 B
#define NSTAGE 3
#define GEMM_SMEM (NSTAGE * STAGE_ELEMS * 2)        // 61440 bytes
#define NCHUNK (KDIM / BK)                          // 64

__device__ __forceinline__ void issue_stage(
    uint32_t sb, int stage,
    const __half* __restrict__ Ahi, const __half* __restrict__ Alo,
    const __half* __restrict__ B,
    int m0, int n0, int k0, int tid)
{
    #pragma unroll
    for (int t = 0; t < 8; t++) {
        int idx = tid + t * 128;            // 0..1023
        int ch = idx & 3;                   // 16B chunk within 64B of row data
        const __half* src;
        uint32_t dstoff;
        if (idx < 512) {
            int tl = idx >> 8;              // 0=Ahi, 1=Alo
            int row = (idx >> 2) & 63;
            src = (tl ? Alo : Ahi) + (size_t)(m0 + row) * KDIM + k0 + ch * 8;
            dstoff = (uint32_t)(tl * A_ELEMS + row * PITCH + ch * 8);
        } else {
            int row = (idx >> 2) & 127;
            src = B + (size_t)(n0 + row) * KDIM + k0 + ch * 8;
            dstoff = (uint32_t)(2 * A_ELEMS + row * PITCH + ch * 8);
        }
        uint32_t dst = sb + 2u * ((uint32_t)stage * STAGE_ELEMS + dstoff);
        asm volatile("cp.async.cg.shared.global [%0], [%1], 16;" :: "r"(dst), "l"(src));
    }
    asm volatile("cp.async.commit_group;");
}

__global__ __launch_bounds__(128, 3) void gemm_fp16x2_kernel(
    const __half* __restrict__ Ahi, const __half* __restrict__ Alo,
    const __half* __restrict__ B,
    float* __restrict__ C, int N)
{
    extern __shared__ char smem[];
    const uint32_t sb = smem_to_u32(smem);
    const int tid = threadIdx.x;
    const int wid = tid >> 5;               // 0..3 -> n slice
    const int lid = tid & 31;
    const int g = lid >> 2;
    const int t4 = lid & 3;
    const int n0 = blockIdx.x * 128;
    const int m0 = blockIdx.y * 64;

    const int arow_l = (lid & 7) + ((lid >> 3) & 1) * 8;
    const int acol_l = (lid >> 4) * 8;
    const int brow_l = (lid & 7) + (lid >> 4) * 8;
    const int bcol_l = ((lid >> 3) & 1) * 8;

    float acc[4][4][4];
    #pragma unroll
    for (int i = 0; i < 4; i++)
        #pragma unroll
        for (int j = 0; j < 4; j++)
            #pragma unroll
            for (int r = 0; r < 4; r++) acc[i][j][r] = 0.f;

    issue_stage(sb, 0, Ahi, Alo, B, m0, n0, 0, tid);
    issue_stage(sb, 1, Ahi, Alo, B, m0, n0, BK, tid);

    int p = 0;
    for (int i = 0; i < NCHUNK; i++) {
        if (i + 2 < NCHUNK) {
            int st = p + 2; if (st >= NSTAGE) st -= NSTAGE;
            issue_stage(sb, st, Ahi, Alo, B, m0, n0, (i + 2) * BK, tid);
            asm volatile("cp.async.wait_group 2;" ::: "memory");
        } else if (i + 1 < NCHUNK) {
            asm volatile("cp.async.wait_group 1;" ::: "memory");
        } else {
            asm volatile("cp.async.wait_group 0;" ::: "memory");
        }
        __syncthreads();

        const uint32_t base = sb + 2u * (uint32_t)(p * STAGE_ELEMS);
        #pragma unroll
        for (int ks = 0; ks < 2; ks++) {
            const int kb = ks * 16;
            uint32_t ah[4][4], al[4][4], bb[4][2];
            #pragma unroll
            for (int mt = 0; mt < 4; mt++) {
                uint32_t ad = base + 2u * (uint32_t)((mt * 16 + arow_l) * PITCH + kb + acol_l);
                LDM4(ah[mt][0], ah[mt][1], ah[mt][2], ah[mt][3], ad);
                LDM4(al[mt][0], al[mt][1], al[mt][2], al[mt][3], ad + 2u * A_ELEMS);
            }
            #pragma unroll
            for (int ntp = 0; ntp < 2; ntp++) {
                uint32_t bd = base + 2u * (uint32_t)(2 * A_ELEMS + (wid * 32 + ntp * 16 + brow_l) * PITCH + kb + bcol_l);
                uint32_t r0, r1, r2, r3;
                LDM4(r0, r1, r2, r3, bd);
                bb[2 * ntp][0] = r0; bb[2 * ntp][1] = r1;
                bb[2 * ntp + 1][0] = r2; bb[2 * ntp + 1][1] = r3;
            }
            #pragma unroll
            for (int mt = 0; mt < 4; mt++)
                #pragma unroll
                for (int nt = 0; nt < 4; nt++)
                    mma16816(acc[mt][nt], ah[mt], bb[nt][0], bb[nt][1]);
            #pragma unroll
            for (int mt = 0; mt < 4; mt++)
                #pragma unroll
                for (int nt = 0; nt < 4; nt++)
                    mma16816(acc[mt][nt], al[mt], bb[nt][0], bb[nt][1]);
        }
        __syncthreads();
        if (++p == NSTAGE) p = 0;
    }

    #pragma unroll
    for (int mt = 0; mt < 4; mt++) {
        int row = m0 + mt * 16 + g;
        #pragma unroll
        for (int nt = 0; nt < 4; nt++) {
            int col = n0 + wid * 32 + nt * 8 + 2 * t4;
            *(float2*)&C[(size_t)row * N + col] = make_float2(acc[mt][nt][0], acc[mt][nt][1]);
            *(float2*)&C[(size_t)(row + 8) * N + col] = make_float2(acc[mt][nt][2], acc[mt][nt][3]);
        }
    }
}

// ---------------- fp32 -> fp16 hi/lo split ----------------
__global__ void split_kernel(const float* __restrict__ x,
                             __half* __restrict__ hi,
                             __half* __restrict__ lo, int n)
{
    int i = blockIdx.x * blockDim.x + threadIdx.x;
    if (i >= n) return;
    float v = x[i];
    __half h = __float2half_rn(v);
    float r = v - __half2float(h);
    hi[i] = h;
    lo[i] = __float2half_rn(r);
}

// ---------------- all 4 weight transposes in ONE launch ----------------
// n-tiles: [0,64) Wq -> bQKV, [64,80) Wk -> bQKV+2048K, [80,96) Wv -> bQKV+2560K, [96,160) Wo -> bO
__global__ void tsplit_all_kernel(const float* __restrict__ Wq, const float* __restrict__ Wk,
                                  const float* __restrict__ Wv, const float* __restrict__ Wo,
                                  __half* __restrict__ bQKV, __half* __restrict__ bO)
{
    __shared__ float t[32][33];
    const int ntile = blockIdx.x;
    const int k0 = blockIdx.y * 32;
    const float* W;  __half* dst;  int N;  int n0;
    if (ntile < 64)      { W = Wq; dst = bQKV;                          N = 2048; n0 = ntile * 32; }
    else if (ntile < 80) { W = Wk; dst = bQKV + (size_t)2048 * KDIM;    N = 512;  n0 = (ntile - 64) * 32; }
    else if (ntile < 96) { W = Wv; dst = bQKV + (size_t)2560 * KDIM;    N = 512;  n0 = (ntile - 80) * 32; }
    else                 { W = Wo; dst = bO;                            N = 2048; n0 = (ntile - 96) * 32; }

    const int tx = threadIdx.x, ty = threadIdx.y;
    #pragma unroll
    for (int i = 0; i < 32; i += 8)
        t[ty + i][tx] = W[(size_t)(k0 + ty + i) * N + n0 + tx];
    __syncthreads();
    #pragma unroll
    for (int i = 0; i < 32; i += 8) {
        float v = t[tx][ty + i];
        dst[(size_t)(n0 + ty + i) * KDIM + k0 + tx] = __float2half_rn(v);
    }
}

// ---------------- V cols of qkv -> V^T [b,8,64,1024] fp16 hi/lo ----------------
__global__ void vtsplit_kernel(const float* __restrict__ qkv,
                               __half* __restrict__ hi,
                               __half* __restrict__ lo)
{
    __shared__ float t[32][33];
    const int s0 = blockIdx.x * 32;
    const int d0 = blockIdx.y * 32;
    const int b = blockIdx.z >> 3;
    const int h = blockIdx.z & 7;
    const int tx = threadIdx.x, ty = threadIdx.y;
    #pragma unroll
    for (int i = 0; i < 32; i += 8)
        t[ty + i][tx] = qkv[((size_t)b * SEQ + s0 + ty + i) * NQKV + 2560 + h * HD + d0 + tx];
    __syncthreads();
    #pragma unroll
    for (int i = 0; i < 32; i += 8) {
        float x = t[tx][ty + i];
        __half hh = __float2half_rn(x);
        float r = x - __half2float(hh);
        size_t o = (((size_t)b * HKV + h) * HD + d0 + ty + i) * SEQ + s0 + tx;
        hi[o] = hh;
        lo[o] = __float2half_rn(r);
    }
}

// ---------------- RoPE + fp16 split (reads fused qkv) ----------------
__global__ void rope_split_kernel(const float* __restrict__ qkv, int colOff,
                                  __half* __restrict__ hi,
                                  __half* __restrict__ lo, int heads)
{
    int idx = blockIdx.x * blockDim.x + threadIdx.x;
    int total = BATCH * SEQ * heads * (HD / 2);
    if (idx >= total) return;
    int dpair = idx & 31;
    int t = idx >> 5;
    int h = t % heads;  t /= heads;
    int s = t % SEQ;
    int b = t / SEQ;

    float inv = powf(10000.0f, -(float)(2 * dpair) / (float)HD);
    float ang = (float)s * inv;
    float sn, cs;
    sincosf(ang, &sn, &cs);

    size_t src = ((size_t)b * SEQ + s) * NQKV + colOff + h * HD + dpair;
    float x1 = qkv[src];
    float x2 = qkv[src + HD / 2];
    float y1 = x1 * cs - x2 * sn;
    float y2 = x2 * cs + x1 * sn;

    size_t base = (((size_t)b * SEQ + s) * heads + h) * HD + dpair;
    __half h1 = __float2half_rn(y1);
    __half h2 = __float2half_rn(y2);
    hi[base] = h1;
    hi[base + HD / 2] = h2;
    if (lo) {
        lo[base] = __float2half_rn(y1 - __half2float(h1));
        lo[base + HD / 2] = __float2half_rn(y2 - __half2float(h2));
    }
}

// ---------------- flash attention (fp16 tensor cores) ----------------
#define FPITCH 72
#define QH_OFF 0
#define QL_OFF (128 * FPITCH)
#define KH_OFF (256 * FPITCH)
#define VH_OFF (320 * FPITCH)
#define VL_OFF (384 * FPITCH)
#define FLASH_SMEM (448 * FPITCH * 2)   // 64512 bytes

__global__ __launch_bounds__(256, 1) void flash_mma_kernel(
    const __half* __restrict__ qhi, const __half* __restrict__ qlo,
    const __half* __restrict__ khi,
    const __half* __restrict__ vthi, const __half* __restrict__ vtlo,
    __half* __restrict__ outHi, __half* __restrict__ outLo)
{
    extern __shared__ char smem[];
    const uint32_t sb = smem_to_u32(smem);
    __half* sm = (__half*)smem;

    const int tid = threadIdx.x;
    const int wid = tid >> 5;
    const int lid = tid & 31;
    const int g = lid >> 2;
    const int t4 = lid & 3;
    const int qt = blockIdx.x;
    const int bh = blockIdx.y;
    const int b = bh >> 5;
    const int h = bh & 31;
    const int hkv = h >> 2;

    const int arow_l = (lid & 7) + ((lid >> 3) & 1) * 8;
    const int acol_l = (lid >> 4) * 8;
    const int brow_l = (lid & 7) + (lid >> 4) * 8;
    const int bcol_l = ((lid >> 3) & 1) * 8;

    #pragma unroll
    for (int it = 0; it < 4; it++) {
        int idx = tid + it * 256;
        int row = idx >> 3;
        int ch = idx & 7;
        size_t goff = (((size_t)b * SEQ + qt * 128 + row) * HQ + h) * HD + ch * 8;
        *(uint4*)&sm[QH_OFF + row * FPITCH + ch * 8] = *(const uint4*)&qhi[goff];
        *(uint4*)&sm[QL_OFF + row * FPITCH + ch * 8] = *(const uint4*)&qlo[goff];
    }
    __syncthreads();

    uint32_t qh[4][4], ql[4][4];
    #pragma unroll
    for (int ks = 0; ks < 4; ks++) {
        uint32_t ad = sb + 2u * (uint32_t)(QH_OFF + (wid * 16 + arow_l) * FPITCH + ks * 16 + acol_l);
        LDM4(qh[ks][0], qh[ks][1], qh[ks][2], qh[ks][3], ad);
        ad = sb + 2u * (uint32_t)(QL_OFF + (wid * 16 + arow_l) * FPITCH + ks * 16 + acol_l);
        LDM4(ql[ks][0], ql[ks][1], ql[ks][2], ql[ks][3], ad);
    }

    float m0 = -1e30f, m1 = -1e30f, l0 = 0.f, l1 = 0.f;
    float oacc[8][4];
    #pragma unroll
    for (int nt = 0; nt < 8; nt++)
        #pragma unroll
        for (int r = 0; r < 4; r++) oacc[nt][r] = 0.f;

    const int row0 = qt * 128 + wid * 16;
    const int r_g = row0 + g;
    const int r_g8 = r_g + 8;
    const float scale = 0.125f;
    const int nkt = 2 * qt + 2;

    for (int kt = 0; kt < nkt; kt++) {
        #pragma unroll
        for (int it = 0; it < 6; it++) {
            int idx = tid + it * 256;
            int tile = idx >> 9;
            int r = (idx >> 3) & 63;
            int ch = idx & 7;
            const __half* src;
            int dstoff;
            if (tile == 0) { src = &khi[(((size_t)b * SEQ + kt * 64 + r) * HKV + hkv) * HD + ch * 8]; dstoff = KH_OFF; }
            else if (tile == 1) { src = &vthi[(((size_t)b * HKV + hkv) * HD + r) * SEQ + kt * 64 + ch * 8]; dstoff = VH_OFF; }
            else { src = &vtlo[(((size_t)b * HKV + hkv) * HD + r) * SEQ + kt * 64 + ch * 8]; dstoff = VL_OFF; }
            *(uint4*)&sm[dstoff + r * FPITCH + ch * 8] = *(const uint4*)src;
        }
        __syncthreads();

        float sacc[8][4];
        #pragma unroll
        for (int nt = 0; nt < 8; nt++)
            #pragma unroll
            for (int r = 0; r < 4; r++) sacc[nt][r] = 0.f;

        #pragma unroll
        for (int ks = 0; ks < 4; ks++) {
            uint32_t kf[4][4];
            #pragma unroll
            for (int ntp = 0; ntp < 4; ntp++) {
                uint32_t bd = sb + 2u * (uint32_t)(KH_OFF + (ntp * 16 + brow_l) * FPITCH + ks * 16 + bcol_l);
                LDM4(kf[ntp][0], kf[ntp][1], kf[ntp][2], kf[ntp][3], bd);
            }
            #pragma unroll
            for (int ntp = 0; ntp < 4; ntp++) {
                mma16816(sacc[2 * ntp],     qh[ks], kf[ntp][0], kf[ntp][1]);
                mma16816(sacc[2 * ntp + 1], qh[ks], kf[ntp][2], kf[ntp][3]);
            }
            #pragma unroll
            for (int ntp = 0; ntp < 4; ntp++) {
                mma16816(sacc[2 * ntp],     ql[ks], kf[ntp][0], kf[ntp][1]);
                mma16816(sacc[2 * ntp + 1], ql[ks], kf[ntp][2], kf[ntp][3]);
            }
        }

        const bool maybe_mask = (kt * 64 + 63 > row0);
        float mx0 = -1e30f, mx1 = -1e30f;
        #pragma unroll
        for (int nt = 0; nt < 8; nt++) {
            #pragma unroll
            for (int r = 0; r < 4; r++) sacc[nt][r] *= scale;
            if (maybe_mask) {
                int colb = kt * 64 + nt * 8 + 2 * t4;
                if (colb > r_g)      sacc[nt][0] = NEG_BIG;
                if (colb + 1 > r_g)  sacc[nt][1] = NEG_BIG;
                if (colb > r_g8)     sacc[nt][2] = NEG_BIG;
                if (colb + 1 > r_g8) sacc[nt][3] = NEG_BIG;
            }
            mx0 = fmaxf(mx0, fmaxf(sacc[nt][0], sacc[nt][1]));
            mx1 = fmaxf(mx1, fmaxf(sacc[nt][2], sacc[nt][3]));
        }
        mx0 = fmaxf(mx0, __shfl_xor_sync(0xffffffffu, mx0, 1));
        mx0 = fmaxf(mx0, __shfl_xor_sync(0xffffffffu, mx0, 2));
        mx1 = fmaxf(mx1, __shfl_xor_sync(0xffffffffu, mx1, 1));
        mx1 = fmaxf(mx1, __shfl_xor_sync(0xffffffffu, mx1, 2));

        float mn0 = fmaxf(m0, mx0), mn1 = fmaxf(m1, mx1);
        float corr0 = __expf(m0 - mn0), corr1 = __expf(m1 - mn1);

        uint32_t ph[8][2];
        float rs0 = 0.f, rs1 = 0.f;
        #pragma unroll
        for (int nt = 0; nt < 8; nt++) {
            float p00 = __expf(sacc[nt][0] - mn0);
            float p01 = __expf(sacc[nt][1] - mn0);
            float p10 = __expf(sacc[nt][2] - mn1);
            float p11 = __expf(sacc[nt][3] - mn1);
            rs0 += p00 + p01;
            rs1 += p10 + p11;
            ph[nt][0] = pack_f16x2(p00, p01);
            ph[nt][1] = pack_f16x2(p10, p11);
        }
        rs0 += __shfl_xor_sync(0xffffffffu, rs0, 1);
        rs0 += __shfl_xor_sync(0xffffffffu, rs0, 2);
        rs1 += __shfl_xor_sync(0xffffffffu, rs1, 1);
        rs1 += __shfl_xor_sync(0xffffffffu, rs1, 2);

        l0 = l0 * corr0 + rs0;
        l1 = l1 * corr1 + rs1;
        m0 = mn0; m1 = mn1;
        #pragma unroll
        for (int nt = 0; nt < 8; nt++) {
            oacc[nt][0] *= corr0; oacc[nt][1] *= corr0;
            oacc[nt][2] *= corr1; oacc[nt][3] *= corr1;
        }

        #pragma unroll
        for (int ks = 0; ks < 4; ks++) {
            uint32_t pah[4] = { ph[2 * ks][0], ph[2 * ks][1], ph[2 * ks + 1][0], ph[2 * ks + 1][1] };
            uint32_t vfh[4][4], vfl[4][4];
            #pragma unroll
            for (int ntp = 0; ntp < 4; ntp++) {
                uint32_t bd = sb + 2u * (uint32_t)(VH_OFF + (ntp * 16 + brow_l) * FPITCH + ks * 16 + bcol_l);
                LDM4(vfh[ntp][0], vfh[ntp][1], vfh[ntp][2], vfh[ntp][3], bd);
                bd = sb + 2u * (uint32_t)(VL_OFF + (ntp * 16 + brow_l) * FPITCH + ks * 16 + bcol_l);
                LDM4(vfl[ntp][0], vfl[ntp][1], vfl[ntp][2], vfl[ntp][3], bd);
            }
            #pragma unroll
            for (int ntp = 0; ntp < 4; ntp++) {
                mma16816(oacc[2 * ntp],     pah, vfh[ntp][0], vfh[ntp][1]);
                mma16816(oacc[2 * ntp + 1], pah, vfh[ntp][2], vfh[ntp][3]);
            }
            #pragma unroll
            for (int ntp = 0; ntp < 4; ntp++) {
                mma16816(oacc[2 * ntp],     pah, vfl[ntp][0], vfl[ntp][1]);
                mma16816(oacc[2 * ntp + 1], pah, vfl[ntp][2], vfl[ntp][3]);
            }
        }
        __syncthreads();
    }

    float inv0 = 1.0f / l0, inv1 = 1.0f / l1;
    uint32_t* oHi = (uint32_t*)outHi;
    uint32_t* oLo = (uint32_t*)outLo;
    #pragma unroll
    for (int nt = 0; nt < 8; nt++) {
        float o00 = oacc[nt][0] * inv0, o01 = oacc[nt][1] * inv0;
        float o10 = oacc[nt][2] * inv1, o11 = oacc[nt][3] * inv1;
        float h00 = __half2float(__float2half_rn(o00));
        float h01 = __half2float(__float2half_rn(o01));
        float h10 = __half2float(__float2half_rn(o10));
        float h11 = __half2float(__float2half_rn(o11));
        size_t row = (size_t)b * SEQ + qt * 128 + wid * 16 + g;
        int col = h * 64 + nt * 8 + 2 * t4;
        oHi[(row * 2048 + col) >> 1] = pack_f16x2(h00, h01);
        oLo[(row * 2048 + col) >> 1] = pack_f16x2(o00 - h00, o01 - h01);
        oHi[((row + 8) * 2048 + col) >> 1] = pack_f16x2(h10, h11);
        oLo[((row + 8) * 2048 + col) >> 1] = pack_f16x2(o10 - h10, o11 - h11);
    }
}

// ---------------- launcher ----------------
extern "C" void kernel_launch(void* const* d_in, const int* in_sizes, int n_in,
                              void* d_out, int out_size)
{
    const float* hidden = (const float*)d_in[0];
    const float* Wq = (const float*)d_in[2];
    const float* Wk = (const float*)d_in[3];
    const float* Wv = (const float*)d_in[4];
    const float* Wo = (const float*)d_in[5];
    float* out = (float*)d_out;

    float* qkv_ptr;
    cudaGetSymbolAddress((void**)&qkv_ptr, g_qkv);

    __half *aHi, *aLo, *bQKV, *bO;
    __half *qH, *qL, *kH, *vtH, *vtL;
    cudaGetSymbolAddress((void**)&aHi, gA_hi);
    cudaGetSymbolAddress((void**)&aLo, gA_lo);
    cudaGetSymbolAddress((void**)&bQKV, gBqkv);
    cudaGetSymbolAddress((void**)&bO, gBo);
    cudaGetSymbolAddress((void**)&qH, gQhi);
    cudaGetSymbolAddress((void**)&qL, gQlo);
    cudaGetSymbolAddress((void**)&kH, gKhi);
    cudaGetSymbolAddress((void**)&vtH, gVThi);
    cudaGetSymbolAddress((void**)&vtL, gVTlo);

    cudaFuncSetAttribute(gemm_fp16x2_kernel, cudaFuncAttributeMaxDynamicSharedMemorySize, GEMM_SMEM);
    cudaFuncSetAttribute(flash_mma_kernel, cudaFuncAttributeMaxDynamicSharedMemorySize, FLASH_SMEM);

    // 1) splits: activations hi/lo + ALL weight transposes in one launch
    {
        int n = MROWS * KDIM;
        split_kernel<<<(n + 255) / 256, 256>>>(hidden, aHi, aLo, n);
        dim3 tb(32, 8);
        tsplit_all_kernel<<<dim3(160, KDIM / 32), tb>>>(Wq, Wk, Wv, Wo, bQKV, bO);
    }

    // 2) fused QKV projection (64x128 tiles, occ 3)
    gemm_fp16x2_kernel<<<dim3(NQKV / 128, MROWS / 64), 128, GEMM_SMEM>>>(aHi, aLo, bQKV, qkv_ptr, NQKV);

    // 3) RoPE + split; V transpose + split
    {
        int nq = BATCH * SEQ * HQ * (HD / 2);
        rope_split_kernel<<<(nq + 255) / 256, 256>>>(qkv_ptr, 0, qH, qL, HQ);
        int nk = BATCH * SEQ * HKV * (HD / 2);
        rope_split_kernel<<<(nk + 255) / 256, 256>>>(qkv_ptr, 2048, kH, (__half*)nullptr, HKV);
        dim3 tb(32, 8);
        vtsplit_kernel<<<dim3(SEQ / 32, HD / 32, BATCH * HKV), tb>>>(qkv_ptr, vtH, vtL);
    }

    // 4) attention
    {
        dim3 g(SEQ / 128, BATCH * HQ);
        flash_mma_kernel<<<g, 256, FLASH_SMEM>>>(qH, qL, kH, vtH, vtL, aHi, aLo);
    }

    // 5) output projection
    gemm_fp16x2_kernel<<<dim3(2048 / 128, MROWS / 64), 128, GEMM_SMEM>>>(aHi, aLo, bO, out, 2048);
}

// round 9
// speedup vs baseline: 5.1761x; 1.0605x over previous
#include <cuda_runtime.h>
#include <cuda_fp16.h>
#include <math.h>
#include <stdint.h>

// ---------------- problem constants ----------------
#define BATCH 2
#define SEQ 1024
#define HIDDEN 2048
#define HQ 32
#define HKV 8
#define HD 64
#define MROWS (BATCH * SEQ)     // 2048
#define KDIM HIDDEN             // 2048
#define NQKV 3072               // fused q(2048) | k(512) | v(512)
#define NEG_BIG (-1e9f)

// ---------------- scratch ----------------
__device__ float g_qkv[MROWS * NQKV];

__device__ __half gA_hi[MROWS * KDIM];
__device__ __half gA_lo[MROWS * KDIM];
__device__ __half gBqkv[NQKV * KDIM];
__device__ __half gBo[2048 * KDIM];

__device__ __half gQhi[MROWS * HQ * HD];
__device__ __half gQlo[MROWS * HQ * HD];
__device__ __half gKhi[MROWS * HKV * HD];
__device__ __half gVThi[BATCH * HKV * HD * SEQ];
__device__ __half gVTlo[BATCH * HKV * HD * SEQ];

// ---------------- helpers ----------------
__device__ __forceinline__ uint32_t smem_to_u32(const void* p) {
    uint32_t a;
    asm("{ .reg .u64 t; cvta.to.shared.u64 t, %1; cvt.u32.u64 %0, t; }" : "=r"(a) : "l"(p));
    return a;
}
#define LDM4(r0, r1, r2, r3, addr) \
    asm volatile("ldmatrix.sync.aligned.m8n8.x4.shared.b16 {%0,%1,%2,%3}, [%4];" \
        : "=r"(r0), "=r"(r1), "=r"(r2), "=r"(r3) : "r"(addr))

__device__ __forceinline__ void mma16816(float* d, const uint32_t* a, uint32_t b0, uint32_t b1) {
    asm volatile("mma.sync.aligned.m16n8k16.row.col.f32.f16.f16.f32 "
        "{%0,%1,%2,%3}, {%4,%5,%6,%7}, {%8,%9}, {%0,%1,%2,%3};"
        : "+f"(d[0]), "+f"(d[1]), "+f"(d[2]), "+f"(d[3])
        : "r"(a[0]), "r"(a[1]), "r"(a[2]), "r"(a[3]), "r"(b0), "r"(b1));
}
__device__ __forceinline__ uint32_t pack_f16x2(float lo, float hi) {
    uint32_t d;
    asm("cvt.rn.f16x2.f32 %0, %1, %2;" : "=r"(d) : "f"(hi), "f"(lo));
    return d;
}

// ---------------- fp16x2 GEMM: 64x128 tile, 128 threads, occ 3, 1 sync/chunk ----------------
#define BK 32
#define PITCH 40
#define A_ELEMS (64 * PITCH)                        // 2560
#define B_ELEMS (128 * PITCH)                       // 5120
#define STAGE_ELEMS (2 * A_ELEMS + B_ELEMS)         // 10240 elems = 20480 B
#define NSTAGE 3
#define GEMM_SMEM (NSTAGE * STAGE_ELEMS * 2)        // 61440 bytes
#define NCHUNK (KDIM / BK)                          // 64

__device__ __forceinline__ void issue_stage(
    uint32_t sb, int stage,
    const __half* __restrict__ Ahi, const __half* __restrict__ Alo,
    const __half* __restrict__ B,
    int m0, int n0, int k0, int tid)
{
    #pragma unroll
    for (int t = 0; t < 8; t++) {
        int idx = tid + t * 128;            // 0..1023
        int ch = idx & 3;
        const __half* src;
        uint32_t dstoff;
        if (idx < 512) {
            int tl = idx >> 8;
            int row = (idx >> 2) & 63;
            src = (tl ? Alo : Ahi) + (size_t)(m0 + row) * KDIM + k0 + ch * 8;
            dstoff = (uint32_t)(tl * A_ELEMS + row * PITCH + ch * 8);
        } else {
            int row = (idx >> 2) & 127;
            src = B + (size_t)(n0 + row) * KDIM + k0 + ch * 8;
            dstoff = (uint32_t)(2 * A_ELEMS + row * PITCH + ch * 8);
        }
        uint32_t dst = sb + 2u * ((uint32_t)stage * STAGE_ELEMS + dstoff);
        asm volatile("cp.async.cg.shared.global [%0], [%1], 16;" :: "r"(dst), "l"(src));
    }
    asm volatile("cp.async.commit_group;");
}

__global__ __launch_bounds__(128, 3) void gemm_fp16x2_kernel(
    const __half* __restrict__ Ahi, const __half* __restrict__ Alo,
    const __half* __restrict__ B,
    float* __restrict__ C, int N)
{
    extern __shared__ char smem[];
    const uint32_t sb = smem_to_u32(smem);
    const int tid = threadIdx.x;
    const int wid = tid >> 5;
    const int lid = tid & 31;
    const int g = lid >> 2;
    const int t4 = lid & 3;
    const int n0 = blockIdx.x * 128;
    const int m0 = blockIdx.y * 64;

    const int arow_l = (lid & 7) + ((lid >> 3) & 1) * 8;
    const int acol_l = (lid >> 4) * 8;
    const int brow_l = (lid & 7) + (lid >> 4) * 8;
    const int bcol_l = ((lid >> 3) & 1) * 8;

    float acc[4][4][4];
    #pragma unroll
    for (int i = 0; i < 4; i++)
        #pragma unroll
        for (int j = 0; j < 4; j++)
            #pragma unroll
            for (int r = 0; r < 4; r++) acc[i][j][r] = 0.f;

    issue_stage(sb, 0, Ahi, Alo, B, m0, n0, 0, tid);
    issue_stage(sb, 1, Ahi, Alo, B, m0, n0, BK, tid);

    int p = 0;
    for (int i = 0; i < NCHUNK; i++) {
        if (i < NCHUNK - 1) {
            asm volatile("cp.async.wait_group 1;" ::: "memory");
        } else {
            asm volatile("cp.async.wait_group 0;" ::: "memory");
        }
        __syncthreads();   // orders: stage p readable by all; stage p-1 reads (iter i-1) done

        if (i + 2 < NCHUNK) {
            int st = p + 2; if (st >= NSTAGE) st -= NSTAGE;
            issue_stage(sb, st, Ahi, Alo, B, m0, n0, (i + 2) * BK, tid);
        }

        const uint32_t base = sb + 2u * (uint32_t)(p * STAGE_ELEMS);
        #pragma unroll
        for (int ks = 0; ks < 2; ks++) {
            const int kb = ks * 16;
            uint32_t ah[4][4], al[4][4], bb[4][2];
            #pragma unroll
            for (int mt = 0; mt < 4; mt++) {
                uint32_t ad = base + 2u * (uint32_t)((mt * 16 + arow_l) * PITCH + kb + acol_l);
                LDM4(ah[mt][0], ah[mt][1], ah[mt][2], ah[mt][3], ad);
                LDM4(al[mt][0], al[mt][1], al[mt][2], al[mt][3], ad + 2u * A_ELEMS);
            }
            #pragma unroll
            for (int ntp = 0; ntp < 2; ntp++) {
                uint32_t bd = base + 2u * (uint32_t)(2 * A_ELEMS + (wid * 32 + ntp * 16 + brow_l) * PITCH + kb + bcol_l);
                uint32_t r0, r1, r2, r3;
                LDM4(r0, r1, r2, r3, bd);
                bb[2 * ntp][0] = r0; bb[2 * ntp][1] = r1;
                bb[2 * ntp + 1][0] = r2; bb[2 * ntp + 1][1] = r3;
            }
            #pragma unroll
            for (int mt = 0; mt < 4; mt++)
                #pragma unroll
                for (int nt = 0; nt < 4; nt++)
                    mma16816(acc[mt][nt], ah[mt], bb[nt][0], bb[nt][1]);
            #pragma unroll
            for (int mt = 0; mt < 4; mt++)
                #pragma unroll
                for (int nt = 0; nt < 4; nt++)
                    mma16816(acc[mt][nt], al[mt], bb[nt][0], bb[nt][1]);
        }
        if (++p == NSTAGE) p = 0;
    }

    #pragma unroll
    for (int mt = 0; mt < 4; mt++) {
        int row = m0 + mt * 16 + g;
        #pragma unroll
        for (int nt = 0; nt < 4; nt++) {
            int col = n0 + wid * 32 + nt * 8 + 2 * t4;
            *(float2*)&C[(size_t)row * N + col] = make_float2(acc[mt][nt][0], acc[mt][nt][1]);
            *(float2*)&C[(size_t)(row + 8) * N + col] = make_float2(acc[mt][nt][2], acc[mt][nt][3]);
        }
    }
}

// ---------------- fp32 -> fp16 hi/lo split ----------------
__global__ void split_kernel(const float* __restrict__ x,
                             __half* __restrict__ hi,
                             __half* __restrict__ lo, int n)
{
    int i = blockIdx.x * blockDim.x + threadIdx.x;
    if (i >= n) return;
    float v = x[i];
    __half h = __float2half_rn(v);
    float r = v - __half2float(h);
    hi[i] = h;
    lo[i] = __float2half_rn(r);
}

// ---------------- all 4 weight transposes in ONE launch ----------------
__global__ void tsplit_all_kernel(const float* __restrict__ Wq, const float* __restrict__ Wk,
                                  const float* __restrict__ Wv, const float* __restrict__ Wo,
                                  __half* __restrict__ bQKV, __half* __restrict__ bO)
{
    __shared__ float t[32][33];
    const int ntile = blockIdx.x;
    const int k0 = blockIdx.y * 32;
    const float* W;  __half* dst;  int N;  int n0;
    if (ntile < 64)      { W = Wq; dst = bQKV;                          N = 2048; n0 = ntile * 32; }
    else if (ntile < 80) { W = Wk; dst = bQKV + (size_t)2048 * KDIM;    N = 512;  n0 = (ntile - 64) * 32; }
    else if (ntile < 96) { W = Wv; dst = bQKV + (size_t)2560 * KDIM;    N = 512;  n0 = (ntile - 80) * 32; }
    else                 { W = Wo; dst = bO;                            N = 2048; n0 = (ntile - 96) * 32; }

    const int tx = threadIdx.x, ty = threadIdx.y;
    #pragma unroll
    for (int i = 0; i < 32; i += 8)
        t[ty + i][tx] = W[(size_t)(k0 + ty + i) * N + n0 + tx];
    __syncthreads();
    #pragma unroll
    for (int i = 0; i < 32; i += 8) {
        float v = t[tx][ty + i];
        dst[(size_t)(n0 + ty + i) * KDIM + k0 + tx] = __float2half_rn(v);
    }
}

// ---------------- fused prep: rope(Q) | rope(K) | V-transpose, one launch ----------------
// blocks [0,8192): rope Q; [8192,10240): rope K; [10240,11264): vtranspose+split
#define PREP_ROPEQ_BLKS 8192
#define PREP_ROPEK_BLKS 2048
#define PREP_VT_BLKS 1024
#define PREP_TOTAL_BLKS (PREP_ROPEQ_BLKS + PREP_ROPEK_BLKS + PREP_VT_BLKS)

__device__ __forceinline__ void rope_body(const float* __restrict__ qkv, int colOff,
                                          __half* __restrict__ hi, __half* __restrict__ lo,
                                          int heads, int idx)
{
    int dpair = idx & 31;
    int t = idx >> 5;
    int h = t % heads;  t /= heads;
    int s = t % SEQ;
    int b = t / SEQ;

    float inv = powf(10000.0f, -(float)(2 * dpair) / (float)HD);
    float ang = (float)s * inv;
    float sn, cs;
    sincosf(ang, &sn, &cs);

    size_t src = ((size_t)b * SEQ + s) * NQKV + colOff + h * HD + dpair;
    float x1 = qkv[src];
    float x2 = qkv[src + HD / 2];
    float y1 = x1 * cs - x2 * sn;
    float y2 = x2 * cs + x1 * sn;

    size_t base = (((size_t)b * SEQ + s) * heads + h) * HD + dpair;
    __half h1 = __float2half_rn(y1);
    __half h2 = __float2half_rn(y2);
    hi[base] = h1;
    hi[base + HD / 2] = h2;
    if (lo) {
        lo[base] = __float2half_rn(y1 - __half2float(h1));
        lo[base + HD / 2] = __float2half_rn(y2 - __half2float(h2));
    }
}

__global__ void prep_kernel(const float* __restrict__ qkv,
                            __half* __restrict__ qH, __half* __restrict__ qL,
                            __half* __restrict__ kH,
                            __half* __restrict__ vtH, __half* __restrict__ vtL)
{
    const int blk = blockIdx.x;
    const int tid = threadIdx.x;

    if (blk < PREP_ROPEQ_BLKS) {
        rope_body(qkv, 0, qH, qL, HQ, blk * 256 + tid);
    } else if (blk < PREP_ROPEQ_BLKS + PREP_ROPEK_BLKS) {
        rope_body(qkv, 2048, kH, (__half*)0, HKV, (blk - PREP_ROPEQ_BLKS) * 256 + tid);
    } else {
        __shared__ float t[32][33];
        int local = blk - PREP_ROPEQ_BLKS - PREP_ROPEK_BLKS;   // 0..1023
        const int s0 = (local & 31) * 32;
        const int d0 = ((local >> 5) & 1) * 32;
        const int bh = local >> 6;                              // 0..15
        const int b = bh >> 3;
        const int h = bh & 7;
        const int tx = tid & 31, ty = tid >> 5;
        #pragma unroll
        for (int i = 0; i < 32; i += 8)
            t[ty + i][tx] = qkv[((size_t)b * SEQ + s0 + ty + i) * NQKV + 2560 + h * HD + d0 + tx];
        __syncthreads();
        #pragma unroll
        for (int i = 0; i < 32; i += 8) {
            float x = t[tx][ty + i];
            __half hh = __float2half_rn(x);
            float r = x - __half2float(hh);
            size_t o = (((size_t)b * HKV + h) * HD + d0 + ty + i) * SEQ + s0 + tx;
            vtH[o] = hh;
            vtL[o] = __float2half_rn(r);
        }
    }
}

// ---------------- flash attention (fp16 tensor cores, occ 2, overlaid smem) ----------------
#define FPITCH 72
// Q staging overlays the KV region (Q only needed until fragments are in regs)
#define QH_OFF 0
#define QL_OFF (128 * FPITCH)
#define KH_OFF 0
#define VH_OFF (64 * FPITCH)
#define VL_OFF (128 * FPITCH)
#define FLASH_SMEM (256 * FPITCH * 2)   // 36864 bytes

__global__ __launch_bounds__(256, 2) void flash_mma_kernel(
    const __half* __restrict__ qhi, const __half* __restrict__ qlo,
    const __half* __restrict__ khi,
    const __half* __restrict__ vthi, const __half* __restrict__ vtlo,
    __half* __restrict__ outHi, __half* __restrict__ outLo)
{
    extern __shared__ char smem[];
    const uint32_t sb = smem_to_u32(smem);
    __half* sm = (__half*)smem;

    const int tid = threadIdx.x;
    const int wid = tid >> 5;
    const int lid = tid & 31;
    const int g = lid >> 2;
    const int t4 = lid & 3;
    const int qt = blockIdx.x;
    const int bh = blockIdx.y;
    const int b = bh >> 5;
    const int h = bh & 31;
    const int hkv = h >> 2;

    const int arow_l = (lid & 7) + ((lid >> 3) & 1) * 8;
    const int acol_l = (lid >> 4) * 8;
    const int brow_l = (lid & 7) + (lid >> 4) * 8;
    const int bcol_l = ((lid >> 3) & 1) * 8;

    #pragma unroll
    for (int it = 0; it < 4; it++) {
        int idx = tid + it * 256;
        int row = idx >> 3;
        int ch = idx & 7;
        size_t goff = (((size_t)b * SEQ + qt * 128 + row) * HQ + h) * HD + ch * 8;
        *(uint4*)&sm[QH_OFF + row * FPITCH + ch * 8] = *(const uint4*)&qhi[goff];
        *(uint4*)&sm[QL_OFF + row * FPITCH + ch * 8] = *(const uint4*)&qlo[goff];
    }
    __syncthreads();

    uint32_t qh[4][4], ql[4][4];
    #pragma unroll
    for (int ks = 0; ks < 4; ks++) {
        uint32_t ad = sb + 2u * (uint32_t)(QH_OFF + (wid * 16 + arow_l) * FPITCH + ks * 16 + acol_l);
        LDM4(qh[ks][0], qh[ks][1], qh[ks][2], qh[ks][3], ad);
        ad = sb + 2u * (uint32_t)(QL_OFF + (wid * 16 + arow_l) * FPITCH + ks * 16 + acol_l);
        LDM4(ql[ks][0], ql[ks][1], ql[ks][2], ql[ks][3], ad);
    }
    __syncthreads();   // Q fragment reads complete before KV tiles overwrite the region

    float m0 = -1e30f, m1 = -1e30f, l0 = 0.f, l1 = 0.f;
    float oacc[8][4];
    #pragma unroll
    for (int nt = 0; nt < 8; nt++)
        #pragma unroll
        for (int r = 0; r < 4; r++) oacc[nt][r] = 0.f;

    const int row0 = qt * 128 + wid * 16;
    const int r_g = row0 + g;
    const int r_g8 = r_g + 8;
    const float scale = 0.125f;
    const int nkt = 2 * qt + 2;

    for (int kt = 0; kt < nkt; kt++) {
        #pragma unroll
        for (int it = 0; it < 6; it++) {
            int idx = tid + it * 256;
            int tile = idx >> 9;
            int r = (idx >> 3) & 63;
            int ch = idx & 7;
            const __half* src;
            int dstoff;
            if (tile == 0) { src = &khi[(((size_t)b * SEQ + kt * 64 + r) * HKV + hkv) * HD + ch * 8]; dstoff = KH_OFF; }
            else if (tile == 1) { src = &vthi[(((size_t)b * HKV + hkv) * HD + r) * SEQ + kt * 64 + ch * 8]; dstoff = VH_OFF; }
            else { src = &vtlo[(((size_t)b * HKV + hkv) * HD + r) * SEQ + kt * 64 + ch * 8]; dstoff = VL_OFF; }
            *(uint4*)&sm[dstoff + r * FPITCH + ch * 8] = *(const uint4*)src;
        }
        __syncthreads();

        float sacc[8][4];
        #pragma unroll
        for (int nt = 0; nt < 8; nt++)
            #pragma unroll
            for (int r = 0; r < 4; r++) sacc[nt][r] = 0.f;

        #pragma unroll
        for (int ks = 0; ks < 4; ks++) {
            uint32_t kf[4][4];
            #pragma unroll
            for (int ntp = 0; ntp < 4; ntp++) {
                uint32_t bd = sb + 2u * (uint32_t)(KH_OFF + (ntp * 16 + brow_l) * FPITCH + ks * 16 + bcol_l);
                LDM4(kf[ntp][0], kf[ntp][1], kf[ntp][2], kf[ntp][3], bd);
            }
            #pragma unroll
            for (int ntp = 0; ntp < 4; ntp++) {
                mma16816(sacc[2 * ntp],     qh[ks], kf[ntp][0], kf[ntp][1]);
                mma16816(sacc[2 * ntp + 1], qh[ks], kf[ntp][2], kf[ntp][3]);
            }
            #pragma unroll
            for (int ntp = 0; ntp < 4; ntp++) {
                mma16816(sacc[2 * ntp],     ql[ks], kf[ntp][0], kf[ntp][1]);
                mma16816(sacc[2 * ntp + 1], ql[ks], kf[ntp][2], kf[ntp][3]);
            }
        }

        const bool maybe_mask = (kt * 64 + 63 > row0);
        float mx0 = -1e30f, mx1 = -1e30f;
        #pragma unroll
        for (int nt = 0; nt < 8; nt++) {
            #pragma unroll
            for (int r = 0; r < 4; r++) sacc[nt][r] *= scale;
            if (maybe_mask) {
                int colb = kt * 64 + nt * 8 + 2 * t4;
                if (colb > r_g)      sacc[nt][0] = NEG_BIG;
                if (colb + 1 > r_g)  sacc[nt][1] = NEG_BIG;
                if (colb > r_g8)     sacc[nt][2] = NEG_BIG;
                if (colb + 1 > r_g8) sacc[nt][3] = NEG_BIG;
            }
            mx0 = fmaxf(mx0, fmaxf(sacc[nt][0], sacc[nt][1]));
            mx1 = fmaxf(mx1, fmaxf(sacc[nt][2], sacc[nt][3]));
        }
        mx0 = fmaxf(mx0, __shfl_xor_sync(0xffffffffu, mx0, 1));
        mx0 = fmaxf(mx0, __shfl_xor_sync(0xffffffffu, mx0, 2));
        mx1 = fmaxf(mx1, __shfl_xor_sync(0xffffffffu, mx1, 1));
        mx1 = fmaxf(mx1, __shfl_xor_sync(0xffffffffu, mx1, 2));

        float mn0 = fmaxf(m0, mx0), mn1 = fmaxf(m1, mx1);
        float corr0 = __expf(m0 - mn0), corr1 = __expf(m1 - mn1);

        uint32_t ph[8][2];
        float rs0 = 0.f, rs1 = 0.f;
        #pragma unroll
        for (int nt = 0; nt < 8; nt++) {
            float p00 = __expf(sacc[nt][0] - mn0);
            float p01 = __expf(sacc[nt][1] - mn0);
            float p10 = __expf(sacc[nt][2] - mn1);
            float p11 = __expf(sacc[nt][3] - mn1);
            rs0 += p00 + p01;
            rs1 += p10 + p11;
            ph[nt][0] = pack_f16x2(p00, p01);
            ph[nt][1] = pack_f16x2(p10, p11);
        }
        rs0 += __shfl_xor_sync(0xffffffffu, rs0, 1);
        rs0 += __shfl_xor_sync(0xffffffffu, rs0, 2);
        rs1 += __shfl_xor_sync(0xffffffffu, rs1, 1);
        rs1 += __shfl_xor_sync(0xffffffffu, rs1, 2);

        l0 = l0 * corr0 + rs0;
        l1 = l1 * corr1 + rs1;
        m0 = mn0; m1 = mn1;
        #pragma unroll
        for (int nt = 0; nt < 8; nt++) {
            oacc[nt][0] *= corr0; oacc[nt][1] *= corr0;
            oacc[nt][2] *= corr1; oacc[nt][3] *= corr1;
        }

        #pragma unroll
        for (int ks = 0; ks < 4; ks++) {
            uint32_t pah[4] = { ph[2 * ks][0], ph[2 * ks][1], ph[2 * ks + 1][0], ph[2 * ks + 1][1] };
            uint32_t vfh[4][4], vfl[4][4];
            #pragma unroll
            for (int ntp = 0; ntp < 4; ntp++) {
                uint32_t bd = sb + 2u * (uint32_t)(VH_OFF + (ntp * 16 + brow_l) * FPITCH + ks * 16 + bcol_l);
                LDM4(vfh[ntp][0], vfh[ntp][1], vfh[ntp][2], vfh[ntp][3], bd);
                bd = sb + 2u * (uint32_t)(VL_OFF + (ntp * 16 + brow_l) * FPITCH + ks * 16 + bcol_l);
                LDM4(vfl[ntp][0], vfl[ntp][1], vfl[ntp][2], vfl[ntp][3], bd);
            }
            #pragma unroll
            for (int ntp = 0; ntp < 4; ntp++) {
                mma16816(oacc[2 * ntp],     pah, vfh[ntp][0], vfh[ntp][1]);
                mma16816(oacc[2 * ntp + 1], pah, vfh[ntp][2], vfh[ntp][3]);
            }
            #pragma unroll
            for (int ntp = 0; ntp < 4; ntp++) {
                mma16816(oacc[2 * ntp],     pah, vfl[ntp][0], vfl[ntp][1]);
                mma16816(oacc[2 * ntp + 1], pah, vfl[ntp][2], vfl[ntp][3]);
            }
        }
        __syncthreads();
    }

    float inv0 = 1.0f / l0, inv1 = 1.0f / l1;
    uint32_t* oHi = (uint32_t*)outHi;
    uint32_t* oLo = (uint32_t*)outLo;
    #pragma unroll
    for (int nt = 0; nt < 8; nt++) {
        float o00 = oacc[nt][0] * inv0, o01 = oacc[nt][1] * inv0;
        float o10 = oacc[nt][2] * inv1, o11 = oacc[nt][3] * inv1;
        float h00 = __half2float(__float2half_rn(o00));
        float h01 = __half2float(__float2half_rn(o01));
        float h10 = __half2float(__float2half_rn(o10));
        float h11 = __half2float(__float2half_rn(o11));
        size_t row = (size_t)b * SEQ + qt * 128 + wid * 16 + g;
        int col = h * 64 + nt * 8 + 2 * t4;
        oHi[(row * 2048 + col) >> 1] = pack_f16x2(h00, h01);
        oLo[(row * 2048 + col) >> 1] = pack_f16x2(o00 - h00, o01 - h01);
        oHi[((row + 8) * 2048 + col) >> 1] = pack_f16x2(h10, h11);
        oLo[((row + 8) * 2048 + col) >> 1] = pack_f16x2(o10 - h10, o11 - h11);
    }
}

// ---------------- launcher ----------------
extern "C" void kernel_launch(void* const* d_in, const int* in_sizes, int n_in,
                              void* d_out, int out_size)
{
    const float* hidden = (const float*)d_in[0];
    const float* Wq = (const float*)d_in[2];
    const float* Wk = (const float*)d_in[3];
    const float* Wv = (const float*)d_in[4];
    const float* Wo = (const float*)d_in[5];
    float* out = (float*)d_out;

    float* qkv_ptr;
    cudaGetSymbolAddress((void**)&qkv_ptr, g_qkv);

    __half *aHi, *aLo, *bQKV, *bO;
    __half *qH, *qL, *kH, *vtH, *vtL;
    cudaGetSymbolAddress((void**)&aHi, gA_hi);
    cudaGetSymbolAddress((void**)&aLo, gA_lo);
    cudaGetSymbolAddress((void**)&bQKV, gBqkv);
    cudaGetSymbolAddress((void**)&bO, gBo);
    cudaGetSymbolAddress((void**)&qH, gQhi);
    cudaGetSymbolAddress((void**)&qL, gQlo);
    cudaGetSymbolAddress((void**)&kH, gKhi);
    cudaGetSymbolAddress((void**)&vtH, gVThi);
    cudaGetSymbolAddress((void**)&vtL, gVTlo);

    cudaFuncSetAttribute(gemm_fp16x2_kernel, cudaFuncAttributeMaxDynamicSharedMemorySize, GEMM_SMEM);
    cudaFuncSetAttribute(flash_mma_kernel, cudaFuncAttributeMaxDynamicSharedMemorySize, FLASH_SMEM);

    // 1) splits
    {
        int n = MROWS * KDIM;
        split_kernel<<<(n + 255) / 256, 256>>>(hidden, aHi, aLo, n);
        dim3 tb(32, 8);
        tsplit_all_kernel<<<dim3(160, KDIM / 32), tb>>>(Wq, Wk, Wv, Wo, bQKV, bO);
    }

    // 2) fused QKV projection
    gemm_fp16x2_kernel<<<dim3(NQKV / 128, MROWS / 64), 128, GEMM_SMEM>>>(aHi, aLo, bQKV, qkv_ptr, NQKV);

    // 3) fused prep (rope Q, rope K, V transpose) — one launch
    prep_kernel<<<PREP_TOTAL_BLKS, 256>>>(qkv_ptr, qH, qL, kH, vtH, vtL);

    // 4) attention
    {
        dim3 g(SEQ / 128, BATCH * HQ);
        flash_mma_kernel<<<g, 256, FLASH_SMEM>>>(qH, qL, kH, vtH, vtL, aHi, aLo);
    }

    // 5) output projection
    gemm_fp16x2_kernel<<<dim3(2048 / 128, MROWS / 64), 128, GEMM_SMEM>>>(aHi, aLo, bO, out, 2048);
}